// round 3
// baseline (speedup 1.0000x reference)
#include <cuda_runtime.h>

#define NN 10000
#define NE 320000
#define FD 64
#define HD 256
#define GD 256
#define H3 768
#define MB_PER_SCALE 79   // ceil(10000/128)

// ---------------- static scratch (no allocs allowed) ----------------
__device__ float d_XGL[600000 * 768];   // long:   x@Wih^T + biases, rows (n*60+t)
__device__ float d_XGM[300000 * 768];   // medium
__device__ float d_XGS[ 80000 * 768];   // short
__device__ unsigned d_WHH[3 * 768 * 256];  // tf32 preconverted, scale order l,m,s
__device__ unsigned d_WIH[3 * 768 * 64];
__device__ float d_BIAS[3 * 768];          // bih + (col<512 ? bhh : 0)
__device__ float d_HA[3 * NN * HD];
__device__ float d_HB[3 * NN * HD];
__device__ float d_COMB[NN * H3];
__device__ float d_TEMB[NN * GD];
__device__ float d_XL[NN * GD];
__device__ float d_AGG[NN * GD];
__device__ float d_G1[NN * GD];
__device__ float d_G2[NN * GD];
__device__ float d_P[NN];
__device__ float d_Q[NN];
__device__ float d_SSUM[NN];
__device__ unsigned d_MENC[NN];
__device__ float d_SC[NE];

// ---------------- helpers ----------------
__device__ __forceinline__ unsigned f2tf(float f) {
    unsigned r;
    asm("cvt.rna.tf32.f32 %0, %1;" : "=r"(r) : "f"(f));
    return r;
}
__device__ __forceinline__ float sigf(float x) { return 1.f / (1.f + expf(-x)); }

__device__ __forceinline__ void cp16(void* dst_smem, const void* src) {
    unsigned a = (unsigned)__cvta_generic_to_shared(dst_smem);
    asm volatile("cp.async.cg.shared.global [%0], [%1], 16;" :: "r"(a), "l"(src));
}
__device__ __forceinline__ void cp_commit() {
    asm volatile("cp.async.commit_group;");
}
__device__ __forceinline__ void cp_wait0() {
    asm volatile("cp.async.wait_group 0;");
}
__device__ __forceinline__ void mma_tf32(float* c, const unsigned* a, const unsigned* b) {
    asm volatile(
        "mma.sync.aligned.m16n8k8.row.col.f32.tf32.tf32.f32 "
        "{%0,%1,%2,%3},{%4,%5,%6,%7},{%8,%9},{%0,%1,%2,%3};"
        : "+f"(c[0]), "+f"(c[1]), "+f"(c[2]), "+f"(c[3])
        : "r"(a[0]), "r"(a[1]), "r"(a[2]), "r"(a[3]), "r"(b[0]), "r"(b[1]));
}

// ---------------- weight/bias preconversion (per scale) ----------------
__global__ void k_prep(const float* __restrict__ whh, const float* __restrict__ wih,
                       const float* __restrict__ bih, const float* __restrict__ bhh,
                       int s) {
    int i = blockIdx.x * 256 + threadIdx.x;
    if (i < 768 * 256) d_WHH[s * 768 * 256 + i] = f2tf(whh[i]);
    if (i < 768 * 64)  d_WIH[s * 768 * 64 + i] = f2tf(wih[i]);
    if (i < 768)       d_BIAS[s * 768 + i] = bih[i] + (i < 512 ? bhh[i] : 0.f);
}

// ---------------- XG precompute: C[M,768] = cvt(A[M,64]) @ Wih^T + bias ----
// block 128x192, 512 thr (16 warps 4m x 4n), warp tile 32x48.
__global__ void __launch_bounds__(512) gemm_xg(
    const float* __restrict__ A, int M,
    const unsigned* __restrict__ Bw,    // [768][64] tf32
    const float* __restrict__ bias,     // [768]
    float* __restrict__ C)
{
    __shared__ unsigned As[128 * 36];
    __shared__ unsigned Bs[192 * 36];
    const int tid = threadIdx.x;
    const int m0 = blockIdx.x * 128;
    const int n0 = blockIdx.y * 192;
    const int lane = tid & 31;
    const int gid = lane >> 2, tig = lane & 3;
    const int warp = tid >> 5;
    const int wm = warp & 3, wn = warp >> 2;

    float acc[2][6][4];
#pragma unroll
    for (int i = 0; i < 2; i++)
#pragma unroll
        for (int j = 0; j < 6; j++)
#pragma unroll
            for (int r = 0; r < 4; r++) acc[i][j][r] = 0.f;

    for (int kb = 0; kb < 2; kb++) {
        // A: 128 rows x 32 k
#pragma unroll
        for (int p = 0; p < 2; p++) {
            int task = tid + p * 512;
            int row = task >> 3, ch = task & 7;
            float4 v = make_float4(0.f, 0.f, 0.f, 0.f);
            if (m0 + row < M)
                v = *(const float4*)(A + (size_t)(m0 + row) * 64 + kb * 32 + ch * 4);
            unsigned* d = As + row * 36 + ch * 4;
            d[0] = f2tf(v.x); d[1] = f2tf(v.y); d[2] = f2tf(v.z); d[3] = f2tf(v.w);
        }
        // B: 192 rows x 32 k (already tf32)
#pragma unroll
        for (int p = 0; p < 3; p++) {
            int task = tid + p * 512;
            int q = task >> 3, ch = task & 7;
            uint4 v = *(const uint4*)(Bw + (size_t)(n0 + q) * 64 + kb * 32 + ch * 4);
            unsigned* d = Bs + q * 36 + ch * 4;
            d[0] = v.x; d[1] = v.y; d[2] = v.z; d[3] = v.w;
        }
        __syncthreads();
#pragma unroll
        for (int ks = 0; ks < 4; ks++) {
            const int kk = ks * 8;
            unsigned af[2][4];
#pragma unroll
            for (int i = 0; i < 2; i++) {
                int rb = (wm * 32 + i * 16 + gid) * 36;
                af[i][0] = As[rb + kk + tig];
                af[i][1] = As[rb + 8 * 36 + kk + tig];
                af[i][2] = As[rb + kk + tig + 4];
                af[i][3] = As[rb + 8 * 36 + kk + tig + 4];
            }
#pragma unroll
            for (int jt = 0; jt < 6; jt++) {
                int qb = (wn * 48 + jt * 8 + gid) * 36;
                unsigned bf[2];
                bf[0] = Bs[qb + kk + tig];
                bf[1] = Bs[qb + kk + tig + 4];
#pragma unroll
                for (int i = 0; i < 2; i++) mma_tf32(acc[i][jt], af[i], bf);
            }
        }
        __syncthreads();
    }

#pragma unroll
    for (int i = 0; i < 2; i++)
#pragma unroll
        for (int jt = 0; jt < 6; jt++)
#pragma unroll
            for (int h = 0; h < 2; h++) {
                int row = m0 + wm * 32 + i * 16 + gid + h * 8;
                if (row >= M) continue;
                int col = n0 + wn * 48 + jt * 8 + 2 * tig;
                float2 v;
                v.x = acc[i][jt][h * 2 + 0] + bias[col];
                v.y = acc[i][jt][h * 2 + 1] + bias[col + 1];
                *(float2*)(C + (size_t)row * 768 + col) = v;
            }
}

// ---------------- recurrent step: gates = h @ Whh^T, then GRU update -------
// Block tile 128m x 192n (64 j x 3 chunks), K=256, 512 thr, cp.async 2-stage.
#define A_WORDS (128 * 36)
#define B_WORDS (192 * 36)
#define STAGE (A_WORDS + B_WORDS)
#define STEP_SMEM (STAGE * 2 * 4)

__global__ void __launch_bounds__(512) gru_step(
    const float* __restrict__ hin, float* __restrict__ hout,
    const unsigned* __restrict__ whh,
    const float* __restrict__ xg0, const float* __restrict__ xg1,
    const float* __restrict__ xg2,
    int xs0, int xs1, int xs2,
    const float* __restrict__ bhh0, const float* __restrict__ bhh1,
    const float* __restrict__ bhh2)
{
    extern __shared__ unsigned smem_u[];
    const int tid = threadIdx.x;
    const int s = blockIdx.x / MB_PER_SCALE;
    const int m0 = (blockIdx.x % MB_PER_SCALE) * 128;
    const int j0 = blockIdx.y * 64;
    const int lane = tid & 31;
    const int gid = lane >> 2, tig = lane & 3;
    const int warp = tid >> 5;
    const int wm = warp & 3, wn = warp >> 2;

    const float* xgb = (s == 0) ? xg0 : (s == 1) ? xg1 : xg2;
    const int xstr = (s == 0) ? xs0 : (s == 1) ? xs1 : xs2;
    const float* bhh = (s == 0) ? bhh0 : (s == 1) ? bhh1 : bhh2;
    const unsigned* wb = whh + (size_t)s * 768 * 256;
    const float* hbase = hin + (size_t)s * NN * HD;

    const int arow = tid >> 3;          // A task row base (2 tasks)
    const int ach = (tid & 7) * 4;

    float acc[2][6][4];
#pragma unroll
    for (int i = 0; i < 2; i++)
#pragma unroll
        for (int j = 0; j < 6; j++)
#pragma unroll
            for (int r = 0; r < 4; r++) acc[i][j][r] = 0.f;

    float4 areg[2];

#define LDG_A(kb)                                                              \
    {                                                                          \
        _Pragma("unroll")                                                      \
        for (int p = 0; p < 2; p++) {                                          \
            int row = arow + p * 64;                                           \
            int m = m0 + row;                                                  \
            areg[p] = (m < NN)                                                 \
                ? *(const float4*)(hbase + (size_t)m * HD + (kb) * 32 + ach)   \
                : make_float4(0.f, 0.f, 0.f, 0.f);                             \
        }                                                                      \
    }
#define STS_A(As_)                                                             \
    {                                                                          \
        _Pragma("unroll")                                                      \
        for (int p = 0; p < 2; p++) {                                          \
            unsigned* d = (As_) + (arow + p * 64) * 36 + ach;                  \
            d[0] = f2tf(areg[p].x); d[1] = f2tf(areg[p].y);                    \
            d[2] = f2tf(areg[p].z); d[3] = f2tf(areg[p].w);                    \
        }                                                                      \
    }
#define CP_B(kb, Bs_)                                                          \
    {                                                                          \
        _Pragma("unroll")                                                      \
        for (int p = 0; p < 3; p++) {                                          \
            int task = tid + p * 512;                                          \
            int q = task >> 3, ch = (task & 7) * 4;                            \
            int wrow = (q >> 6) * 256 + j0 + (q & 63);                         \
            cp16((Bs_) + q * 36 + ch, wb + (size_t)wrow * 256 + (kb) * 32 + ch); \
        }                                                                      \
    }

    // prologue: stage 0
    LDG_A(0);
    CP_B(0, smem_u + A_WORDS);
    cp_commit();
    STS_A(smem_u);
    cp_wait0();
    __syncthreads();

#pragma unroll
    for (int kb = 0; kb < 8; kb++) {
        unsigned* As = smem_u + (kb & 1) * STAGE;
        unsigned* Bs = As + A_WORDS;
        unsigned* Asn = smem_u + ((kb + 1) & 1) * STAGE;
        unsigned* Bsn = Asn + A_WORDS;
        if (kb < 7) {
            LDG_A(kb + 1);
            CP_B(kb + 1, Bsn);
            cp_commit();
        }
#pragma unroll
        for (int ks = 0; ks < 4; ks++) {
            const int kk = ks * 8;
            unsigned af[2][4];
#pragma unroll
            for (int i = 0; i < 2; i++) {
                int rb = (wm * 32 + i * 16 + gid) * 36;
                af[i][0] = As[rb + kk + tig];
                af[i][1] = As[rb + 8 * 36 + kk + tig];
                af[i][2] = As[rb + kk + tig + 4];
                af[i][3] = As[rb + 8 * 36 + kk + tig + 4];
            }
#pragma unroll
            for (int c = 0; c < 3; c++)
#pragma unroll
                for (int u = 0; u < 2; u++) {
                    int qb = (c * 64 + wn * 16 + u * 8 + gid) * 36;
                    unsigned bf[2];
                    bf[0] = Bs[qb + kk + tig];
                    bf[1] = Bs[qb + kk + tig + 4];
#pragma unroll
                    for (int i = 0; i < 2; i++) mma_tf32(acc[i][c * 2 + u], af[i], bf);
                }
        }
        if (kb < 7) {
            STS_A(Asn);
            cp_wait0();
        }
        __syncthreads();
    }

    // epilogue: GRU gate update
#pragma unroll
    for (int i = 0; i < 2; i++)
#pragma unroll
        for (int u = 0; u < 2; u++)
#pragma unroll
            for (int h = 0; h < 2; h++)
#pragma unroll
                for (int pp = 0; pp < 2; pp++) {
                    int row = m0 + wm * 32 + i * 16 + gid + h * 8;
                    if (row >= NN) continue;
                    int jg = j0 + wn * 16 + u * 8 + 2 * tig + pp;
                    float ar = acc[i][0 + u][h * 2 + pp];
                    float az = acc[i][2 + u][h * 2 + pp];
                    float an = acc[i][4 + u][h * 2 + pp];
                    const float* xr = xgb + (size_t)row * xstr + jg;
                    float r = sigf(xr[0] + ar);
                    float z = sigf(xr[256] + az);
                    float n = tanhf(xr[512] + r * (an + bhh[512 + jg]));
                    float hp = hbase[(size_t)row * HD + jg];
                    hout[((size_t)s * NN + row) * HD + jg] = (1.f - z) * n + z * hp;
                }
}

// ---------------- fp32 f32x2 GEMM (GNN section) ----------------
__device__ __forceinline__ unsigned long long pack2(float x, float y) {
    unsigned long long r;
    asm("mov.b64 %0, {%1, %2};" : "=l"(r) : "f"(x), "f"(y));
    return r;
}
__device__ __forceinline__ void unpack2(unsigned long long v, float& x, float& y) {
    asm("mov.b64 {%0, %1}, %2;" : "=f"(x), "=f"(y) : "l"(v));
}
__device__ __forceinline__ void ffma2(unsigned long long& d, unsigned long long a,
                                      unsigned long long b) {
    asm("fma.rn.f32x2 %0, %1, %2, %0;" : "+l"(d) : "l"(a), "l"(b));
}

__global__ void __launch_bounds__(256) gemm_tn(
    const float* __restrict__ A, int lda,
    const float* __restrict__ B, int ldb,
    const float* __restrict__ bias,
    float* __restrict__ C, int ldc,
    int M, int K, int relu)
{
    __shared__ float As[16][128];
    __shared__ float Bs[16][64];
    const int tid = threadIdx.x;
    const int m0 = blockIdx.x * 128;
    const int n0 = blockIdx.y * 64;
    const int tx = tid & 15;
    const int ty = tid >> 4;

    unsigned long long acc[8][2];
#pragma unroll
    for (int i = 0; i < 8; i++) { acc[i][0] = 0ull; acc[i][1] = 0ull; }

    const int ar0 = tid >> 2;
    const int ar1 = (tid + 256) >> 2;
    const int aq = tid & 3;
    const int br = tid >> 2;
    const int bq = tid & 3;

    for (int k0 = 0; k0 < K; k0 += 16) {
        float4 va0 = make_float4(0.f, 0.f, 0.f, 0.f);
        float4 va1 = va0;
        if (m0 + ar0 < M) va0 = *(const float4*)(A + (size_t)(m0 + ar0) * lda + k0 + aq * 4);
        if (m0 + ar1 < M) va1 = *(const float4*)(A + (size_t)(m0 + ar1) * lda + k0 + aq * 4);
        float4 vb = *(const float4*)(B + (size_t)(n0 + br) * ldb + k0 + bq * 4);

        As[aq * 4 + 0][ar0] = va0.x; As[aq * 4 + 1][ar0] = va0.y;
        As[aq * 4 + 2][ar0] = va0.z; As[aq * 4 + 3][ar0] = va0.w;
        As[aq * 4 + 0][ar1] = va1.x; As[aq * 4 + 1][ar1] = va1.y;
        As[aq * 4 + 2][ar1] = va1.z; As[aq * 4 + 3][ar1] = va1.w;
        Bs[bq * 4 + 0][br] = vb.x; Bs[bq * 4 + 1][br] = vb.y;
        Bs[bq * 4 + 2][br] = vb.z; Bs[bq * 4 + 3][br] = vb.w;
        __syncthreads();

#pragma unroll
        for (int kk = 0; kk < 16; kk++) {
            float4 a0 = *(const float4*)&As[kk][ty * 8];
            float4 a1 = *(const float4*)&As[kk][ty * 8 + 4];
            unsigned long long b0 = *(const unsigned long long*)&Bs[kk][tx * 4];
            unsigned long long b1 = *(const unsigned long long*)&Bs[kk][tx * 4 + 2];
            float av[8] = {a0.x, a0.y, a0.z, a0.w, a1.x, a1.y, a1.z, a1.w};
#pragma unroll
            for (int i = 0; i < 8; i++) {
                unsigned long long a2 = pack2(av[i], av[i]);
                ffma2(acc[i][0], a2, b0);
                ffma2(acc[i][1], a2, b1);
            }
        }
        __syncthreads();
    }

    float b4[4] = {0.f, 0.f, 0.f, 0.f};
    if (bias) {
        float4 bv = *(const float4*)(bias + n0 + tx * 4);
        b4[0] = bv.x; b4[1] = bv.y; b4[2] = bv.z; b4[3] = bv.w;
    }
#pragma unroll
    for (int i = 0; i < 8; i++) {
        int m = m0 + ty * 8 + i;
        if (m < M) {
            float c0, c1, c2, c3;
            unpack2(acc[i][0], c0, c1);
            unpack2(acc[i][1], c2, c3);
            c0 += b4[0]; c1 += b4[1]; c2 += b4[2]; c3 += b4[3];
            if (relu) {
                c0 = fmaxf(c0, 0.f); c1 = fmaxf(c1, 0.f);
                c2 = fmaxf(c2, 0.f); c3 = fmaxf(c3, 0.f);
            }
            *(float4*)(C + (size_t)m * ldc + n0 + tx * 4) = make_float4(c0, c1, c2, c3);
        }
    }
}

__global__ void k_concat(const float* __restrict__ hs, const float* __restrict__ hm,
                         const float* __restrict__ hl) {
    int i = blockIdx.x * 256 + threadIdx.x;
    if (i >= NN * H3) return;
    int n = i / H3, j = i % H3;
    float v;
    if (j < 256)      v = hs[n * HD + j];
    else if (j < 512) v = hm[n * HD + j - 256];
    else              v = hl[n * HD + j - 512];
    d_COMB[i] = v;
}

// ---------------- SAGE attention (decomposed scores) ----------------
__device__ __forceinline__ unsigned fenc(float f) {
    unsigned u = __float_as_uint(f);
    return (u & 0x80000000u) ? ~u : (u | 0x80000000u);
}
__device__ __forceinline__ float fdec(unsigned u) {
    u = (u & 0x80000000u) ? (u & 0x7fffffffu) : ~u;
    return __uint_as_float(u);
}

__global__ void k_pq(const float* __restrict__ aw) {
    int n = blockIdx.x * 8 + (threadIdx.x >> 5);
    int lane = threadIdx.x & 31;
    if (n >= NN) return;
    float p = 0.f, q = 0.f;
#pragma unroll
    for (int j = lane; j < 256; j += 32) {
        float v = d_XL[n * GD + j];
        p += v * aw[j];
        q += v * aw[256 + j];
    }
#pragma unroll
    for (int o = 16; o; o >>= 1) {
        p += __shfl_xor_sync(0xffffffffu, p, o);
        q += __shfl_xor_sync(0xffffffffu, q, o);
    }
    if (lane == 0) { d_P[n] = p; d_Q[n] = q; }
}

__global__ void k_init() {
    int n = blockIdx.x * 256 + threadIdx.x;
    if (n < NN) { d_MENC[n] = 0x007fffffu; d_SSUM[n] = 0.f; }
}

__global__ void k_edge1(const int* __restrict__ ei, const float* __restrict__ ea,
                        const float* __restrict__ aw, const float* __restrict__ ab) {
    int e = blockIdx.x * 256 + threadIdx.x;
    if (e >= NE) return;
    int row = ei[e], col = ei[NE + e];
    float sc = d_P[row] + d_Q[col] + aw[512] * ea[e] + ab[0];
    d_SC[e] = sc;
    atomicMax(&d_MENC[row], fenc(sc));
}

__global__ void k_edge2(const int* __restrict__ ei) {
    int e = blockIdx.x * 256 + threadIdx.x;
    if (e >= NE) return;
    int row = ei[e];
    float m = fdec(d_MENC[row]);
    float ex = expf(d_SC[e] - m);
    d_SC[e] = ex;
    atomicAdd(&d_SSUM[row], ex);
}

__global__ void k_edge3(const int* __restrict__ ei) {
    int e = blockIdx.x * 4 + (threadIdx.x >> 6);
    int l = threadIdx.x & 63;
    if (e >= NE) return;
    int row = ei[e], col = ei[NE + e];
    float alpha = d_SC[e] / (d_SSUM[row] + 1e-16f);
    float4 v = *(const float4*)&d_XL[row * GD + l * 4];
    float* dst = &d_AGG[col * GD + l * 4];
    atomicAdd(dst + 0, alpha * v.x);
    atomicAdd(dst + 1, alpha * v.y);
    atomicAdd(dst + 2, alpha * v.z);
    atomicAdd(dst + 3, alpha * v.w);
}

__global__ void k_finish(const float* __restrict__ addsrc, float* __restrict__ dst) {
    int i = blockIdx.x * 256 + threadIdx.x;
    if (i >= NN * GD) return;
    float v = d_AGG[i];
    v = v > 0.f ? v : 0.f;
    if (addsrc) v += addsrc[i];
    dst[i] = v;
}

__global__ void k_heads(const float* __restrict__ impW, const float* __restrict__ impb,
                        const float* __restrict__ uncW, const float* __restrict__ uncb,
                        float* __restrict__ out) {
    int n = blockIdx.x * 8 + (threadIdx.x >> 5);
    int lane = threadIdx.x & 31;
    if (n >= NN) return;
    float a = 0.f, b = 0.f;
#pragma unroll
    for (int j = lane; j < GD; j += 32) {
        float v = d_G2[n * GD + j];
        a += v * impW[j];
        b += v * uncW[j];
    }
#pragma unroll
    for (int o = 16; o; o >>= 1) {
        a += __shfl_xor_sync(0xffffffffu, a, o);
        b += __shfl_xor_sync(0xffffffffu, b, o);
    }
    if (lane == 0) {
        out[n] = tanhf(a + impb[0]);
        out[NN + n] = 1.f / (1.f + expf(-(b + uncb[0])));
    }
}

// ---------------- host orchestration ----------------
extern "C" void kernel_launch(void* const* d_in, const int* in_sizes, int n_in,
                              void* d_out, int out_size)
{
    const float* x_s = (const float*)d_in[0];
    const float* x_m = (const float*)d_in[1];
    const float* x_l = (const float*)d_in[2];
    const int*   ei  = (const int*)d_in[3];
    const float* ea  = (const float*)d_in[4];
    // input order: s(5..8), m(9..12), l(13..16); our scale order: 0=l, 1=m, 2=s
    const float* Wih[3] = {(const float*)d_in[13], (const float*)d_in[9], (const float*)d_in[5]};
    const float* Whh[3] = {(const float*)d_in[14], (const float*)d_in[10], (const float*)d_in[6]};
    const float* bih[3] = {(const float*)d_in[15], (const float*)d_in[11], (const float*)d_in[7]};
    const float* bhh[3] = {(const float*)d_in[16], (const float*)d_in[12], (const float*)d_in[8]};
    const float* fW   = (const float*)d_in[17];
    const float* fb   = (const float*)d_in[18];
    const float* g1W  = (const float*)d_in[19];
    const float* g1aw = (const float*)d_in[20];
    const float* g1ab = (const float*)d_in[21];
    const float* g2W  = (const float*)d_in[22];
    const float* g2aw = (const float*)d_in[23];
    const float* g2ab = (const float*)d_in[24];
    const float* impW = (const float*)d_in[25];
    const float* impb = (const float*)d_in[26];
    const float* uncW = (const float*)d_in[27];
    const float* uncb = (const float*)d_in[28];

    void *pXGL, *pXGM, *pXGS, *pWHH, *pWIH, *pBIAS, *pHA, *pHB;
    void *pCOMB, *pTEMB, *pXL, *pAGG, *pG1, *pG2;
    cudaGetSymbolAddress(&pXGL, d_XGL);
    cudaGetSymbolAddress(&pXGM, d_XGM);
    cudaGetSymbolAddress(&pXGS, d_XGS);
    cudaGetSymbolAddress(&pWHH, d_WHH);
    cudaGetSymbolAddress(&pWIH, d_WIH);
    cudaGetSymbolAddress(&pBIAS, d_BIAS);
    cudaGetSymbolAddress(&pHA, d_HA);
    cudaGetSymbolAddress(&pHB, d_HB);
    cudaGetSymbolAddress(&pCOMB, d_COMB);
    cudaGetSymbolAddress(&pTEMB, d_TEMB);
    cudaGetSymbolAddress(&pXL, d_XL);
    cudaGetSymbolAddress(&pAGG, d_AGG);
    cudaGetSymbolAddress(&pG1, d_G1);
    cudaGetSymbolAddress(&pG2, d_G2);
    float* XG[3] = {(float*)pXGL, (float*)pXGM, (float*)pXGS};
    unsigned* WHHp = (unsigned*)pWHH;
    unsigned* WIHp = (unsigned*)pWIH;
    float* BIASp = (float*)pBIAS;
    float* HA = (float*)pHA; float* HB = (float*)pHB;
    float* COMB = (float*)pCOMB; float* TEMB = (float*)pTEMB;
    float* XL = (float*)pXL; float* AGG = (float*)pAGG;
    float* G1 = (float*)pG1; float* G2 = (float*)pG2;

    cudaFuncSetAttribute(gru_step,
                         cudaFuncAttributeMaxDynamicSharedMemorySize, STEP_SMEM);

    const float* xsrc[3] = {x_l, x_m, x_s};
    const int Ts[3] = {60, 30, 8};

    // ---- preconvert weights + fold biases ----
    for (int s = 0; s < 3; s++)
        k_prep<<<768, 256>>>(Whh[s], Wih[s], bih[s], bhh[s], s);

    // ---- XG precompute (parallel over all timesteps) ----
    for (int s = 0; s < 3; s++) {
        int M = NN * Ts[s];
        dim3 g((M + 127) / 128, 4);
        gemm_xg<<<g, 512>>>(xsrc[s], M, WIHp + s * 768 * 64, BIASp + s * 768, XG[s]);
    }

    // ---- recurrence: 60 merged steps ----
    cudaMemsetAsync(HA, 0, (size_t)3 * NN * HD * sizeof(float));
    for (int t = 0; t < 60; t++) {
        int nact = (t < 8) ? 3 : (t < 30) ? 2 : 1;
        float* hin  = (t & 1) ? HB : HA;
        float* hout = (t & 1) ? HA : HB;
        dim3 g(MB_PER_SCALE * nact, 4);
        gru_step<<<g, 512, STEP_SMEM>>>(
            hin, hout, WHHp,
            XG[0] + (size_t)t * 768, XG[1] + (size_t)t * 768, XG[2] + (size_t)t * 768,
            Ts[0] * 768, Ts[1] * 768, Ts[2] * 768,
            bhh[0], bhh[1], bhh[2]);
    }
    // finals all land in HA: 0=l, 1=m, 2=s
    float* HL = HA;
    float* HM = HA + (size_t)NN * HD;
    float* HS = HA + (size_t)2 * NN * HD;

    // ---- fusion ----
    dim3 gS((NN + 127) / 128, GD / 64);
    k_concat<<<(NN * H3 + 255) / 256, 256>>>(HS, HM, HL);
    gemm_tn<<<gS, 256>>>(COMB, H3, fW, H3, fb, TEMB, GD, NN, H3, 1);

    // ---- SAGE layer 1 ----
    gemm_tn<<<gS, 256>>>(TEMB, GD, g1W, GD, nullptr, XL, GD, NN, GD, 0);
    k_pq<<<(NN + 7) / 8, 256>>>(g1aw);
    k_init<<<(NN + 255) / 256, 256>>>();
    cudaMemsetAsync(AGG, 0, (size_t)NN * GD * sizeof(float));
    k_edge1<<<(NE + 255) / 256, 256>>>(ei, ea, g1aw, g1ab);
    k_edge2<<<(NE + 255) / 256, 256>>>(ei);
    k_edge3<<<NE / 4, 256>>>(ei);
    k_finish<<<(NN * GD + 255) / 256, 256>>>(nullptr, G1);

    // ---- SAGE layer 2 ----
    gemm_tn<<<gS, 256>>>(G1, GD, g2W, GD, nullptr, XL, GD, NN, GD, 0);
    k_pq<<<(NN + 7) / 8, 256>>>(g2aw);
    k_init<<<(NN + 255) / 256, 256>>>();
    cudaMemsetAsync(AGG, 0, (size_t)NN * GD * sizeof(float));
    k_edge1<<<(NE + 255) / 256, 256>>>(ei, ea, g2aw, g2ab);
    k_edge2<<<(NE + 255) / 256, 256>>>(ei);
    k_edge3<<<NE / 4, 256>>>(ei);
    k_finish<<<(NN * GD + 255) / 256, 256>>>(TEMB, G2);

    // ---- heads ----
    k_heads<<<(NN + 7) / 8, 256>>>(impW, impb, uncW, uncb, (float*)d_out);
}

// round 4
// speedup vs baseline: 1.4917x; 1.4917x over previous
#include <cuda_runtime.h>

#define NN 10000
#define NE 320000
#define FD 64
#define HD 256
#define GD 256
#define H3 768
#define MB 79                 // blocks per scale (ceil 10000/128)

#define AST 261               // h tile smem stride (words)
#define XST 69                // x tile smem stride
#define BST 36                // weight tile stride
#define ASM_W (128 * AST)
#define XSM_W (128 * XST)
#define BSM_W (192 * BST)
#define PERSIST_SMEM ((ASM_W + XSM_W + 2 * BSM_W) * 4)

// ---------------- static scratch ----------------
__device__ unsigned d_WHH[3 * 768 * 256];   // tf32, scale order l,m,s
__device__ unsigned d_WIH[3 * 768 * 64];
__device__ float d_BIAS[3 * 768];           // bih + (col<512 ? bhh : 0)
__device__ float d_HA[3 * NN * HD];
__device__ float d_HB[3 * NN * HD];
__device__ float d_COMB[NN * H3];
__device__ float d_TEMB[NN * GD];
__device__ float d_XL[NN * GD];
__device__ float d_AGG[NN * GD];
__device__ float d_G1[NN * GD];
__device__ float d_G2[NN * GD];
__device__ float d_P[NN];
__device__ float d_Q[NN];
__device__ float d_SSUM[NN];
__device__ unsigned d_MENC[NN];
__device__ float d_SC[NE];

// ---------------- helpers ----------------
__device__ __forceinline__ unsigned f2tf(float f) {
    unsigned r;
    asm("cvt.rna.tf32.f32 %0, %1;" : "=r"(r) : "f"(f));
    return r;
}
__device__ __forceinline__ float sigf(float x) { return 1.f / (1.f + expf(-x)); }

__device__ __forceinline__ void cp16(void* dst_smem, const void* src) {
    unsigned a = (unsigned)__cvta_generic_to_shared(dst_smem);
    asm volatile("cp.async.cg.shared.global [%0], [%1], 16;" :: "r"(a), "l"(src));
}
__device__ __forceinline__ void cp_commit() { asm volatile("cp.async.commit_group;"); }
__device__ __forceinline__ void cp_wait0() { asm volatile("cp.async.wait_group 0;"); }

__device__ __forceinline__ void mma_tf32(float* c, const unsigned* a, const unsigned* b) {
    asm volatile(
        "mma.sync.aligned.m16n8k8.row.col.f32.tf32.tf32.f32 "
        "{%0,%1,%2,%3},{%4,%5,%6,%7},{%8,%9},{%0,%1,%2,%3};"
        : "+f"(c[0]), "+f"(c[1]), "+f"(c[2]), "+f"(c[3])
        : "r"(a[0]), "r"(a[1]), "r"(a[2]), "r"(a[3]), "r"(b[0]), "r"(b[1]));
}

// ---------------- weight/bias preconversion ----------------
__global__ void k_prep(const float* __restrict__ whh, const float* __restrict__ wih,
                       const float* __restrict__ bih, const float* __restrict__ bhh,
                       int s) {
    int i = blockIdx.x * 256 + threadIdx.x;
    if (i < 768 * 256) d_WHH[s * 768 * 256 + i] = f2tf(whh[i]);
    if (i < 768 * 64)  d_WIH[s * 768 * 64 + i] = f2tf(wih[i]);
    if (i < 768)       d_BIAS[s * 768 + i] = bih[i] + (i < 512 ? bhh[i] : 0.f);
}

// ================== persistent GRU: all timesteps in one launch ==========
// Block = 128 nodes of one scale. Per step: gates[j] needs
//   r,z: [x|h]@W (K=320); n: x-part (K=64) and h-part (K=256) separately.
// 4 j-chunks of 64; acc chunks: 0=r,1=z,2=n_h,3=n_x.
__global__ void __launch_bounds__(512) gru_persist(
    float* __restrict__ hA, float* __restrict__ hB,
    const unsigned* __restrict__ whhAll, const unsigned* __restrict__ wihAll,
    const float* __restrict__ xL, const float* __restrict__ xM,
    const float* __restrict__ xS,
    const float* __restrict__ biasAll,
    const float* __restrict__ bhhL, const float* __restrict__ bhhM,
    const float* __restrict__ bhhS)
{
    extern __shared__ unsigned sm[];
    unsigned* Asm_ = sm;                       // h tf32 [128][AST]
    unsigned* Xsm = sm + ASM_W;                // x tf32 [128][XST]
    unsigned* B0 = sm + ASM_W + XSM_W;
    unsigned* B1 = B0 + BSM_W;

    const int tid = threadIdx.x;
    const int s = blockIdx.x / MB;             // 0=long,1=medium,2=short
    const int m0 = (blockIdx.x % MB) * 128;
    const int T = (s == 0) ? 60 : ((s == 1) ? 30 : 8);
    const float* xsrc = (s == 0) ? xL : ((s == 1) ? xM : xS);
    const float* bhh = (s == 0) ? bhhL : ((s == 1) ? bhhM : bhhS);
    const float* bias = biasAll + s * 768;
    const unsigned* wh = whhAll + (size_t)s * 768 * 256;
    const unsigned* wi = wihAll + (size_t)s * 768 * 64;
    float* ha = hA + (size_t)s * NN * HD;
    float* hb = hB + (size_t)s * NN * HD;

    const int lane = tid & 31, gid = lane >> 2, tig = lane & 3;
    const int warp = tid >> 5, wm = warp & 3, wn = warp >> 2;
    const int lrow = tid >> 2;                 // 0..127 loader row
    const int cbase = (tid & 3) * 4;           // col base for staging

#define CPB_H(kb, dst)                                                          \
    {                                                                           \
        _Pragma("unroll")                                                       \
        for (int p = 0; p < 3; p++) {                                           \
            int task = tid + p * 512;                                           \
            int q = task >> 3, ch = (task & 7) * 4;                             \
            int wrow = (q >> 6) * 256 + j0 + (q & 63);                          \
            cp16((dst) + q * BST + ch, wh + (size_t)wrow * 256 + (kb) * 32 + ch); \
        }                                                                       \
        cp_commit();                                                            \
    }
#define CPB_X(xb, dst)                                                          \
    {                                                                           \
        _Pragma("unroll")                                                       \
        for (int p = 0; p < 3; p++) {                                           \
            int task = tid + p * 512;                                           \
            int q = task >> 3, ch = (task & 7) * 4;                             \
            int wrow = (q >> 6) * 256 + j0 + (q & 63);                          \
            cp16((dst) + q * BST + ch, wi + (size_t)wrow * 64 + (xb) * 32 + ch); \
        }                                                                       \
        cp_commit();                                                            \
    }
#define FRAG_MMA(Ab, astr, XPH)                                                 \
    {                                                                           \
        _Pragma("unroll")                                                       \
        for (int ks = 0; ks < 4; ks++) {                                        \
            const int kk = ks * 8;                                              \
            unsigned af[2][4];                                                  \
            _Pragma("unroll")                                                   \
            for (int i = 0; i < 2; i++) {                                       \
                int ab = (wm * 32 + i * 16 + gid) * (astr) + kk + tig;          \
                af[i][0] = (Ab)[ab];                                            \
                af[i][1] = (Ab)[ab + 8 * (astr)];                               \
                af[i][2] = (Ab)[ab + 4];                                        \
                af[i][3] = (Ab)[ab + 8 * (astr) + 4];                           \
            }                                                                   \
            _Pragma("unroll")                                                   \
            for (int c = 0; c < 3; c++) {                                       \
                const int ci = ((XPH) && c == 2) ? 3 : c;                       \
                _Pragma("unroll")                                               \
                for (int u = 0; u < 2; u++) {                                   \
                    int qb = (c * 64 + wn * 16 + u * 8 + gid) * BST + kk + tig; \
                    unsigned bf[2] = {Bs[qb], Bs[qb + 4]};                      \
                    _Pragma("unroll")                                           \
                    for (int i = 0; i < 2; i++)                                 \
                        mma_tf32(acc[i][ci * 2 + u], af[i], bf);                \
                }                                                               \
            }                                                                   \
        }                                                                       \
    }

    for (int t = 0; t < T; t++) {
        const float* hin = (t & 1) ? hb : ha;
        float* hout = (t & 1) ? ha : hb;

        // ---- stage h (128x256) and x_t (128x64) into SMEM as tf32 ----
        {
            int grow = m0 + lrow;
            bool ok = grow < NN;
            const float* hr = hin + (size_t)grow * HD;
            unsigned* da = Asm_ + lrow * AST;
#pragma unroll
            for (int q = 0; q < 16; q++) {
                int col = cbase + q * 16;
                float4 v = ok ? *(const float4*)(hr + col)
                              : make_float4(0.f, 0.f, 0.f, 0.f);
                da[col + 0] = f2tf(v.x); da[col + 1] = f2tf(v.y);
                da[col + 2] = f2tf(v.z); da[col + 3] = f2tf(v.w);
            }
            const float* xr = xsrc + ((size_t)grow * T + t) * 64;
            unsigned* dx = Xsm + lrow * XST;
#pragma unroll
            for (int q = 0; q < 4; q++) {
                int col = cbase + q * 16;
                float4 v = ok ? *(const float4*)(xr + col)
                              : make_float4(0.f, 0.f, 0.f, 0.f);
                dx[col + 0] = f2tf(v.x); dx[col + 1] = f2tf(v.y);
                dx[col + 2] = f2tf(v.z); dx[col + 3] = f2tf(v.w);
            }
        }

        for (int jc = 0; jc < 4; jc++) {
            const int j0 = jc * 64;
            float acc[2][8][4];
#pragma unroll
            for (int i = 0; i < 2; i++)
#pragma unroll
                for (int j = 0; j < 8; j++)
#pragma unroll
                    for (int r = 0; r < 4; r++) acc[i][j][r] = 0.f;

            CPB_H(0, B0);
            cp_wait0();
            __syncthreads();   // also covers h/x staging before first use

            // h phase: K = 256 (8 chunks)
#pragma unroll
            for (int kb = 0; kb < 8; kb++) {
                unsigned* Bs = (kb & 1) ? B1 : B0;
                unsigned* Bn = (kb & 1) ? B0 : B1;
                if (kb < 7) { CPB_H(kb + 1, Bn); }
                else        { CPB_X(0, Bn); }
                FRAG_MMA(Asm_ + kb * 32, AST, 0);
                cp_wait0();
                __syncthreads();
            }
            // x phase: K = 64 (2 chunks)
#pragma unroll
            for (int xb = 0; xb < 2; xb++) {
                unsigned* Bs = (xb & 1) ? B1 : B0;
                if (xb == 0) { CPB_X(1, B1); }
                FRAG_MMA(Xsm + xb * 32, XST, 1);
                if (xb == 0) cp_wait0();
                __syncthreads();
            }

            // ---- epilogue: GRU update for these 64 j ----
#pragma unroll
            for (int i = 0; i < 2; i++)
#pragma unroll
                for (int u = 0; u < 2; u++)
#pragma unroll
                    for (int h2 = 0; h2 < 2; h2++)
#pragma unroll
                        for (int pp = 0; pp < 2; pp++) {
                            int row = m0 + wm * 32 + i * 16 + gid + h2 * 8;
                            if (row >= NN) continue;
                            int jg = j0 + wn * 16 + u * 8 + 2 * tig + pp;
                            int reg = h2 * 2 + pp;
                            float ar  = acc[i][0 + u][reg];
                            float az  = acc[i][2 + u][reg];
                            float anh = acc[i][4 + u][reg];
                            float anx = acc[i][6 + u][reg];
                            float r = sigf(ar + bias[jg]);
                            float z = sigf(az + bias[256 + jg]);
                            float n = tanhf(anx + bias[512 + jg] +
                                            r * (anh + bhh[512 + jg]));
                            float hp = hin[(size_t)row * HD + jg];
                            hout[(size_t)row * HD + jg] = (1.f - z) * n + z * hp;
                        }
        }
        __threadfence_block();
        __syncthreads();
    }
#undef CPB_H
#undef CPB_X
#undef FRAG_MMA
}

// ---------------- fp32 f32x2 GEMM (GNN section) ----------------
__device__ __forceinline__ unsigned long long pack2(float x, float y) {
    unsigned long long r;
    asm("mov.b64 %0, {%1, %2};" : "=l"(r) : "f"(x), "f"(y));
    return r;
}
__device__ __forceinline__ void unpack2(unsigned long long v, float& x, float& y) {
    asm("mov.b64 {%0, %1}, %2;" : "=f"(x), "=f"(y) : "l"(v));
}
__device__ __forceinline__ void ffma2(unsigned long long& d, unsigned long long a,
                                      unsigned long long b) {
    asm("fma.rn.f32x2 %0, %1, %2, %0;" : "+l"(d) : "l"(a), "l"(b));
}

__global__ void __launch_bounds__(256) gemm_tn(
    const float* __restrict__ A, int lda,
    const float* __restrict__ B, int ldb,
    const float* __restrict__ bias,
    float* __restrict__ C, int ldc,
    int M, int K, int relu)
{
    __shared__ float As[16][128];
    __shared__ float Bs[16][64];
    const int tid = threadIdx.x;
    const int m0 = blockIdx.x * 128;
    const int n0 = blockIdx.y * 64;
    const int tx = tid & 15;
    const int ty = tid >> 4;

    unsigned long long acc[8][2];
#pragma unroll
    for (int i = 0; i < 8; i++) { acc[i][0] = 0ull; acc[i][1] = 0ull; }

    const int ar0 = tid >> 2;
    const int ar1 = (tid + 256) >> 2;
    const int aq = tid & 3;
    const int br = tid >> 2;
    const int bq = tid & 3;

    for (int k0 = 0; k0 < K; k0 += 16) {
        float4 va0 = make_float4(0.f, 0.f, 0.f, 0.f);
        float4 va1 = va0;
        if (m0 + ar0 < M) va0 = *(const float4*)(A + (size_t)(m0 + ar0) * lda + k0 + aq * 4);
        if (m0 + ar1 < M) va1 = *(const float4*)(A + (size_t)(m0 + ar1) * lda + k0 + aq * 4);
        float4 vb = *(const float4*)(B + (size_t)(n0 + br) * ldb + k0 + bq * 4);

        As[aq * 4 + 0][ar0] = va0.x; As[aq * 4 + 1][ar0] = va0.y;
        As[aq * 4 + 2][ar0] = va0.z; As[aq * 4 + 3][ar0] = va0.w;
        As[aq * 4 + 0][ar1] = va1.x; As[aq * 4 + 1][ar1] = va1.y;
        As[aq * 4 + 2][ar1] = va1.z; As[aq * 4 + 3][ar1] = va1.w;
        Bs[bq * 4 + 0][br] = vb.x; Bs[bq * 4 + 1][br] = vb.y;
        Bs[bq * 4 + 2][br] = vb.z; Bs[bq * 4 + 3][br] = vb.w;
        __syncthreads();

#pragma unroll
        for (int kk = 0; kk < 16; kk++) {
            float4 a0 = *(const float4*)&As[kk][ty * 8];
            float4 a1 = *(const float4*)&As[kk][ty * 8 + 4];
            unsigned long long b0 = *(const unsigned long long*)&Bs[kk][tx * 4];
            unsigned long long b1 = *(const unsigned long long*)&Bs[kk][tx * 4 + 2];
            float av[8] = {a0.x, a0.y, a0.z, a0.w, a1.x, a1.y, a1.z, a1.w};
#pragma unroll
            for (int i = 0; i < 8; i++) {
                unsigned long long a2 = pack2(av[i], av[i]);
                ffma2(acc[i][0], a2, b0);
                ffma2(acc[i][1], a2, b1);
            }
        }
        __syncthreads();
    }

    float b4[4] = {0.f, 0.f, 0.f, 0.f};
    if (bias) {
        float4 bv = *(const float4*)(bias + n0 + tx * 4);
        b4[0] = bv.x; b4[1] = bv.y; b4[2] = bv.z; b4[3] = bv.w;
    }
#pragma unroll
    for (int i = 0; i < 8; i++) {
        int m = m0 + ty * 8 + i;
        if (m < M) {
            float c0, c1, c2, c3;
            unpack2(acc[i][0], c0, c1);
            unpack2(acc[i][1], c2, c3);
            c0 += b4[0]; c1 += b4[1]; c2 += b4[2]; c3 += b4[3];
            if (relu) {
                c0 = fmaxf(c0, 0.f); c1 = fmaxf(c1, 0.f);
                c2 = fmaxf(c2, 0.f); c3 = fmaxf(c3, 0.f);
            }
            *(float4*)(C + (size_t)m * ldc + n0 + tx * 4) = make_float4(c0, c1, c2, c3);
        }
    }
}

__global__ void k_concat(const float* __restrict__ hs, const float* __restrict__ hm,
                         const float* __restrict__ hl) {
    int i = blockIdx.x * 256 + threadIdx.x;
    if (i >= NN * H3) return;
    int n = i / H3, j = i % H3;
    float v;
    if (j < 256)      v = hs[n * HD + j];
    else if (j < 512) v = hm[n * HD + j - 256];
    else              v = hl[n * HD + j - 512];
    d_COMB[i] = v;
}

// ---------------- SAGE attention (decomposed scores) ----------------
__device__ __forceinline__ unsigned fenc(float f) {
    unsigned u = __float_as_uint(f);
    return (u & 0x80000000u) ? ~u : (u | 0x80000000u);
}
__device__ __forceinline__ float fdec(unsigned u) {
    u = (u & 0x80000000u) ? (u & 0x7fffffffu) : ~u;
    return __uint_as_float(u);
}

__global__ void k_pq(const float* __restrict__ aw) {
    int n = blockIdx.x * 8 + (threadIdx.x >> 5);
    int lane = threadIdx.x & 31;
    if (n >= NN) return;
    float p = 0.f, q = 0.f;
#pragma unroll
    for (int j = lane; j < 256; j += 32) {
        float v = d_XL[n * GD + j];
        p += v * aw[j];
        q += v * aw[256 + j];
    }
#pragma unroll
    for (int o = 16; o; o >>= 1) {
        p += __shfl_xor_sync(0xffffffffu, p, o);
        q += __shfl_xor_sync(0xffffffffu, q, o);
    }
    if (lane == 0) { d_P[n] = p; d_Q[n] = q; }
}

__global__ void k_init() {
    int n = blockIdx.x * 256 + threadIdx.x;
    if (n < NN) { d_MENC[n] = 0x007fffffu; d_SSUM[n] = 0.f; }
}

__global__ void k_edge1(const int* __restrict__ ei, const float* __restrict__ ea,
                        const float* __restrict__ aw, const float* __restrict__ ab) {
    int e = blockIdx.x * 256 + threadIdx.x;
    if (e >= NE) return;
    int row = ei[e], col = ei[NE + e];
    float sc = d_P[row] + d_Q[col] + aw[512] * ea[e] + ab[0];
    d_SC[e] = sc;
    atomicMax(&d_MENC[row], fenc(sc));
}

__global__ void k_edge2(const int* __restrict__ ei) {
    int e = blockIdx.x * 256 + threadIdx.x;
    if (e >= NE) return;
    int row = ei[e];
    float m = fdec(d_MENC[row]);
    float ex = expf(d_SC[e] - m);
    d_SC[e] = ex;
    atomicAdd(&d_SSUM[row], ex);
}

__global__ void k_edge3(const int* __restrict__ ei) {
    int e = blockIdx.x * 4 + (threadIdx.x >> 6);
    int l = threadIdx.x & 63;
    if (e >= NE) return;
    int row = ei[e], col = ei[NE + e];
    float alpha = d_SC[e] / (d_SSUM[row] + 1e-16f);
    float4 v = *(const float4*)&d_XL[row * GD + l * 4];
    float* dst = &d_AGG[col * GD + l * 4];
    atomicAdd(dst + 0, alpha * v.x);
    atomicAdd(dst + 1, alpha * v.y);
    atomicAdd(dst + 2, alpha * v.z);
    atomicAdd(dst + 3, alpha * v.w);
}

__global__ void k_finish(const float* __restrict__ addsrc, float* __restrict__ dst) {
    int i = blockIdx.x * 256 + threadIdx.x;
    if (i >= NN * GD) return;
    float v = d_AGG[i];
    v = v > 0.f ? v : 0.f;
    if (addsrc) v += addsrc[i];
    dst[i] = v;
}

__global__ void k_heads(const float* __restrict__ impW, const float* __restrict__ impb,
                        const float* __restrict__ uncW, const float* __restrict__ uncb,
                        float* __restrict__ out) {
    int n = blockIdx.x * 8 + (threadIdx.x >> 5);
    int lane = threadIdx.x & 31;
    if (n >= NN) return;
    float a = 0.f, b = 0.f;
#pragma unroll
    for (int j = lane; j < GD; j += 32) {
        float v = d_G2[n * GD + j];
        a += v * impW[j];
        b += v * uncW[j];
    }
#pragma unroll
    for (int o = 16; o; o >>= 1) {
        a += __shfl_xor_sync(0xffffffffu, a, o);
        b += __shfl_xor_sync(0xffffffffu, b, o);
    }
    if (lane == 0) {
        out[n] = tanhf(a + impb[0]);
        out[NN + n] = 1.f / (1.f + expf(-(b + uncb[0])));
    }
}

// ---------------- host orchestration ----------------
extern "C" void kernel_launch(void* const* d_in, const int* in_sizes, int n_in,
                              void* d_out, int out_size)
{
    const float* x_s = (const float*)d_in[0];
    const float* x_m = (const float*)d_in[1];
    const float* x_l = (const float*)d_in[2];
    const int*   ei  = (const int*)d_in[3];
    const float* ea  = (const float*)d_in[4];
    // scale order here: 0=long, 1=medium, 2=short
    const float* Wih[3] = {(const float*)d_in[13], (const float*)d_in[9], (const float*)d_in[5]};
    const float* Whh[3] = {(const float*)d_in[14], (const float*)d_in[10], (const float*)d_in[6]};
    const float* bih[3] = {(const float*)d_in[15], (const float*)d_in[11], (const float*)d_in[7]};
    const float* bhh[3] = {(const float*)d_in[16], (const float*)d_in[12], (const float*)d_in[8]};
    const float* fW   = (const float*)d_in[17];
    const float* fb   = (const float*)d_in[18];
    const float* g1W  = (const float*)d_in[19];
    const float* g1aw = (const float*)d_in[20];
    const float* g1ab = (const float*)d_in[21];
    const float* g2W  = (const float*)d_in[22];
    const float* g2aw = (const float*)d_in[23];
    const float* g2ab = (const float*)d_in[24];
    const float* impW = (const float*)d_in[25];
    const float* impb = (const float*)d_in[26];
    const float* uncW = (const float*)d_in[27];
    const float* uncb = (const float*)d_in[28];

    void *pWHH, *pWIH, *pBIAS, *pHA, *pHB;
    void *pCOMB, *pTEMB, *pXL, *pAGG, *pG1, *pG2;
    cudaGetSymbolAddress(&pWHH, d_WHH);
    cudaGetSymbolAddress(&pWIH, d_WIH);
    cudaGetSymbolAddress(&pBIAS, d_BIAS);
    cudaGetSymbolAddress(&pHA, d_HA);
    cudaGetSymbolAddress(&pHB, d_HB);
    cudaGetSymbolAddress(&pCOMB, d_COMB);
    cudaGetSymbolAddress(&pTEMB, d_TEMB);
    cudaGetSymbolAddress(&pXL, d_XL);
    cudaGetSymbolAddress(&pAGG, d_AGG);
    cudaGetSymbolAddress(&pG1, d_G1);
    cudaGetSymbolAddress(&pG2, d_G2);
    unsigned* WHHp = (unsigned*)pWHH;
    unsigned* WIHp = (unsigned*)pWIH;
    float* BIASp = (float*)pBIAS;
    float* HA = (float*)pHA; float* HB = (float*)pHB;
    float* COMB = (float*)pCOMB; float* TEMB = (float*)pTEMB;
    float* XL = (float*)pXL; float* AGG = (float*)pAGG;
    float* G1 = (float*)pG1; float* G2 = (float*)pG2;

    cudaFuncSetAttribute(gru_persist,
                         cudaFuncAttributeMaxDynamicSharedMemorySize, PERSIST_SMEM);

    // ---- preconvert weights + fold biases ----
    for (int s = 0; s < 3; s++)
        k_prep<<<768, 256>>>(Whh[s], Wih[s], bih[s], bhh[s], s);

    // ---- persistent recurrence: ONE launch for all 3 GRUs, all timesteps --
    cudaMemsetAsync(HA, 0, (size_t)3 * NN * HD * sizeof(float));
    gru_persist<<<3 * MB, 512, PERSIST_SMEM>>>(
        HA, HB, WHHp, WIHp, x_l, x_m, x_s, BIASp, bhh[0], bhh[1], bhh[2]);

    // finals all land in HA (T even for every scale): 0=l, 1=m, 2=s
    float* HL = HA;
    float* HM = HA + (size_t)NN * HD;
    float* HS = HA + (size_t)2 * NN * HD;

    // ---- fusion ----
    dim3 gS((NN + 127) / 128, GD / 64);
    k_concat<<<(NN * H3 + 255) / 256, 256>>>(HS, HM, HL);
    gemm_tn<<<gS, 256>>>(COMB, H3, fW, H3, fb, TEMB, GD, NN, H3, 1);

    // ---- SAGE layer 1 ----
    gemm_tn<<<gS, 256>>>(TEMB, GD, g1W, GD, nullptr, XL, GD, NN, GD, 0);
    k_pq<<<(NN + 7) / 8, 256>>>(g1aw);
    k_init<<<(NN + 255) / 256, 256>>>();
    cudaMemsetAsync(AGG, 0, (size_t)NN * GD * sizeof(float));
    k_edge1<<<(NE + 255) / 256, 256>>>(ei, ea, g1aw, g1ab);
    k_edge2<<<(NE + 255) / 256, 256>>>(ei);
    k_edge3<<<NE / 4, 256>>>(ei);
    k_finish<<<(NN * GD + 255) / 256, 256>>>(nullptr, G1);

    // ---- SAGE layer 2 ----
    gemm_tn<<<gS, 256>>>(G1, GD, g2W, GD, nullptr, XL, GD, NN, GD, 0);
    k_pq<<<(NN + 7) / 8, 256>>>(g2aw);
    k_init<<<(NN + 255) / 256, 256>>>();
    cudaMemsetAsync(AGG, 0, (size_t)NN * GD * sizeof(float));
    k_edge1<<<(NE + 255) / 256, 256>>>(ei, ea, g2aw, g2ab);
    k_edge2<<<(NE + 255) / 256, 256>>>(ei);
    k_edge3<<<NE / 4, 256>>>(ei);
    k_finish<<<(NN * GD + 255) / 256, 256>>>(TEMB, G2);

    // ---- heads ----
    k_heads<<<(NN + 7) / 8, 256>>>(impW, impb, uncW, uncb, (float*)d_out);
}

// round 5
// speedup vs baseline: 2.3563x; 1.5796x over previous
#include <cuda_runtime.h>
#include <cuda_fp16.h>

#define NN 10000
#define NE 320000
#define FD 64
#define HD 256
#define GD 256
#define H3 768
#define MB 79                 // blocks per scale (ceil 10000/128)

#define ASTH 264              // h tile smem stride (halves)
#define XSTH 72               // x tile smem stride (halves)
#define BSTH 40               // weight tile stride (halves)
#define ASM_H (128 * ASTH)
#define XSM_H (128 * XSTH)
#define BSM_H (192 * BSTH)
#define PERSIST_SMEM ((ASM_H + XSM_H + 2 * BSM_H) * 2)

// ---------------- static scratch ----------------
__device__ __half d_WHH[3 * 768 * 256];   // fp16, scale order l,m,s
__device__ __half d_WIH[3 * 768 * 64];
__device__ float d_BIAS[3 * 768];          // bih + (col<512 ? bhh : 0)
__device__ float d_HA[3 * NN * HD];
__device__ float d_HB[3 * NN * HD];
__device__ float d_COMB[NN * H3];
__device__ float d_TEMB[NN * GD];
__device__ float d_XL[NN * GD];
__device__ float d_AGG[NN * GD];
__device__ float d_G1[NN * GD];
__device__ float d_G2[NN * GD];
__device__ float d_P[NN];
__device__ float d_Q[NN];
__device__ float d_SSUM[NN];
__device__ unsigned d_MENC[NN];
__device__ float d_SC[NE];

// ---------------- helpers ----------------
__device__ __forceinline__ float sigf(float x) { return 1.f / (1.f + expf(-x)); }

__device__ __forceinline__ void cp16(void* dst_smem, const void* src) {
    unsigned a = (unsigned)__cvta_generic_to_shared(dst_smem);
    asm volatile("cp.async.cg.shared.global [%0], [%1], 16;" :: "r"(a), "l"(src));
}
__device__ __forceinline__ void cp_commit() { asm volatile("cp.async.commit_group;"); }
__device__ __forceinline__ void cp_wait0() { asm volatile("cp.async.wait_group 0;"); }

__device__ __forceinline__ void mma_f16(float* c, const unsigned* a, const unsigned* b) {
    asm volatile(
        "mma.sync.aligned.m16n8k16.row.col.f32.f16.f16.f32 "
        "{%0,%1,%2,%3},{%4,%5,%6,%7},{%8,%9},{%0,%1,%2,%3};"
        : "+f"(c[0]), "+f"(c[1]), "+f"(c[2]), "+f"(c[3])
        : "r"(a[0]), "r"(a[1]), "r"(a[2]), "r"(a[3]), "r"(b[0]), "r"(b[1]));
}

// ---------------- weight/bias preconversion ----------------
__global__ void k_prep(const float* __restrict__ whh, const float* __restrict__ wih,
                       const float* __restrict__ bih, const float* __restrict__ bhh,
                       int s) {
    int i = blockIdx.x * 256 + threadIdx.x;
    if (i < 768 * 256) d_WHH[s * 768 * 256 + i] = __float2half_rn(whh[i]);
    if (i < 768 * 64)  d_WIH[s * 768 * 64 + i] = __float2half_rn(wih[i]);
    if (i < 768)       d_BIAS[s * 768 + i] = bih[i] + (i < 512 ? bhh[i] : 0.f);
}

// ================== persistent GRU: fp16 mma, all timesteps ==========
__global__ void __launch_bounds__(512) gru_persist(
    float* __restrict__ hA, float* __restrict__ hB,
    const __half* __restrict__ whhAll, const __half* __restrict__ wihAll,
    const float* __restrict__ xL, const float* __restrict__ xM,
    const float* __restrict__ xS,
    const float* __restrict__ biasAll,
    const float* __restrict__ bhhL, const float* __restrict__ bhhM,
    const float* __restrict__ bhhS)
{
    extern __shared__ __half smh[];
    __half* Ah = smh;                       // h fp16 [128][ASTH]
    __half* Xh = smh + ASM_H;               // x fp16 [128][XSTH]
    __half* B0 = smh + ASM_H + XSM_H;
    __half* B1 = B0 + BSM_H;

    const int tid = threadIdx.x;
    const int s = blockIdx.x / MB;             // 0=long,1=medium,2=short
    const int m0 = (blockIdx.x % MB) * 128;
    const int T = (s == 0) ? 60 : ((s == 1) ? 30 : 8);
    const float* xsrc = (s == 0) ? xL : ((s == 1) ? xM : xS);
    const float* bhh = (s == 0) ? bhhL : ((s == 1) ? bhhM : bhhS);
    const float* bias = biasAll + s * 768;
    const __half* wh = whhAll + (size_t)s * 768 * 256;
    const __half* wi = wihAll + (size_t)s * 768 * 64;
    float* ha = hA + (size_t)s * NN * HD;
    float* hb = hB + (size_t)s * NN * HD;

    const int lane = tid & 31, gid = lane >> 2, tig = lane & 3;
    const int warp = tid >> 5, wm = warp & 3, wn = warp >> 2;
    const int lrow = tid >> 2;                 // 0..127 loader row
    const int cbase = (tid & 3) * 4;           // col base for staging

    // weight cp tasks: 192 rows x 4 chunks(16B=8 halves) = 768 tasks
#define CPB_H(kb, dst)                                                          \
    {                                                                           \
        _Pragma("unroll")                                                       \
        for (int p = 0; p < 2; p++) {                                           \
            int task = tid + p * 512;                                           \
            if (task < 768) {                                                   \
                int q = task >> 2, ch = (task & 3) * 8;                         \
                int wrow = (q >> 6) * 256 + j0 + (q & 63);                      \
                cp16((dst) + q * BSTH + ch,                                     \
                     wh + (size_t)wrow * 256 + (kb) * 32 + ch);                 \
            }                                                                   \
        }                                                                       \
        cp_commit();                                                            \
    }
#define CPB_X(xb, dst)                                                          \
    {                                                                           \
        _Pragma("unroll")                                                       \
        for (int p = 0; p < 2; p++) {                                           \
            int task = tid + p * 512;                                           \
            if (task < 768) {                                                   \
                int q = task >> 2, ch = (task & 3) * 8;                         \
                int wrow = (q >> 6) * 256 + j0 + (q & 63);                      \
                cp16((dst) + q * BSTH + ch,                                     \
                     wi + (size_t)wrow * 64 + (xb) * 32 + ch);                  \
            }                                                                   \
        }                                                                       \
        cp_commit();                                                            \
    }
// one 32-wide K chunk: 2 k16 steps; XPH remaps c==2 accumulator to n_x
#define FRAG_MMA(Ab, astr, kbase, XPH)                                          \
    {                                                                           \
        _Pragma("unroll")                                                       \
        for (int ks = 0; ks < 2; ks++) {                                        \
            const int k0 = (kbase) + ks * 16;                                   \
            unsigned af[2][4];                                                  \
            _Pragma("unroll")                                                   \
            for (int i = 0; i < 2; i++) {                                       \
                int ab = (wm * 32 + i * 16 + gid) * (astr) + k0 + 2 * tig;      \
                af[i][0] = *(const unsigned*)((Ab) + ab);                       \
                af[i][1] = *(const unsigned*)((Ab) + ab + 8 * (astr));          \
                af[i][2] = *(const unsigned*)((Ab) + ab + 8);                   \
                af[i][3] = *(const unsigned*)((Ab) + ab + 8 * (astr) + 8);      \
            }                                                                   \
            _Pragma("unroll")                                                   \
            for (int c = 0; c < 3; c++) {                                       \
                const int ci = ((XPH) && c == 2) ? 3 : c;                       \
                _Pragma("unroll")                                               \
                for (int u = 0; u < 2; u++) {                                   \
                    int qb = (c * 64 + wn * 16 + u * 8 + gid) * BSTH            \
                             + ks * 16 + 2 * tig;                               \
                    unsigned bf[2];                                             \
                    bf[0] = *(const unsigned*)(Bs + qb);                        \
                    bf[1] = *(const unsigned*)(Bs + qb + 8);                    \
                    _Pragma("unroll")                                           \
                    for (int i = 0; i < 2; i++)                                 \
                        mma_f16(acc[i][ci * 2 + u], af[i], bf);                 \
                }                                                               \
            }                                                                   \
        }                                                                       \
    }

    for (int t = 0; t < T; t++) {
        const float* hin = (t & 1) ? hb : ha;
        float* hout = (t & 1) ? ha : hb;

        // ---- stage h (128x256) and x_t (128x64) into SMEM as fp16 ----
        {
            int grow = m0 + lrow;
            bool ok = grow < NN;
            const float* hr = hin + (size_t)grow * HD;
            __half* da = Ah + lrow * ASTH;
#pragma unroll
            for (int q = 0; q < 16; q++) {
                int col = cbase + q * 16;
                float4 v = ok ? *(const float4*)(hr + col)
                              : make_float4(0.f, 0.f, 0.f, 0.f);
                *(__half2*)(da + col)     = __floats2half2_rn(v.x, v.y);
                *(__half2*)(da + col + 2) = __floats2half2_rn(v.z, v.w);
            }
            const float* xr = xsrc + ((size_t)grow * T + t) * 64;
            __half* dx = Xh + lrow * XSTH;
#pragma unroll
            for (int q = 0; q < 4; q++) {
                int col = cbase + q * 16;
                float4 v = ok ? *(const float4*)(xr + col)
                              : make_float4(0.f, 0.f, 0.f, 0.f);
                *(__half2*)(dx + col)     = __floats2half2_rn(v.x, v.y);
                *(__half2*)(dx + col + 2) = __floats2half2_rn(v.z, v.w);
            }
        }

        for (int jc = 0; jc < 4; jc++) {
            const int j0 = jc * 64;
            float acc[2][8][4];
#pragma unroll
            for (int i = 0; i < 2; i++)
#pragma unroll
                for (int j = 0; j < 8; j++)
#pragma unroll
                    for (int r = 0; r < 4; r++) acc[i][j][r] = 0.f;

            CPB_H(0, B0);
            cp_wait0();
            __syncthreads();   // covers h/x staging before first use

            // h phase: K = 256 (8 chunks of 32)
#pragma unroll
            for (int kb = 0; kb < 8; kb++) {
                __half* Bs = (kb & 1) ? B1 : B0;
                __half* Bn = (kb & 1) ? B0 : B1;
                if (kb < 7) { CPB_H(kb + 1, Bn); }
                else        { CPB_X(0, Bn); }
                FRAG_MMA(Ah, ASTH, kb * 32, 0);
                cp_wait0();
                __syncthreads();
            }
            // x phase: K = 64 (2 chunks of 32)
#pragma unroll
            for (int xb = 0; xb < 2; xb++) {
                __half* Bs = (xb & 1) ? B1 : B0;
                if (xb == 0) { CPB_X(1, B1); }
                FRAG_MMA(Xh, XSTH, xb * 32, 1);
                if (xb == 0) cp_wait0();
                __syncthreads();
            }

            // ---- epilogue: GRU update for these 64 j ----
#pragma unroll
            for (int i = 0; i < 2; i++)
#pragma unroll
                for (int u = 0; u < 2; u++)
#pragma unroll
                    for (int h2 = 0; h2 < 2; h2++)
#pragma unroll
                        for (int pp = 0; pp < 2; pp++) {
                            int row = m0 + wm * 32 + i * 16 + gid + h2 * 8;
                            if (row >= NN) continue;
                            int jg = j0 + wn * 16 + u * 8 + 2 * tig + pp;
                            int reg = h2 * 2 + pp;
                            float ar  = acc[i][0 + u][reg];
                            float az  = acc[i][2 + u][reg];
                            float anh = acc[i][4 + u][reg];
                            float anx = acc[i][6 + u][reg];
                            float r = sigf(ar + bias[jg]);
                            float z = sigf(az + bias[256 + jg]);
                            float n = tanhf(anx + bias[512 + jg] +
                                            r * (anh + bhh[512 + jg]));
                            float hp = hin[(size_t)row * HD + jg];
                            hout[(size_t)row * HD + jg] = (1.f - z) * n + z * hp;
                        }
        }
        __threadfence_block();
        __syncthreads();
    }
#undef CPB_H
#undef CPB_X
#undef FRAG_MMA
}

// ---------------- fp32 f32x2 GEMM (GNN section) ----------------
__device__ __forceinline__ unsigned long long pack2(float x, float y) {
    unsigned long long r;
    asm("mov.b64 %0, {%1, %2};" : "=l"(r) : "f"(x), "f"(y));
    return r;
}
__device__ __forceinline__ void unpack2(unsigned long long v, float& x, float& y) {
    asm("mov.b64 {%0, %1}, %2;" : "=f"(x), "=f"(y) : "l"(v));
}
__device__ __forceinline__ void ffma2(unsigned long long& d, unsigned long long a,
                                      unsigned long long b) {
    asm("fma.rn.f32x2 %0, %1, %2, %0;" : "+l"(d) : "l"(a), "l"(b));
}

__global__ void __launch_bounds__(256) gemm_tn(
    const float* __restrict__ A, int lda,
    const float* __restrict__ B, int ldb,
    const float* __restrict__ bias,
    float* __restrict__ C, int ldc,
    int M, int K, int relu)
{
    __shared__ float As[16][128];
    __shared__ float Bs[16][64];
    const int tid = threadIdx.x;
    const int m0 = blockIdx.x * 128;
    const int n0 = blockIdx.y * 64;
    const int tx = tid & 15;
    const int ty = tid >> 4;

    unsigned long long acc[8][2];
#pragma unroll
    for (int i = 0; i < 8; i++) { acc[i][0] = 0ull; acc[i][1] = 0ull; }

    const int ar0 = tid >> 2;
    const int ar1 = (tid + 256) >> 2;
    const int aq = tid & 3;
    const int br = tid >> 2;
    const int bq = tid & 3;

    for (int k0 = 0; k0 < K; k0 += 16) {
        float4 va0 = make_float4(0.f, 0.f, 0.f, 0.f);
        float4 va1 = va0;
        if (m0 + ar0 < M) va0 = *(const float4*)(A + (size_t)(m0 + ar0) * lda + k0 + aq * 4);
        if (m0 + ar1 < M) va1 = *(const float4*)(A + (size_t)(m0 + ar1) * lda + k0 + aq * 4);
        float4 vb = *(const float4*)(B + (size_t)(n0 + br) * ldb + k0 + bq * 4);

        As[aq * 4 + 0][ar0] = va0.x; As[aq * 4 + 1][ar0] = va0.y;
        As[aq * 4 + 2][ar0] = va0.z; As[aq * 4 + 3][ar0] = va0.w;
        As[aq * 4 + 0][ar1] = va1.x; As[aq * 4 + 1][ar1] = va1.y;
        As[aq * 4 + 2][ar1] = va1.z; As[aq * 4 + 3][ar1] = va1.w;
        Bs[bq * 4 + 0][br] = vb.x; Bs[bq * 4 + 1][br] = vb.y;
        Bs[bq * 4 + 2][br] = vb.z; Bs[bq * 4 + 3][br] = vb.w;
        __syncthreads();

#pragma unroll
        for (int kk = 0; kk < 16; kk++) {
            float4 a0 = *(const float4*)&As[kk][ty * 8];
            float4 a1 = *(const float4*)&As[kk][ty * 8 + 4];
            unsigned long long b0 = *(const unsigned long long*)&Bs[kk][tx * 4];
            unsigned long long b1 = *(const unsigned long long*)&Bs[kk][tx * 4 + 2];
            float av[8] = {a0.x, a0.y, a0.z, a0.w, a1.x, a1.y, a1.z, a1.w};
#pragma unroll
            for (int i = 0; i < 8; i++) {
                unsigned long long a2 = pack2(av[i], av[i]);
                ffma2(acc[i][0], a2, b0);
                ffma2(acc[i][1], a2, b1);
            }
        }
        __syncthreads();
    }

    float b4[4] = {0.f, 0.f, 0.f, 0.f};
    if (bias) {
        float4 bv = *(const float4*)(bias + n0 + tx * 4);
        b4[0] = bv.x; b4[1] = bv.y; b4[2] = bv.z; b4[3] = bv.w;
    }
#pragma unroll
    for (int i = 0; i < 8; i++) {
        int m = m0 + ty * 8 + i;
        if (m < M) {
            float c0, c1, c2, c3;
            unpack2(acc[i][0], c0, c1);
            unpack2(acc[i][1], c2, c3);
            c0 += b4[0]; c1 += b4[1]; c2 += b4[2]; c3 += b4[3];
            if (relu) {
                c0 = fmaxf(c0, 0.f); c1 = fmaxf(c1, 0.f);
                c2 = fmaxf(c2, 0.f); c3 = fmaxf(c3, 0.f);
            }
            *(float4*)(C + (size_t)m * ldc + n0 + tx * 4) = make_float4(c0, c1, c2, c3);
        }
    }
}

__global__ void k_concat(const float* __restrict__ hs, const float* __restrict__ hm,
                         const float* __restrict__ hl) {
    int i = blockIdx.x * 256 + threadIdx.x;
    if (i >= NN * H3) return;
    int n = i / H3, j = i % H3;
    float v;
    if (j < 256)      v = hs[n * HD + j];
    else if (j < 512) v = hm[n * HD + j - 256];
    else              v = hl[n * HD + j - 512];
    d_COMB[i] = v;
}

// ---------------- SAGE attention (decomposed scores) ----------------
__device__ __forceinline__ unsigned fenc(float f) {
    unsigned u = __float_as_uint(f);
    return (u & 0x80000000u) ? ~u : (u | 0x80000000u);
}
__device__ __forceinline__ float fdec(unsigned u) {
    u = (u & 0x80000000u) ? (u & 0x7fffffffu) : ~u;
    return __uint_as_float(u);
}

__global__ void k_pq(const float* __restrict__ aw) {
    int n = blockIdx.x * 8 + (threadIdx.x >> 5);
    int lane = threadIdx.x & 31;
    if (n >= NN) return;
    float p = 0.f, q = 0.f;
#pragma unroll
    for (int j = lane; j < 256; j += 32) {
        float v = d_XL[n * GD + j];
        p += v * aw[j];
        q += v * aw[256 + j];
    }
#pragma unroll
    for (int o = 16; o; o >>= 1) {
        p += __shfl_xor_sync(0xffffffffu, p, o);
        q += __shfl_xor_sync(0xffffffffu, q, o);
    }
    if (lane == 0) { d_P[n] = p; d_Q[n] = q; }
}

__global__ void k_init() {
    int n = blockIdx.x * 256 + threadIdx.x;
    if (n < NN) { d_MENC[n] = 0x007fffffu; d_SSUM[n] = 0.f; }
}

__global__ void k_edge1(const int* __restrict__ ei, const float* __restrict__ ea,
                        const float* __restrict__ aw, const float* __restrict__ ab) {
    int e = blockIdx.x * 256 + threadIdx.x;
    if (e >= NE) return;
    int row = ei[e], col = ei[NE + e];
    float sc = d_P[row] + d_Q[col] + aw[512] * ea[e] + ab[0];
    d_SC[e] = sc;
    atomicMax(&d_MENC[row], fenc(sc));
}

__global__ void k_edge2(const int* __restrict__ ei) {
    int e = blockIdx.x * 256 + threadIdx.x;
    if (e >= NE) return;
    int row = ei[e];
    float m = fdec(d_MENC[row]);
    float ex = expf(d_SC[e] - m);
    d_SC[e] = ex;
    atomicAdd(&d_SSUM[row], ex);
}

__global__ void k_edge3(const int* __restrict__ ei) {
    int e = blockIdx.x * 4 + (threadIdx.x >> 6);
    int l = threadIdx.x & 63;
    if (e >= NE) return;
    int row = ei[e], col = ei[NE + e];
    float alpha = d_SC[e] / (d_SSUM[row] + 1e-16f);
    float4 v = *(const float4*)&d_XL[row * GD + l * 4];
    float* dst = &d_AGG[col * GD + l * 4];
    atomicAdd(dst + 0, alpha * v.x);
    atomicAdd(dst + 1, alpha * v.y);
    atomicAdd(dst + 2, alpha * v.z);
    atomicAdd(dst + 3, alpha * v.w);
}

__global__ void k_finish(const float* __restrict__ addsrc, float* __restrict__ dst) {
    int i = blockIdx.x * 256 + threadIdx.x;
    if (i >= NN * GD) return;
    float v = d_AGG[i];
    v = v > 0.f ? v : 0.f;
    if (addsrc) v += addsrc[i];
    dst[i] = v;
}

__global__ void k_heads(const float* __restrict__ impW, const float* __restrict__ impb,
                        const float* __restrict__ uncW, const float* __restrict__ uncb,
                        float* __restrict__ out) {
    int n = blockIdx.x * 8 + (threadIdx.x >> 5);
    int lane = threadIdx.x & 31;
    if (n >= NN) return;
    float a = 0.f, b = 0.f;
#pragma unroll
    for (int j = lane; j < GD; j += 32) {
        float v = d_G2[n * GD + j];
        a += v * impW[j];
        b += v * uncW[j];
    }
#pragma unroll
    for (int o = 16; o; o >>= 1) {
        a += __shfl_xor_sync(0xffffffffu, a, o);
        b += __shfl_xor_sync(0xffffffffu, b, o);
    }
    if (lane == 0) {
        out[n] = tanhf(a + impb[0]);
        out[NN + n] = 1.f / (1.f + expf(-(b + uncb[0])));
    }
}

// ---------------- host orchestration ----------------
extern "C" void kernel_launch(void* const* d_in, const int* in_sizes, int n_in,
                              void* d_out, int out_size)
{
    const float* x_s = (const float*)d_in[0];
    const float* x_m = (const float*)d_in[1];
    const float* x_l = (const float*)d_in[2];
    const int*   ei  = (const int*)d_in[3];
    const float* ea  = (const float*)d_in[4];
    // scale order here: 0=long, 1=medium, 2=short
    const float* Wih[3] = {(const float*)d_in[13], (const float*)d_in[9], (const float*)d_in[5]};
    const float* Whh[3] = {(const float*)d_in[14], (const float*)d_in[10], (const float*)d_in[6]};
    const float* bih[3] = {(const float*)d_in[15], (const float*)d_in[11], (const float*)d_in[7]};
    const float* bhh[3] = {(const float*)d_in[16], (const float*)d_in[12], (const float*)d_in[8]};
    const float* fW   = (const float*)d_in[17];
    const float* fb   = (const float*)d_in[18];
    const float* g1W  = (const float*)d_in[19];
    const float* g1aw = (const float*)d_in[20];
    const float* g1ab = (const float*)d_in[21];
    const float* g2W  = (const float*)d_in[22];
    const float* g2aw = (const float*)d_in[23];
    const float* g2ab = (const float*)d_in[24];
    const float* impW = (const float*)d_in[25];
    const float* impb = (const float*)d_in[26];
    const float* uncW = (const float*)d_in[27];
    const float* uncb = (const float*)d_in[28];

    void *pWHH, *pWIH, *pBIAS, *pHA, *pHB;
    void *pCOMB, *pTEMB, *pXL, *pAGG, *pG1, *pG2;
    cudaGetSymbolAddress(&pWHH, d_WHH);
    cudaGetSymbolAddress(&pWIH, d_WIH);
    cudaGetSymbolAddress(&pBIAS, d_BIAS);
    cudaGetSymbolAddress(&pHA, d_HA);
    cudaGetSymbolAddress(&pHB, d_HB);
    cudaGetSymbolAddress(&pCOMB, d_COMB);
    cudaGetSymbolAddress(&pTEMB, d_TEMB);
    cudaGetSymbolAddress(&pXL, d_XL);
    cudaGetSymbolAddress(&pAGG, d_AGG);
    cudaGetSymbolAddress(&pG1, d_G1);
    cudaGetSymbolAddress(&pG2, d_G2);
    __half* WHHp = (__half*)pWHH;
    __half* WIHp = (__half*)pWIH;
    float* BIASp = (float*)pBIAS;
    float* HA = (float*)pHA; float* HB = (float*)pHB;
    float* COMB = (float*)pCOMB; float* TEMB = (float*)pTEMB;
    float* XL = (float*)pXL; float* AGG = (float*)pAGG;
    float* G1 = (float*)pG1; float* G2 = (float*)pG2;

    cudaFuncSetAttribute(gru_persist,
                         cudaFuncAttributeMaxDynamicSharedMemorySize, PERSIST_SMEM);

    // ---- preconvert weights + fold biases ----
    for (int s = 0; s < 3; s++)
        k_prep<<<768, 256>>>(Whh[s], Wih[s], bih[s], bhh[s], s);

    // ---- persistent recurrence: ONE launch for all 3 GRUs, all timesteps --
    cudaMemsetAsync(HA, 0, (size_t)3 * NN * HD * sizeof(float));
    gru_persist<<<3 * MB, 512, PERSIST_SMEM>>>(
        HA, HB, WHHp, WIHp, x_l, x_m, x_s, BIASp, bhh[0], bhh[1], bhh[2]);

    // finals all land in HA (T even for every scale): 0=l, 1=m, 2=s
    float* HL = HA;
    float* HM = HA + (size_t)NN * HD;
    float* HS = HA + (size_t)2 * NN * HD;

    // ---- fusion ----
    dim3 gS((NN + 127) / 128, GD / 64);
    k_concat<<<(NN * H3 + 255) / 256, 256>>>(HS, HM, HL);
    gemm_tn<<<gS, 256>>>(COMB, H3, fW, H3, fb, TEMB, GD, NN, H3, 1);

    // ---- SAGE layer 1 ----
    gemm_tn<<<gS, 256>>>(TEMB, GD, g1W, GD, nullptr, XL, GD, NN, GD, 0);
    k_pq<<<(NN + 7) / 8, 256>>>(g1aw);
    k_init<<<(NN + 255) / 256, 256>>>();
    cudaMemsetAsync(AGG, 0, (size_t)NN * GD * sizeof(float));
    k_edge1<<<(NE + 255) / 256, 256>>>(ei, ea, g1aw, g1ab);
    k_edge2<<<(NE + 255) / 256, 256>>>(ei);
    k_edge3<<<NE / 4, 256>>>(ei);
    k_finish<<<(NN * GD + 255) / 256, 256>>>(nullptr, G1);

    // ---- SAGE layer 2 ----
    gemm_tn<<<gS, 256>>>(G1, GD, g2W, GD, nullptr, XL, GD, NN, GD, 0);
    k_pq<<<(NN + 7) / 8, 256>>>(g2aw);
    k_init<<<(NN + 255) / 256, 256>>>();
    cudaMemsetAsync(AGG, 0, (size_t)NN * GD * sizeof(float));
    k_edge1<<<(NE + 255) / 256, 256>>>(ei, ea, g2aw, g2ab);
    k_edge2<<<(NE + 255) / 256, 256>>>(ei);
    k_edge3<<<NE / 4, 256>>>(ei);
    k_finish<<<(NN * GD + 255) / 256, 256>>>(TEMB, G2);

    // ---- heads ----
    k_heads<<<(NN + 7) / 8, 256>>>(impW, impb, uncW, uncb, (float*)d_out);
}

// round 6
// speedup vs baseline: 2.3699x; 1.0058x over previous
#include <cuda_runtime.h>
#include <cuda_fp16.h>

#define NN 10000
#define NE 320000
#define FD 64
#define HD 256
#define GD 256
#define H3 768
#define MB 79                 // blocks per scale (ceil 10000/128)

#define ASTH 264              // h tile smem stride (halves)
#define XSTH 72               // x tile smem stride (halves)
#define BSTH 72               // weight tile stride (halves), k=64 chunks
#define ASM_H (128 * ASTH)
#define XSM_H (128 * XSTH)
#define BSM_H (192 * BSTH)
#define PERSIST_SMEM ((ASM_H + XSM_H + 3 * BSM_H) * 2)

// ---------------- static scratch ----------------
__device__ __half d_WHH[3 * 768 * 256];   // fp16, scale order l,m,s
__device__ __half d_WIH[3 * 768 * 64];
__device__ float d_BIAS[3 * 768];          // bih + (col<512 ? bhh : 0)
__device__ float d_HA[3 * NN * HD];
__device__ float d_HB[3 * NN * HD];
__device__ float d_COMB[NN * H3];
__device__ float d_TEMB[NN * GD];
__device__ float d_XL[NN * GD];
__device__ float d_AGG[NN * GD];
__device__ float d_G1[NN * GD];
__device__ float d_G2[NN * GD];
__device__ float d_P[NN];
__device__ float d_Q[NN];
__device__ float d_SSUM[NN];
__device__ unsigned d_MENC[NN];
__device__ float d_SC[NE];

// ---------------- helpers ----------------
__device__ __forceinline__ float sigf(float x) { return 1.f / (1.f + expf(-x)); }

__device__ __forceinline__ void cp16(void* dst_smem, const void* src) {
    unsigned a = (unsigned)__cvta_generic_to_shared(dst_smem);
    asm volatile("cp.async.cg.shared.global [%0], [%1], 16;" :: "r"(a), "l"(src));
}
__device__ __forceinline__ void cp_commit() { asm volatile("cp.async.commit_group;"); }
__device__ __forceinline__ void cp_wait0() { asm volatile("cp.async.wait_group 0;"); }
__device__ __forceinline__ void cp_wait1() { asm volatile("cp.async.wait_group 1;"); }

__device__ __forceinline__ void mma_f16(float* c, const unsigned* a, const unsigned* b) {
    asm volatile(
        "mma.sync.aligned.m16n8k16.row.col.f32.f16.f16.f32 "
        "{%0,%1,%2,%3},{%4,%5,%6,%7},{%8,%9},{%0,%1,%2,%3};"
        : "+f"(c[0]), "+f"(c[1]), "+f"(c[2]), "+f"(c[3])
        : "r"(a[0]), "r"(a[1]), "r"(a[2]), "r"(a[3]), "r"(b[0]), "r"(b[1]));
}

// ---------------- weight/bias preconversion ----------------
__global__ void k_prep(const float* __restrict__ whh, const float* __restrict__ wih,
                       const float* __restrict__ bih, const float* __restrict__ bhh,
                       int s) {
    int i = blockIdx.x * 256 + threadIdx.x;
    if (i < 768 * 256) d_WHH[s * 768 * 256 + i] = __float2half_rn(whh[i]);
    if (i < 768 * 64)  d_WIH[s * 768 * 64 + i] = __float2half_rn(wih[i]);
    if (i < 768)       d_BIAS[s * 768 + i] = bih[i] + (i < 512 ? bhh[i] : 0.f);
}

// ================== persistent GRU: fp16 mma, k64 chunks, 3-stage ring =====
// 20 chunks/step: jc(4) x [4 h-phase k64 + 1 x-phase k64]. B tile 192x64.
__global__ void __launch_bounds__(512) gru_persist(
    float* __restrict__ hA, float* __restrict__ hB,
    const __half* __restrict__ whhAll, const __half* __restrict__ wihAll,
    const float* __restrict__ xL, const float* __restrict__ xM,
    const float* __restrict__ xS,
    const float* __restrict__ biasAll,
    const float* __restrict__ bhhL, const float* __restrict__ bhhM,
    const float* __restrict__ bhhS)
{
    extern __shared__ __half smh[];
    __half* Ah = smh;                       // h fp16 [128][ASTH]
    __half* Xh = smh + ASM_H;               // x fp16 [128][XSTH]
    __half* Bb0 = smh + ASM_H + XSM_H;      // ring of 3 weight buffers

    const int tid = threadIdx.x;
    const int s = blockIdx.x / MB;             // 0=long,1=medium,2=short
    const int m0 = (blockIdx.x % MB) * 128;
    const int T = (s == 0) ? 60 : ((s == 1) ? 30 : 8);
    const float* xsrc = (s == 0) ? xL : ((s == 1) ? xM : xS);
    const float* bhh = (s == 0) ? bhhL : ((s == 1) ? bhhM : bhhS);
    const float* bias = biasAll + s * 768;
    const __half* wh = whhAll + (size_t)s * 768 * 256;
    const __half* wi = wihAll + (size_t)s * 768 * 64;
    float* ha = hA + (size_t)s * NN * HD;
    float* hb = hB + (size_t)s * NN * HD;

    const int lane = tid & 31, gid = lane >> 2, tig = lane & 3;
    const int warp = tid >> 5, wm = warp & 3, wn = warp >> 2;
    const int lrow = tid >> 2;                 // 0..127 loader row
    const int cbase = (tid & 3) * 4;           // col base for staging

    // issue one chunk's weight copy: 192 rows x 64 halves = 1536 16B tasks
#define ISSUE_CHUNK(cc)                                                         \
    if ((cc) < 20) {                                                            \
        const int jc2 = (cc) / 5, pc2 = (cc) % 5;                               \
        __half* dst = Bb0 + ((cc) % 3) * BSM_H;                                 \
        _Pragma("unroll")                                                       \
        for (int p = 0; p < 3; p++) {                                           \
            int task = tid + p * 512;                                           \
            int q = task >> 3, ch = (task & 7) * 8;                             \
            int wrow = (q >> 6) * 256 + jc2 * 64 + (q & 63);                    \
            const __half* src = (pc2 < 4)                                       \
                ? wh + (size_t)wrow * 256 + pc2 * 64 + ch                       \
                : wi + (size_t)wrow * 64 + ch;                                  \
            cp16(dst + q * BSTH + ch, src);                                     \
        }                                                                       \
        cp_commit();                                                            \
    }

    for (int t = 0; t < T; t++) {
        const float* hin = (t & 1) ? hb : ha;
        float* hout = (t & 1) ? ha : hb;

        // prologue copies for chunk 0,1 (buffers free: step-end sync passed)
        ISSUE_CHUNK(0);
        ISSUE_CHUNK(1);

        // ---- stage h (128x256) and x_t (128x64) into SMEM as fp16 ----
        {
            int grow = m0 + lrow;
            bool ok = grow < NN;
            const float* hr = hin + (size_t)grow * HD;
            __half* da = Ah + lrow * ASTH;
#pragma unroll
            for (int q = 0; q < 16; q++) {
                int col = cbase + q * 16;
                float4 v = ok ? *(const float4*)(hr + col)
                              : make_float4(0.f, 0.f, 0.f, 0.f);
                *(__half2*)(da + col)     = __floats2half2_rn(v.x, v.y);
                *(__half2*)(da + col + 2) = __floats2half2_rn(v.z, v.w);
            }
            const float* xr = xsrc + ((size_t)grow * T + t) * 64;
            __half* dx = Xh + lrow * XSTH;
#pragma unroll
            for (int q = 0; q < 4; q++) {
                int col = cbase + q * 16;
                float4 v = ok ? *(const float4*)(xr + col)
                              : make_float4(0.f, 0.f, 0.f, 0.f);
                *(__half2*)(dx + col)     = __floats2half2_rn(v.x, v.y);
                *(__half2*)(dx + col + 2) = __floats2half2_rn(v.z, v.w);
            }
        }

#pragma unroll
        for (int jc = 0; jc < 4; jc++) {
            float acc[2][8][4];
#pragma unroll
            for (int i = 0; i < 2; i++)
#pragma unroll
                for (int j = 0; j < 8; j++)
#pragma unroll
                    for (int r = 0; r < 4; r++) acc[i][j][r] = 0.f;

#pragma unroll
            for (int pc = 0; pc < 5; pc++) {
                const int c = jc * 5 + pc;
                // chunk c copy complete (2-deep lookahead)
                if (c < 19) cp_wait1(); else cp_wait0();
                __syncthreads();           // data visible; ring buffer c+2 free
                ISSUE_CHUNK(c + 2);

                const __half* Bs = Bb0 + (c % 3) * BSM_H;
                const __half* Ab = (pc < 4) ? (Ah + pc * 64) : Xh;
                const int astr = (pc < 4) ? ASTH : XSTH;
#pragma unroll
                for (int ks = 0; ks < 4; ks++) {
                    const int k0 = ks * 16;
                    unsigned af[2][4];
#pragma unroll
                    for (int i = 0; i < 2; i++) {
                        int ab = (wm * 32 + i * 16 + gid) * astr + k0 + 2 * tig;
                        af[i][0] = *(const unsigned*)(Ab + ab);
                        af[i][1] = *(const unsigned*)(Ab + ab + 8 * astr);
                        af[i][2] = *(const unsigned*)(Ab + ab + 8);
                        af[i][3] = *(const unsigned*)(Ab + ab + 8 * astr + 8);
                    }
#pragma unroll
                    for (int gc = 0; gc < 3; gc++) {
                        const int ci = (pc == 4 && gc == 2) ? 3 : gc;
#pragma unroll
                        for (int u = 0; u < 2; u++) {
                            int qb = (gc * 64 + wn * 16 + u * 8 + gid) * BSTH
                                     + ks * 16 + 2 * tig;
                            unsigned bf[2];
                            bf[0] = *(const unsigned*)(Bs + qb);
                            bf[1] = *(const unsigned*)(Bs + qb + 8);
#pragma unroll
                            for (int i = 0; i < 2; i++)
                                mma_f16(acc[i][ci * 2 + u], af[i], bf);
                        }
                    }
                }
            }

            // ---- epilogue: GRU update for these 64 j ----
            const int j0 = jc * 64;
#pragma unroll
            for (int i = 0; i < 2; i++)
#pragma unroll
                for (int u = 0; u < 2; u++)
#pragma unroll
                    for (int h2 = 0; h2 < 2; h2++)
#pragma unroll
                        for (int pp = 0; pp < 2; pp++) {
                            int row = m0 + wm * 32 + i * 16 + gid + h2 * 8;
                            if (row >= NN) continue;
                            int jg = j0 + wn * 16 + u * 8 + 2 * tig + pp;
                            int reg = h2 * 2 + pp;
                            float ar  = acc[i][0 + u][reg];
                            float az  = acc[i][2 + u][reg];
                            float anh = acc[i][4 + u][reg];
                            float anx = acc[i][6 + u][reg];
                            float r = sigf(ar + bias[jg]);
                            float z = sigf(az + bias[256 + jg]);
                            float n = tanhf(anx + bias[512 + jg] +
                                            r * (anh + bhh[512 + jg]));
                            float hp = hin[(size_t)row * HD + jg];
                            hout[(size_t)row * HD + jg] = (1.f - z) * n + z * hp;
                        }
        }
        __threadfence_block();
        __syncthreads();   // hout visible; Ah/Xh and ring bufs free for next t
    }
#undef ISSUE_CHUNK
}

// ---------------- fp32 f32x2 GEMM (GNN section) ----------------
__device__ __forceinline__ unsigned long long pack2(float x, float y) {
    unsigned long long r;
    asm("mov.b64 %0, {%1, %2};" : "=l"(r) : "f"(x), "f"(y));
    return r;
}
__device__ __forceinline__ void unpack2(unsigned long long v, float& x, float& y) {
    asm("mov.b64 {%0, %1}, %2;" : "=f"(x), "=f"(y) : "l"(v));
}
__device__ __forceinline__ void ffma2(unsigned long long& d, unsigned long long a,
                                      unsigned long long b) {
    asm("fma.rn.f32x2 %0, %1, %2, %0;" : "+l"(d) : "l"(a), "l"(b));
}

__global__ void __launch_bounds__(256) gemm_tn(
    const float* __restrict__ A, int lda,
    const float* __restrict__ B, int ldb,
    const float* __restrict__ bias,
    float* __restrict__ C, int ldc,
    int M, int K, int relu)
{
    __shared__ float As[16][128];
    __shared__ float Bs[16][64];
    const int tid = threadIdx.x;
    const int m0 = blockIdx.x * 128;
    const int n0 = blockIdx.y * 64;
    const int tx = tid & 15;
    const int ty = tid >> 4;

    unsigned long long acc[8][2];
#pragma unroll
    for (int i = 0; i < 8; i++) { acc[i][0] = 0ull; acc[i][1] = 0ull; }

    const int ar0 = tid >> 2;
    const int ar1 = (tid + 256) >> 2;
    const int aq = tid & 3;
    const int br = tid >> 2;
    const int bq = tid & 3;

    for (int k0 = 0; k0 < K; k0 += 16) {
        float4 va0 = make_float4(0.f, 0.f, 0.f, 0.f);
        float4 va1 = va0;
        if (m0 + ar0 < M) va0 = *(const float4*)(A + (size_t)(m0 + ar0) * lda + k0 + aq * 4);
        if (m0 + ar1 < M) va1 = *(const float4*)(A + (size_t)(m0 + ar1) * lda + k0 + aq * 4);
        float4 vb = *(const float4*)(B + (size_t)(n0 + br) * ldb + k0 + bq * 4);

        As[aq * 4 + 0][ar0] = va0.x; As[aq * 4 + 1][ar0] = va0.y;
        As[aq * 4 + 2][ar0] = va0.z; As[aq * 4 + 3][ar0] = va0.w;
        As[aq * 4 + 0][ar1] = va1.x; As[aq * 4 + 1][ar1] = va1.y;
        As[aq * 4 + 2][ar1] = va1.z; As[aq * 4 + 3][ar1] = va1.w;
        Bs[bq * 4 + 0][br] = vb.x; Bs[bq * 4 + 1][br] = vb.y;
        Bs[bq * 4 + 2][br] = vb.z; Bs[bq * 4 + 3][br] = vb.w;
        __syncthreads();

#pragma unroll
        for (int kk = 0; kk < 16; kk++) {
            float4 a0 = *(const float4*)&As[kk][ty * 8];
            float4 a1 = *(const float4*)&As[kk][ty * 8 + 4];
            unsigned long long b0 = *(const unsigned long long*)&Bs[kk][tx * 4];
            unsigned long long b1 = *(const unsigned long long*)&Bs[kk][tx * 4 + 2];
            float av[8] = {a0.x, a0.y, a0.z, a0.w, a1.x, a1.y, a1.z, a1.w};
#pragma unroll
            for (int i = 0; i < 8; i++) {
                unsigned long long a2 = pack2(av[i], av[i]);
                ffma2(acc[i][0], a2, b0);
                ffma2(acc[i][1], a2, b1);
            }
        }
        __syncthreads();
    }

    float b4[4] = {0.f, 0.f, 0.f, 0.f};
    if (bias) {
        float4 bv = *(const float4*)(bias + n0 + tx * 4);
        b4[0] = bv.x; b4[1] = bv.y; b4[2] = bv.z; b4[3] = bv.w;
    }
#pragma unroll
    for (int i = 0; i < 8; i++) {
        int m = m0 + ty * 8 + i;
        if (m < M) {
            float c0, c1, c2, c3;
            unpack2(acc[i][0], c0, c1);
            unpack2(acc[i][1], c2, c3);
            c0 += b4[0]; c1 += b4[1]; c2 += b4[2]; c3 += b4[3];
            if (relu) {
                c0 = fmaxf(c0, 0.f); c1 = fmaxf(c1, 0.f);
                c2 = fmaxf(c2, 0.f); c3 = fmaxf(c3, 0.f);
            }
            *(float4*)(C + (size_t)m * ldc + n0 + tx * 4) = make_float4(c0, c1, c2, c3);
        }
    }
}

__global__ void k_concat(const float* __restrict__ hs, const float* __restrict__ hm,
                         const float* __restrict__ hl) {
    int i = blockIdx.x * 256 + threadIdx.x;
    if (i >= NN * H3) return;
    int n = i / H3, j = i % H3;
    float v;
    if (j < 256)      v = hs[n * HD + j];
    else if (j < 512) v = hm[n * HD + j - 256];
    else              v = hl[n * HD + j - 512];
    d_COMB[i] = v;
}

// ---------------- SAGE attention (decomposed scores) ----------------
__device__ __forceinline__ unsigned fenc(float f) {
    unsigned u = __float_as_uint(f);
    return (u & 0x80000000u) ? ~u : (u | 0x80000000u);
}
__device__ __forceinline__ float fdec(unsigned u) {
    u = (u & 0x80000000u) ? (u & 0x7fffffffu) : ~u;
    return __uint_as_float(u);
}

__global__ void k_pq(const float* __restrict__ aw) {
    int n = blockIdx.x * 8 + (threadIdx.x >> 5);
    int lane = threadIdx.x & 31;
    if (n >= NN) return;
    float p = 0.f, q = 0.f;
#pragma unroll
    for (int j = lane; j < 256; j += 32) {
        float v = d_XL[n * GD + j];
        p += v * aw[j];
        q += v * aw[256 + j];
    }
#pragma unroll
    for (int o = 16; o; o >>= 1) {
        p += __shfl_xor_sync(0xffffffffu, p, o);
        q += __shfl_xor_sync(0xffffffffu, q, o);
    }
    if (lane == 0) { d_P[n] = p; d_Q[n] = q; }
}

__global__ void k_init() {
    int n = blockIdx.x * 256 + threadIdx.x;
    if (n < NN) { d_MENC[n] = 0x007fffffu; d_SSUM[n] = 0.f; }
}

__global__ void k_edge1(const int* __restrict__ ei, const float* __restrict__ ea,
                        const float* __restrict__ aw, const float* __restrict__ ab) {
    int e = blockIdx.x * 256 + threadIdx.x;
    if (e >= NE) return;
    int row = ei[e], col = ei[NE + e];
    float sc = d_P[row] + d_Q[col] + aw[512] * ea[e] + ab[0];
    d_SC[e] = sc;
    atomicMax(&d_MENC[row], fenc(sc));
}

__global__ void k_edge2(const int* __restrict__ ei) {
    int e = blockIdx.x * 256 + threadIdx.x;
    if (e >= NE) return;
    int row = ei[e];
    float m = fdec(d_MENC[row]);
    float ex = expf(d_SC[e] - m);
    d_SC[e] = ex;
    atomicAdd(&d_SSUM[row], ex);
}

__global__ void k_edge3(const int* __restrict__ ei) {
    int e = blockIdx.x * 4 + (threadIdx.x >> 6);
    int l = threadIdx.x & 63;
    if (e >= NE) return;
    int row = ei[e], col = ei[NE + e];
    float alpha = d_SC[e] / (d_SSUM[row] + 1e-16f);
    float4 v = *(const float4*)&d_XL[row * GD + l * 4];
    float* dst = &d_AGG[col * GD + l * 4];
    atomicAdd(dst + 0, alpha * v.x);
    atomicAdd(dst + 1, alpha * v.y);
    atomicAdd(dst + 2, alpha * v.z);
    atomicAdd(dst + 3, alpha * v.w);
}

__global__ void k_finish(const float* __restrict__ addsrc, float* __restrict__ dst) {
    int i = blockIdx.x * 256 + threadIdx.x;
    if (i >= NN * GD) return;
    float v = d_AGG[i];
    v = v > 0.f ? v : 0.f;
    if (addsrc) v += addsrc[i];
    dst[i] = v;
}

__global__ void k_heads(const float* __restrict__ impW, const float* __restrict__ impb,
                        const float* __restrict__ uncW, const float* __restrict__ uncb,
                        float* __restrict__ out) {
    int n = blockIdx.x * 8 + (threadIdx.x >> 5);
    int lane = threadIdx.x & 31;
    if (n >= NN) return;
    float a = 0.f, b = 0.f;
#pragma unroll
    for (int j = lane; j < GD; j += 32) {
        float v = d_G2[n * GD + j];
        a += v * impW[j];
        b += v * uncW[j];
    }
#pragma unroll
    for (int o = 16; o; o >>= 1) {
        a += __shfl_xor_sync(0xffffffffu, a, o);
        b += __shfl_xor_sync(0xffffffffu, b, o);
    }
    if (lane == 0) {
        out[n] = tanhf(a + impb[0]);
        out[NN + n] = 1.f / (1.f + expf(-(b + uncb[0])));
    }
}

// ---------------- host orchestration ----------------
extern "C" void kernel_launch(void* const* d_in, const int* in_sizes, int n_in,
                              void* d_out, int out_size)
{
    const float* x_s = (const float*)d_in[0];
    const float* x_m = (const float*)d_in[1];
    const float* x_l = (const float*)d_in[2];
    const int*   ei  = (const int*)d_in[3];
    const float* ea  = (const float*)d_in[4];
    // scale order here: 0=long, 1=medium, 2=short
    const float* Wih[3] = {(const float*)d_in[13], (const float*)d_in[9], (const float*)d_in[5]};
    const float* Whh[3] = {(const float*)d_in[14], (const float*)d_in[10], (const float*)d_in[6]};
    const float* bih[3] = {(const float*)d_in[15], (const float*)d_in[11], (const float*)d_in[7]};
    const float* bhh[3] = {(const float*)d_in[16], (const float*)d_in[12], (const float*)d_in[8]};
    const float* fW   = (const float*)d_in[17];
    const float* fb   = (const float*)d_in[18];
    const float* g1W  = (const float*)d_in[19];
    const float* g1aw = (const float*)d_in[20];
    const float* g1ab = (const float*)d_in[21];
    const float* g2W  = (const float*)d_in[22];
    const float* g2aw = (const float*)d_in[23];
    const float* g2ab = (const float*)d_in[24];
    const float* impW = (const float*)d_in[25];
    const float* impb = (const float*)d_in[26];
    const float* uncW = (const float*)d_in[27];
    const float* uncb = (const float*)d_in[28];

    void *pWHH, *pWIH, *pBIAS, *pHA, *pHB;
    void *pCOMB, *pTEMB, *pXL, *pAGG, *pG1, *pG2;
    cudaGetSymbolAddress(&pWHH, d_WHH);
    cudaGetSymbolAddress(&pWIH, d_WIH);
    cudaGetSymbolAddress(&pBIAS, d_BIAS);
    cudaGetSymbolAddress(&pHA, d_HA);
    cudaGetSymbolAddress(&pHB, d_HB);
    cudaGetSymbolAddress(&pCOMB, d_COMB);
    cudaGetSymbolAddress(&pTEMB, d_TEMB);
    cudaGetSymbolAddress(&pXL, d_XL);
    cudaGetSymbolAddress(&pAGG, d_AGG);
    cudaGetSymbolAddress(&pG1, d_G1);
    cudaGetSymbolAddress(&pG2, d_G2);
    __half* WHHp = (__half*)pWHH;
    __half* WIHp = (__half*)pWIH;
    float* BIASp = (float*)pBIAS;
    float* HA = (float*)pHA; float* HB = (float*)pHB;
    float* COMB = (float*)pCOMB; float* TEMB = (float*)pTEMB;
    float* XL = (float*)pXL; float* AGG = (float*)pAGG;
    float* G1 = (float*)pG1; float* G2 = (float*)pG2;

    cudaFuncSetAttribute(gru_persist,
                         cudaFuncAttributeMaxDynamicSharedMemorySize, PERSIST_SMEM);

    // ---- preconvert weights + fold biases ----
    for (int s = 0; s < 3; s++)
        k_prep<<<768, 256>>>(Whh[s], Wih[s], bih[s], bhh[s], s);

    // ---- persistent recurrence: ONE launch for all 3 GRUs, all timesteps --
    cudaMemsetAsync(HA, 0, (size_t)3 * NN * HD * sizeof(float));
    gru_persist<<<3 * MB, 512, PERSIST_SMEM>>>(
        HA, HB, WHHp, WIHp, x_l, x_m, x_s, BIASp, bhh[0], bhh[1], bhh[2]);

    // finals all land in HA (T even for every scale): 0=l, 1=m, 2=s
    float* HL = HA;
    float* HM = HA + (size_t)NN * HD;
    float* HS = HA + (size_t)2 * NN * HD;

    // ---- fusion ----
    dim3 gS((NN + 127) / 128, GD / 64);
    k_concat<<<(NN * H3 + 255) / 256, 256>>>(HS, HM, HL);
    gemm_tn<<<gS, 256>>>(COMB, H3, fW, H3, fb, TEMB, GD, NN, H3, 1);

    // ---- SAGE layer 1 ----
    gemm_tn<<<gS, 256>>>(TEMB, GD, g1W, GD, nullptr, XL, GD, NN, GD, 0);
    k_pq<<<(NN + 7) / 8, 256>>>(g1aw);
    k_init<<<(NN + 255) / 256, 256>>>();
    cudaMemsetAsync(AGG, 0, (size_t)NN * GD * sizeof(float));
    k_edge1<<<(NE + 255) / 256, 256>>>(ei, ea, g1aw, g1ab);
    k_edge2<<<(NE + 255) / 256, 256>>>(ei);
    k_edge3<<<NE / 4, 256>>>(ei);
    k_finish<<<(NN * GD + 255) / 256, 256>>>(nullptr, G1);

    // ---- SAGE layer 2 ----
    gemm_tn<<<gS, 256>>>(G1, GD, g2W, GD, nullptr, XL, GD, NN, GD, 0);
    k_pq<<<(NN + 7) / 8, 256>>>(g2aw);
    k_init<<<(NN + 255) / 256, 256>>>();
    cudaMemsetAsync(AGG, 0, (size_t)NN * GD * sizeof(float));
    k_edge1<<<(NE + 255) / 256, 256>>>(ei, ea, g2aw, g2ab);
    k_edge2<<<(NE + 255) / 256, 256>>>(ei);
    k_edge3<<<NE / 4, 256>>>(ei);
    k_finish<<<(NN * GD + 255) / 256, 256>>>(TEMB, G2);

    // ---- heads ----
    k_heads<<<(NN + 7) / 8, 256>>>(impW, impb, uncW, uncb, (float*)d_out);
}

// round 7
// speedup vs baseline: 2.4926x; 1.0518x over previous
#include <cuda_runtime.h>
#include <cuda_fp16.h>

#define NN 10000
#define NE 320000
#define FD 64
#define HD 256
#define GD 256
#define H3 768
#define MB 79                 // blocks per scale (ceil 10000/128)

#define ASTH 264              // h tile smem stride (halves)
#define XSTH 72               // x tile smem stride (halves)
#define ASM_H (128 * ASTH)
#define XSM_H (128 * XSTH)
#define CHUNK_WORDS 6144      // 192 rows x 64 halves = 24576 B
#define CHUNK_BYTES 24576
#define RING_BYTES (3 * CHUNK_BYTES)
// smem: [ring 73728][Ah 67584][Xh 18432][mbar 24]
#define SM_AH_OFF RING_BYTES
#define SM_XH_OFF (SM_AH_OFF + ASM_H * 2)
#define SM_MB_OFF (SM_XH_OFF + XSM_H * 2)
#define PERSIST_SMEM (SM_MB_OFF + 32)

// ---------------- static scratch ----------------
__device__ unsigned d_WPK[3 * 20 * CHUNK_WORDS];  // repacked fp16 weights
__device__ float d_BIAS[3 * 768];          // bih + (col<512 ? bhh : 0)
__device__ float d_HA[3 * NN * HD];
__device__ float d_HB[3 * NN * HD];
__device__ float d_COMB[NN * H3];
__device__ float d_TEMB[NN * GD];
__device__ float d_XL[NN * GD];
__device__ float d_AGG[NN * GD];
__device__ float d_G1[NN * GD];
__device__ float d_G2[NN * GD];
__device__ float d_P[NN];
__device__ float d_Q[NN];
__device__ float d_SSUM[NN];
__device__ unsigned d_MENC[NN];
__device__ float d_SC[NE];

// ---------------- helpers ----------------
__device__ __forceinline__ float sigf(float x) { return 1.f / (1.f + expf(-x)); }

__device__ __forceinline__ unsigned smem_u32(const void* p) {
    return (unsigned)__cvta_generic_to_shared(p);
}

__device__ __forceinline__ void mma_f16(float* c, const unsigned* a, const unsigned* b) {
    asm volatile(
        "mma.sync.aligned.m16n8k16.row.col.f32.f16.f16.f32 "
        "{%0,%1,%2,%3},{%4,%5,%6,%7},{%8,%9},{%0,%1,%2,%3};"
        : "+f"(c[0]), "+f"(c[1]), "+f"(c[2]), "+f"(c[3])
        : "r"(a[0]), "r"(a[1]), "r"(a[2]), "r"(a[3]), "r"(b[0]), "r"(b[1]));
}

__device__ __forceinline__ void ldsm_x4(unsigned* r, unsigned addr) {
    asm volatile("ldmatrix.sync.aligned.m8n8.x4.shared.b16 {%0,%1,%2,%3}, [%4];"
                 : "=r"(r[0]), "=r"(r[1]), "=r"(r[2]), "=r"(r[3]) : "r"(addr));
}

#define MBAR_WAIT(addr, par) do {                                               \
    asm volatile(                                                               \
        "{\n\t.reg .pred P1;\n\t"                                               \
        "WAIT_%=:\n\t"                                                          \
        "mbarrier.try_wait.parity.acquire.cta.shared::cta.b64 P1, [%0], %1, 0x989680;\n\t" \
        "@P1 bra.uni DONE_%=;\n\t"                                              \
        "bra.uni WAIT_%=;\n\t"                                                  \
        "DONE_%=:\n\t}"                                                         \
        :: "r"(addr), "r"(par) : "memory");                                     \
} while (0)

// ---------------- bias fold ----------------
__global__ void k_prep_bias(const float* __restrict__ bih,
                            const float* __restrict__ bhh, int s) {
    int i = threadIdx.x;   // 768 threads
    d_BIAS[s * 768 + i] = bih[i] + (i < 512 ? bhh[i] : 0.f);
}

// ---------------- weight repack into fragment-ordered chunks ----------------
// chunk c = jc*5 + pc; pc<4 -> Whh k-slice pc*64, pc==4 -> Wih (K=64).
// word q = ((((wn*3+gc)*2+u)*4+ks)*32 + lane)*2 + w
// source row = gc*256 + jc*64 + wn*16 + u*8 + (lane>>2)
// source k   = ks*16 + 2*(lane&3) + w*8   (halves k, k+1)
__global__ void k_pack(const float* __restrict__ whL, const float* __restrict__ wiL,
                       const float* __restrict__ whM, const float* __restrict__ wiM,
                       const float* __restrict__ whS, const float* __restrict__ wiS) {
    int W = blockIdx.x * 256 + threadIdx.x;
    if (W >= 3 * 20 * CHUNK_WORDS) return;
    int s = W / (20 * CHUNK_WORDS);
    int r = W % (20 * CHUNK_WORDS);
    int c = r / CHUNK_WORDS;
    int q = r % CHUNK_WORDS;
    int w = q & 1, lane = (q >> 1) & 31, ks = (q >> 6) & 3, u = (q >> 8) & 1;
    int gc = (q >> 9) % 3, wn = (q >> 9) / 3;
    int jc = c / 5, pc = c % 5;
    int gid = lane >> 2, tig = lane & 3;
    int grow = gc * 256 + jc * 64 + wn * 16 + u * 8 + gid;
    int k0 = ks * 16 + 2 * tig + w * 8;
    const float* wh = (s == 0) ? whL : ((s == 1) ? whM : whS);
    const float* wi = (s == 0) ? wiL : ((s == 1) ? wiM : wiS);
    const float* src = (pc < 4) ? (wh + (size_t)grow * 256 + pc * 64 + k0)
                                : (wi + (size_t)grow * 64 + k0);
    __half2 h2 = __floats2half2_rn(src[0], src[1]);
    d_WPK[W] = *(unsigned*)&h2;
}

// ================== persistent GRU: fp16 mma + bulk-DMA weight stream ======
__global__ void __launch_bounds__(512) gru_persist(
    float* __restrict__ hA, float* __restrict__ hB,
    const unsigned* __restrict__ wpk,
    const float* __restrict__ xL, const float* __restrict__ xM,
    const float* __restrict__ xS,
    const float* __restrict__ biasAll,
    const float* __restrict__ bhhL, const float* __restrict__ bhhM,
    const float* __restrict__ bhhS)
{
    extern __shared__ char smraw[];
    unsigned* Ring = (unsigned*)smraw;
    __half* Ah = (__half*)(smraw + SM_AH_OFF);
    __half* Xh = (__half*)(smraw + SM_XH_OFF);
    const unsigned ringaddr = smem_u32(smraw);
    const unsigned mbaddr = smem_u32(smraw + SM_MB_OFF);
    const unsigned ah_base = smem_u32(Ah);
    const unsigned xh_base = smem_u32(Xh);

    const int tid = threadIdx.x;
    const int s = blockIdx.x / MB;             // 0=long,1=medium,2=short
    const int m0 = (blockIdx.x % MB) * 128;
    const int T = (s == 0) ? 60 : ((s == 1) ? 30 : 8);
    const float* xsrc = (s == 0) ? xL : ((s == 1) ? xM : xS);
    const float* bhh = (s == 0) ? bhhL : ((s == 1) ? bhhM : bhhS);
    const float* bias = biasAll + s * 768;
    float* ha = hA + (size_t)s * NN * HD;
    float* hb = hB + (size_t)s * NN * HD;

    const int lane = tid & 31, gid = lane >> 2, tig = lane & 3;
    const int warp = tid >> 5, wm = warp & 3, wn = warp >> 2;
    const int lrow = tid >> 2;                 // 0..127 loader row
    const int cbase = (tid & 3) * 4;           // col base for staging
    const int i4 = lane >> 3, r8 = lane & 7;   // ldmatrix address split

    // init mbarriers (arrive count 1: the expect_tx arrive)
    if (tid < 3) {
        asm volatile("mbarrier.init.shared.b64 [%0], %1;"
                     :: "r"(mbaddr + tid * 8), "r"(1u) : "memory");
    }
    __syncthreads();

#define ISSUE_CHUNK(cc) do {                                                    \
        int sl_ = (cc) % 3;                                                     \
        unsigned mb_ = mbaddr + sl_ * 8;                                        \
        asm volatile("mbarrier.arrive.expect_tx.shared.b64 _, [%0], %1;"        \
                     :: "r"(mb_), "r"((unsigned)CHUNK_BYTES) : "memory");       \
        unsigned dst_ = ringaddr + sl_ * CHUNK_BYTES;                           \
        const void* src_ = (const char*)wpk +                                   \
                           ((size_t)(s * 20 + (cc))) * CHUNK_BYTES;             \
        asm volatile(                                                           \
            "cp.async.bulk.shared::cluster.global.mbarrier::complete_tx::bytes " \
            "[%0], [%1], %2, [%3];"                                             \
            :: "r"(dst_), "l"(src_), "r"((unsigned)CHUNK_BYTES), "r"(mb_)       \
            : "memory");                                                        \
    } while (0)

    for (int t = 0; t < T; t++) {
        const float* hin = (t & 1) ? hb : ha;
        float* hout = (t & 1) ? ha : hb;

        // prologue copies (slots free: end-of-step sync passed)
        if (tid == 0) { ISSUE_CHUNK(0); ISSUE_CHUNK(1); ISSUE_CHUNK(2); }

        // ---- stage h (128x256) and x_t (128x64) into SMEM as fp16 ----
        {
            int grow = m0 + lrow;
            bool ok = grow < NN;
            const float* hr = hin + (size_t)grow * HD;
            __half* da = Ah + lrow * ASTH;
#pragma unroll
            for (int q = 0; q < 16; q++) {
                int col = cbase + q * 16;
                float4 v = ok ? *(const float4*)(hr + col)
                              : make_float4(0.f, 0.f, 0.f, 0.f);
                *(__half2*)(da + col)     = __floats2half2_rn(v.x, v.y);
                *(__half2*)(da + col + 2) = __floats2half2_rn(v.z, v.w);
            }
            const float* xr = xsrc + ((size_t)grow * T + t) * 64;
            __half* dx = Xh + lrow * XSTH;
#pragma unroll
            for (int q = 0; q < 4; q++) {
                int col = cbase + q * 16;
                float4 v = ok ? *(const float4*)(xr + col)
                              : make_float4(0.f, 0.f, 0.f, 0.f);
                *(__half2*)(dx + col)     = __floats2half2_rn(v.x, v.y);
                *(__half2*)(dx + col + 2) = __floats2half2_rn(v.z, v.w);
            }
        }
        __syncthreads();   // staged tiles visible to all warps

#pragma unroll
        for (int jc = 0; jc < 4; jc++) {
            float acc[2][8][4];
#pragma unroll
            for (int i = 0; i < 2; i++)
#pragma unroll
                for (int j = 0; j < 8; j++)
#pragma unroll
                    for (int r = 0; r < 4; r++) acc[i][j][r] = 0.f;

#pragma unroll
            for (int pc = 0; pc < 5; pc++) {
                const int c = jc * 5 + pc;
                const int slot = c % 3;
                const int nuse = (slot == 2) ? 6 : 7;
                unsigned par = (unsigned)((t * nuse + c / 3) & 1);
                MBAR_WAIT(mbaddr + slot * 8, par);

                const unsigned* Bs = Ring + slot * CHUNK_WORDS;
                // A fragment source for this chunk
                const unsigned abase = (pc < 4) ? ah_base : xh_base;
                const int astr = (pc < 4) ? ASTH : XSTH;
                const int kofs = (pc < 4) ? pc * 64 : 0;

#pragma unroll
                for (int ks = 0; ks < 4; ks++) {
                    unsigned af[2][4];
#pragma unroll
                    for (int i = 0; i < 2; i++) {
                        int arow = wm * 32 + i * 16 + (i4 & 1) * 8 + r8;
                        int acol = kofs + ks * 16 + (i4 >> 1) * 8;
                        ldsm_x4(af[i], abase + (arow * astr + acol) * 2);
                    }
#pragma unroll
                    for (int gc = 0; gc < 3; gc++) {
                        const int ci = (pc == 4 && gc == 2) ? 3 : gc;
#pragma unroll
                        for (int u = 0; u < 2; u++) {
                            int fb = ((((wn * 3 + gc) * 2 + u) * 4 + ks) * 32
                                      + lane) * 2;
                            uint2 bf = *(const uint2*)(Bs + fb);
#pragma unroll
                            for (int i = 0; i < 2; i++)
                                mma_f16(acc[i][ci * 2 + u], af[i], &bf.x);
                        }
                    }
                }
                __syncthreads();           // all consumers done with slot
                if (tid == 0 && c + 3 < 20) ISSUE_CHUNK(c + 3);
            }

            // ---- epilogue: GRU update for these 64 j ----
            const int j0 = jc * 64;
#pragma unroll
            for (int i = 0; i < 2; i++)
#pragma unroll
                for (int u = 0; u < 2; u++)
#pragma unroll
                    for (int h2 = 0; h2 < 2; h2++)
#pragma unroll
                        for (int pp = 0; pp < 2; pp++) {
                            int row = m0 + wm * 32 + i * 16 + gid + h2 * 8;
                            if (row >= NN) continue;
                            int jg = j0 + wn * 16 + u * 8 + 2 * tig + pp;
                            int reg = h2 * 2 + pp;
                            float ar  = acc[i][0 + u][reg];
                            float az  = acc[i][2 + u][reg];
                            float anh = acc[i][4 + u][reg];
                            float anx = acc[i][6 + u][reg];
                            float r = sigf(ar + bias[jg]);
                            float z = sigf(az + bias[256 + jg]);
                            float n = tanhf(anx + bias[512 + jg] +
                                            r * (anh + bhh[512 + jg]));
                            float hp = hin[(size_t)row * HD + jg];
                            hout[(size_t)row * HD + jg] = (1.f - z) * n + z * hp;
                        }
        }
        __threadfence_block();
        __syncthreads();   // hout visible; Ah/Xh free for next t
    }
#undef ISSUE_CHUNK
}

// ---------------- fp32 f32x2 GEMM (GNN section) ----------------
__device__ __forceinline__ unsigned long long pack2(float x, float y) {
    unsigned long long r;
    asm("mov.b64 %0, {%1, %2};" : "=l"(r) : "f"(x), "f"(y));
    return r;
}
__device__ __forceinline__ void unpack2(unsigned long long v, float& x, float& y) {
    asm("mov.b64 {%0, %1}, %2;" : "=f"(x), "=f"(y) : "l"(v));
}
__device__ __forceinline__ void ffma2(unsigned long long& d, unsigned long long a,
                                      unsigned long long b) {
    asm("fma.rn.f32x2 %0, %1, %2, %0;" : "+l"(d) : "l"(a), "l"(b));
}

__global__ void __launch_bounds__(256) gemm_tn(
    const float* __restrict__ A, int lda,
    const float* __restrict__ B, int ldb,
    const float* __restrict__ bias,
    float* __restrict__ C, int ldc,
    int M, int K, int relu)
{
    __shared__ float As[16][128];
    __shared__ float Bs[16][64];
    const int tid = threadIdx.x;
    const int m0 = blockIdx.x * 128;
    const int n0 = blockIdx.y * 64;
    const int tx = tid & 15;
    const int ty = tid >> 4;

    unsigned long long acc[8][2];
#pragma unroll
    for (int i = 0; i < 8; i++) { acc[i][0] = 0ull; acc[i][1] = 0ull; }

    const int ar0 = tid >> 2;
    const int ar1 = (tid + 256) >> 2;
    const int aq = tid & 3;
    const int br = tid >> 2;
    const int bq = tid & 3;

    for (int k0 = 0; k0 < K; k0 += 16) {
        float4 va0 = make_float4(0.f, 0.f, 0.f, 0.f);
        float4 va1 = va0;
        if (m0 + ar0 < M) va0 = *(const float4*)(A + (size_t)(m0 + ar0) * lda + k0 + aq * 4);
        if (m0 + ar1 < M) va1 = *(const float4*)(A + (size_t)(m0 + ar1) * lda + k0 + aq * 4);
        float4 vb = *(const float4*)(B + (size_t)(n0 + br) * ldb + k0 + bq * 4);

        As[aq * 4 + 0][ar0] = va0.x; As[aq * 4 + 1][ar0] = va0.y;
        As[aq * 4 + 2][ar0] = va0.z; As[aq * 4 + 3][ar0] = va0.w;
        As[aq * 4 + 0][ar1] = va1.x; As[aq * 4 + 1][ar1] = va1.y;
        As[aq * 4 + 2][ar1] = va1.z; As[aq * 4 + 3][ar1] = va1.w;
        Bs[bq * 4 + 0][br] = vb.x; Bs[bq * 4 + 1][br] = vb.y;
        Bs[bq * 4 + 2][br] = vb.z; Bs[bq * 4 + 3][br] = vb.w;
        __syncthreads();

#pragma unroll
        for (int kk = 0; kk < 16; kk++) {
            float4 a0 = *(const float4*)&As[kk][ty * 8];
            float4 a1 = *(const float4*)&As[kk][ty * 8 + 4];
            unsigned long long b0 = *(const unsigned long long*)&Bs[kk][tx * 4];
            unsigned long long b1 = *(const unsigned long long*)&Bs[kk][tx * 4 + 2];
            float av[8] = {a0.x, a0.y, a0.z, a0.w, a1.x, a1.y, a1.z, a1.w};
#pragma unroll
            for (int i = 0; i < 8; i++) {
                unsigned long long a2 = pack2(av[i], av[i]);
                ffma2(acc[i][0], a2, b0);
                ffma2(acc[i][1], a2, b1);
            }
        }
        __syncthreads();
    }

    float b4[4] = {0.f, 0.f, 0.f, 0.f};
    if (bias) {
        float4 bv = *(const float4*)(bias + n0 + tx * 4);
        b4[0] = bv.x; b4[1] = bv.y; b4[2] = bv.z; b4[3] = bv.w;
    }
#pragma unroll
    for (int i = 0; i < 8; i++) {
        int m = m0 + ty * 8 + i;
        if (m < M) {
            float c0, c1, c2, c3;
            unpack2(acc[i][0], c0, c1);
            unpack2(acc[i][1], c2, c3);
            c0 += b4[0]; c1 += b4[1]; c2 += b4[2]; c3 += b4[3];
            if (relu) {
                c0 = fmaxf(c0, 0.f); c1 = fmaxf(c1, 0.f);
                c2 = fmaxf(c2, 0.f); c3 = fmaxf(c3, 0.f);
            }
            *(float4*)(C + (size_t)m * ldc + n0 + tx * 4) = make_float4(c0, c1, c2, c3);
        }
    }
}

__global__ void k_concat(const float* __restrict__ hs, const float* __restrict__ hm,
                         const float* __restrict__ hl) {
    int i = blockIdx.x * 256 + threadIdx.x;
    if (i >= NN * H3) return;
    int n = i / H3, j = i % H3;
    float v;
    if (j < 256)      v = hs[n * HD + j];
    else if (j < 512) v = hm[n * HD + j - 256];
    else              v = hl[n * HD + j - 512];
    d_COMB[i] = v;
}

// ---------------- SAGE attention (decomposed scores) ----------------
__device__ __forceinline__ unsigned fenc(float f) {
    unsigned u = __float_as_uint(f);
    return (u & 0x80000000u) ? ~u : (u | 0x80000000u);
}
__device__ __forceinline__ float fdec(unsigned u) {
    u = (u & 0x80000000u) ? (u & 0x7fffffffu) : ~u;
    return __uint_as_float(u);
}

__global__ void k_pq(const float* __restrict__ aw) {
    int n = blockIdx.x * 8 + (threadIdx.x >> 5);
    int lane = threadIdx.x & 31;
    if (n >= NN) return;
    float p = 0.f, q = 0.f;
#pragma unroll
    for (int j = lane; j < 256; j += 32) {
        float v = d_XL[n * GD + j];
        p += v * aw[j];
        q += v * aw[256 + j];
    }
#pragma unroll
    for (int o = 16; o; o >>= 1) {
        p += __shfl_xor_sync(0xffffffffu, p, o);
        q += __shfl_xor_sync(0xffffffffu, q, o);
    }
    if (lane == 0) { d_P[n] = p; d_Q[n] = q; }
}

__global__ void k_init() {
    int n = blockIdx.x * 256 + threadIdx.x;
    if (n < NN) { d_MENC[n] = 0x007fffffu; d_SSUM[n] = 0.f; }
}

__global__ void k_edge1(const int* __restrict__ ei, const float* __restrict__ ea,
                        const float* __restrict__ aw, const float* __restrict__ ab) {
    int e = blockIdx.x * 256 + threadIdx.x;
    if (e >= NE) return;
    int row = ei[e], col = ei[NE + e];
    float sc = d_P[row] + d_Q[col] + aw[512] * ea[e] + ab[0];
    d_SC[e] = sc;
    atomicMax(&d_MENC[row], fenc(sc));
}

__global__ void k_edge2(const int* __restrict__ ei) {
    int e = blockIdx.x * 256 + threadIdx.x;
    if (e >= NE) return;
    int row = ei[e];
    float m = fdec(d_MENC[row]);
    float ex = expf(d_SC[e] - m);
    d_SC[e] = ex;
    atomicAdd(&d_SSUM[row], ex);
}

__global__ void k_edge3(const int* __restrict__ ei) {
    int e = blockIdx.x * 4 + (threadIdx.x >> 6);
    int l = threadIdx.x & 63;
    if (e >= NE) return;
    int row = ei[e], col = ei[NE + e];
    float alpha = d_SC[e] / (d_SSUM[row] + 1e-16f);
    float4 v = *(const float4*)&d_XL[row * GD + l * 4];
    float* dst = &d_AGG[col * GD + l * 4];
    atomicAdd(dst + 0, alpha * v.x);
    atomicAdd(dst + 1, alpha * v.y);
    atomicAdd(dst + 2, alpha * v.z);
    atomicAdd(dst + 3, alpha * v.w);
}

__global__ void k_finish(const float* __restrict__ addsrc, float* __restrict__ dst) {
    int i = blockIdx.x * 256 + threadIdx.x;
    if (i >= NN * GD) return;
    float v = d_AGG[i];
    v = v > 0.f ? v : 0.f;
    if (addsrc) v += addsrc[i];
    dst[i] = v;
}

__global__ void k_heads(const float* __restrict__ impW, const float* __restrict__ impb,
                        const float* __restrict__ uncW, const float* __restrict__ uncb,
                        float* __restrict__ out) {
    int n = blockIdx.x * 8 + (threadIdx.x >> 5);
    int lane = threadIdx.x & 31;
    if (n >= NN) return;
    float a = 0.f, b = 0.f;
#pragma unroll
    for (int j = lane; j < GD; j += 32) {
        float v = d_G2[n * GD + j];
        a += v * impW[j];
        b += v * uncW[j];
    }
#pragma unroll
    for (int o = 16; o; o >>= 1) {
        a += __shfl_xor_sync(0xffffffffu, a, o);
        b += __shfl_xor_sync(0xffffffffu, b, o);
    }
    if (lane == 0) {
        out[n] = tanhf(a + impb[0]);
        out[NN + n] = 1.f / (1.f + expf(-(b + uncb[0])));
    }
}

// ---------------- host orchestration ----------------
extern "C" void kernel_launch(void* const* d_in, const int* in_sizes, int n_in,
                              void* d_out, int out_size)
{
    const float* x_s = (const float*)d_in[0];
    const float* x_m = (const float*)d_in[1];
    const float* x_l = (const float*)d_in[2];
    const int*   ei  = (const int*)d_in[3];
    const float* ea  = (const float*)d_in[4];
    // scale order here: 0=long, 1=medium, 2=short
    const float* Wih[3] = {(const float*)d_in[13], (const float*)d_in[9], (const float*)d_in[5]};
    const float* Whh[3] = {(const float*)d_in[14], (const float*)d_in[10], (const float*)d_in[6]};
    const float* bih[3] = {(const float*)d_in[15], (const float*)d_in[11], (const float*)d_in[7]};
    const float* bhh[3] = {(const float*)d_in[16], (const float*)d_in[12], (const float*)d_in[8]};
    const float* fW   = (const float*)d_in[17];
    const float* fb   = (const float*)d_in[18];
    const float* g1W  = (const float*)d_in[19];
    const float* g1aw = (const float*)d_in[20];
    const float* g1ab = (const float*)d_in[21];
    const float* g2W  = (const float*)d_in[22];
    const float* g2aw = (const float*)d_in[23];
    const float* g2ab = (const float*)d_in[24];
    const float* impW = (const float*)d_in[25];
    const float* impb = (const float*)d_in[26];
    const float* uncW = (const float*)d_in[27];
    const float* uncb = (const float*)d_in[28];

    void *pWPK, *pBIAS, *pHA, *pHB;
    void *pCOMB, *pTEMB, *pXL, *pAGG, *pG1, *pG2;
    cudaGetSymbolAddress(&pWPK, d_WPK);
    cudaGetSymbolAddress(&pBIAS, d_BIAS);
    cudaGetSymbolAddress(&pHA, d_HA);
    cudaGetSymbolAddress(&pHB, d_HB);
    cudaGetSymbolAddress(&pCOMB, d_COMB);
    cudaGetSymbolAddress(&pTEMB, d_TEMB);
    cudaGetSymbolAddress(&pXL, d_XL);
    cudaGetSymbolAddress(&pAGG, d_AGG);
    cudaGetSymbolAddress(&pG1, d_G1);
    cudaGetSymbolAddress(&pG2, d_G2);
    unsigned* WPKp = (unsigned*)pWPK;
    float* BIASp = (float*)pBIAS;
    float* HA = (float*)pHA; float* HB = (float*)pHB;
    float* COMB = (float*)pCOMB; float* TEMB = (float*)pTEMB;
    float* XL = (float*)pXL; float* AGG = (float*)pAGG;
    float* G1 = (float*)pG1; float* G2 = (float*)pG2;

    cudaFuncSetAttribute(gru_persist,
                         cudaFuncAttributeMaxDynamicSharedMemorySize, PERSIST_SMEM);

    // ---- fold biases + repack weights ----
    for (int s = 0; s < 3; s++)
        k_prep_bias<<<1, 768>>>(bih[s], bhh[s], s);
    k_pack<<<(3 * 20 * CHUNK_WORDS + 255) / 256, 256>>>(
        Whh[0], Wih[0], Whh[1], Wih[1], Whh[2], Wih[2]);

    // ---- persistent recurrence: ONE launch for all 3 GRUs, all timesteps --
    cudaMemsetAsync(HA, 0, (size_t)3 * NN * HD * sizeof(float));
    gru_persist<<<3 * MB, 512, PERSIST_SMEM>>>(
        HA, HB, WPKp, x_l, x_m, x_s, BIASp, bhh[0], bhh[1], bhh[2]);

    // finals all land in HA (T even for every scale): 0=l, 1=m, 2=s
    float* HL = HA;
    float* HM = HA + (size_t)NN * HD;
    float* HS = HA + (size_t)2 * NN * HD;

    // ---- fusion ----
    dim3 gS((NN + 127) / 128, GD / 64);
    k_concat<<<(NN * H3 + 255) / 256, 256>>>(HS, HM, HL);
    gemm_tn<<<gS, 256>>>(COMB, H3, fW, H3, fb, TEMB, GD, NN, H3, 1);

    // ---- SAGE layer 1 ----
    gemm_tn<<<gS, 256>>>(TEMB, GD, g1W, GD, nullptr, XL, GD, NN, GD, 0);
    k_pq<<<(NN + 7) / 8, 256>>>(g1aw);
    k_init<<<(NN + 255) / 256, 256>>>();
    cudaMemsetAsync(AGG, 0, (size_t)NN * GD * sizeof(float));
    k_edge1<<<(NE + 255) / 256, 256>>>(ei, ea, g1aw, g1ab);
    k_edge2<<<(NE + 255) / 256, 256>>>(ei);
    k_edge3<<<NE / 4, 256>>>(ei);
    k_finish<<<(NN * GD + 255) / 256, 256>>>(nullptr, G1);

    // ---- SAGE layer 2 ----
    gemm_tn<<<gS, 256>>>(G1, GD, g2W, GD, nullptr, XL, GD, NN, GD, 0);
    k_pq<<<(NN + 7) / 8, 256>>>(g2aw);
    k_init<<<(NN + 255) / 256, 256>>>();
    cudaMemsetAsync(AGG, 0, (size_t)NN * GD * sizeof(float));
    k_edge1<<<(NE + 255) / 256, 256>>>(ei, ea, g2aw, g2ab);
    k_edge2<<<(NE + 255) / 256, 256>>>(ei);
    k_edge3<<<NE / 4, 256>>>(ei);
    k_finish<<<(NN * GD + 255) / 256, 256>>>(TEMB, G2);

    // ---- heads ----
    k_heads<<<(NN + 7) / 8, 256>>>(impW, impb, uncW, uncb, (float*)d_out);
}

// round 9
// speedup vs baseline: 2.7298x; 1.0952x over previous
#include <cuda_runtime.h>
#include <cuda_fp16.h>

#define NN 10000
#define NE 320000
#define FD 64
#define HD 256
#define GD 256
#define H3 768
#define MB 79                 // blocks per scale (ceil 10000/128)

#define ASTH 264              // h tile smem stride (halves)
#define XSTH 72               // x tile smem stride (halves)
#define ASM_H (128 * ASTH)
#define XSM_H (128 * XSTH)
#define CHUNK_WORDS 6144      // 192 rows x 64 halves = 24576 B
#define CHUNK_BYTES 24576
#define RING_BYTES (3 * CHUNK_BYTES)
// smem: [ring 73728][Ah 67584][Xh 18432][mbar 24]
#define SM_AH_OFF RING_BYTES
#define SM_XH_OFF (SM_AH_OFF + ASM_H * 2)
#define SM_MB_OFF (SM_XH_OFF + XSM_H * 2)
#define PERSIST_SMEM (SM_MB_OFF + 32)

// ---------------- static scratch ----------------
__device__ unsigned d_WPK[3 * 20 * CHUNK_WORDS];  // repacked fp16 weights
__device__ float d_BIAS[3 * 768];          // bih + (col<512 ? bhh : 0)
__device__ float d_HA[3 * NN * HD];
__device__ float d_HB[3 * NN * HD];
__device__ float d_COMB[NN * H3];
__device__ float d_TEMB[NN * GD];
__device__ float d_XL[NN * GD];
__device__ float d_AGG[NN * GD];
__device__ float d_G1[NN * GD];
__device__ float d_G2[NN * GD];
__device__ float d_P[NN];
__device__ float d_Q[NN];
__device__ float d_SSUM[NN];
__device__ unsigned d_MENC[NN];
__device__ float d_SC[NE];

// ---------------- helpers ----------------
__device__ __forceinline__ float sigf(float x) { return 1.f / (1.f + expf(-x)); }

__device__ __forceinline__ unsigned smem_u32(const void* p) {
    return (unsigned)__cvta_generic_to_shared(p);
}

__device__ __forceinline__ void mma_f16(float* c, const unsigned* a, const unsigned* b) {
    asm volatile(
        "mma.sync.aligned.m16n8k16.row.col.f32.f16.f16.f32 "
        "{%0,%1,%2,%3},{%4,%5,%6,%7},{%8,%9},{%0,%1,%2,%3};"
        : "+f"(c[0]), "+f"(c[1]), "+f"(c[2]), "+f"(c[3])
        : "r"(a[0]), "r"(a[1]), "r"(a[2]), "r"(a[3]), "r"(b[0]), "r"(b[1]));
}

__device__ __forceinline__ void ldsm_x4(unsigned* r, unsigned addr) {
    asm volatile("ldmatrix.sync.aligned.m8n8.x4.shared.b16 {%0,%1,%2,%3}, [%4];"
                 : "=r"(r[0]), "=r"(r[1]), "=r"(r[2]), "=r"(r[3]) : "r"(addr));
}

#define MBAR_WAIT(addr, par) do {                                               \
    asm volatile(                                                               \
        "{\n\t.reg .pred P1;\n\t"                                               \
        "WAIT_%=:\n\t"                                                          \
        "mbarrier.try_wait.parity.acquire.cta.shared::cta.b64 P1, [%0], %1, 0x989680;\n\t" \
        "@P1 bra.uni DONE_%=;\n\t"                                              \
        "bra.uni WAIT_%=;\n\t"                                                  \
        "DONE_%=:\n\t}"                                                         \
        :: "r"(addr), "r"(par) : "memory");                                     \
} while (0)

// ---------------- bias fold ----------------
__global__ void k_prep_bias(const float* __restrict__ bih,
                            const float* __restrict__ bhh, int s) {
    int i = threadIdx.x;   // 768 threads
    d_BIAS[s * 768 + i] = bih[i] + (i < 512 ? bhh[i] : 0.f);
}

// ---------------- weight repack into fragment-ordered chunks ----------------
// chunk c = jc*5 + pc; pc<4 -> Whh k-slice pc*64, pc==4 -> Wih (K=64).
// word q = ((((wn*3+gc)*2+u)*4+ks)*32 + lane)*2 + w
// source row = gc*256 + jc*64 + wn*16 + u*8 + (lane>>2)
// source k   = ks*16 + 2*(lane&3) + w*8   (halves k, k+1)
__global__ void k_pack(const float* __restrict__ whL, const float* __restrict__ wiL,
                       const float* __restrict__ whM, const float* __restrict__ wiM,
                       const float* __restrict__ whS, const float* __restrict__ wiS) {
    int W = blockIdx.x * 256 + threadIdx.x;
    if (W >= 3 * 20 * CHUNK_WORDS) return;
    int s = W / (20 * CHUNK_WORDS);
    int r = W % (20 * CHUNK_WORDS);
    int c = r / CHUNK_WORDS;
    int q = r % CHUNK_WORDS;
    int w = q & 1, lane = (q >> 1) & 31, ks = (q >> 6) & 3, u = (q >> 8) & 1;
    int gc = (q >> 9) % 3, wn = (q >> 9) / 3;
    int jc = c / 5, pc = c % 5;
    int gid = lane >> 2, tig = lane & 3;
    int grow = gc * 256 + jc * 64 + wn * 16 + u * 8 + gid;
    int k0 = ks * 16 + 2 * tig + w * 8;
    const float* wh = (s == 0) ? whL : ((s == 1) ? whM : whS);
    const float* wi = (s == 0) ? wiL : ((s == 1) ? wiM : wiS);
    const float* src = (pc < 4) ? (wh + (size_t)grow * 256 + pc * 64 + k0)
                                : (wi + (size_t)grow * 64 + k0);
    __half2 h2 = __floats2half2_rn(src[0], src[1]);
    d_WPK[W] = *(unsigned*)&h2;
}

// ================== persistent GRU: fp16 mma + bulk-DMA, 1024 threads ======
__global__ void __launch_bounds__(1024) gru_persist(
    float* __restrict__ hA, float* __restrict__ hB,
    const unsigned* __restrict__ wpk,
    const float* __restrict__ xL, const float* __restrict__ xM,
    const float* __restrict__ xS,
    const float* __restrict__ biasAll,
    const float* __restrict__ bhhL, const float* __restrict__ bhhM,
    const float* __restrict__ bhhS)
{
    extern __shared__ char smraw[];
    unsigned* Ring = (unsigned*)smraw;
    __half* Ah = (__half*)(smraw + SM_AH_OFF);
    __half* Xh = (__half*)(smraw + SM_XH_OFF);
    const unsigned ringaddr = smem_u32(smraw);
    const unsigned mbaddr = smem_u32(smraw + SM_MB_OFF);
    const unsigned ah_base = smem_u32(Ah);
    const unsigned xh_base = smem_u32(Xh);

    const int tid = threadIdx.x;
    const int s = blockIdx.x / MB;             // 0=long,1=medium,2=short
    const int m0 = (blockIdx.x % MB) * 128;
    const int T = (s == 0) ? 60 : ((s == 1) ? 30 : 8);
    const float* xsrc = (s == 0) ? xL : ((s == 1) ? xM : xS);
    const float* bhh = (s == 0) ? bhhL : ((s == 1) ? bhhM : bhhS);
    const float* bias = biasAll + s * 768;
    float* ha = hA + (size_t)s * NN * HD;
    float* hb = hB + (size_t)s * NN * HD;

    const int lane = tid & 31, gid = lane >> 2, tig = lane & 3;
    const int warp = tid >> 5;
    const int wm = warp & 7, wn = warp >> 3;   // 8 m-groups x 4 n-groups
    const int lrow = tid >> 3;                 // 0..127 staging row
    const int cbase = (tid & 7) * 4;           // col base for staging
    const int i4 = lane >> 3, r8 = lane & 7;   // ldmatrix address split

    // init mbarriers (arrive count 1: the expect_tx arrive)
    if (tid < 3) {
        asm volatile("mbarrier.init.shared.b64 [%0], %1;"
                     :: "r"(mbaddr + tid * 8), "r"(1u) : "memory");
    }
    __syncthreads();

#define ISSUE_CHUNK(cc) do {                                                    \
        int sl_ = (cc) % 3;                                                     \
        unsigned mb_ = mbaddr + sl_ * 8;                                        \
        asm volatile("mbarrier.arrive.expect_tx.shared.b64 _, [%0], %1;"        \
                     :: "r"(mb_), "r"((unsigned)CHUNK_BYTES) : "memory");       \
        unsigned dst_ = ringaddr + sl_ * CHUNK_BYTES;                           \
        const void* src_ = (const char*)wpk +                                   \
                           ((size_t)(s * 20 + (cc))) * CHUNK_BYTES;             \
        asm volatile(                                                           \
            "cp.async.bulk.shared::cluster.global.mbarrier::complete_tx::bytes " \
            "[%0], [%1], %2, [%3];"                                             \
            :: "r"(dst_), "l"(src_), "r"((unsigned)CHUNK_BYTES), "r"(mb_)       \
            : "memory");                                                        \
    } while (0)

    for (int t = 0; t < T; t++) {
        const float* hin = (t & 1) ? hb : ha;
        float* hout = (t & 1) ? ha : hb;

        // prologue copies (slots free: end-of-step sync passed)
        if (tid == 0) { ISSUE_CHUNK(0); ISSUE_CHUNK(1); ISSUE_CHUNK(2); }

        // ---- stage h (128x256) and x_t (128x64) into SMEM as fp16 ----
        {
            int grow = m0 + lrow;
            bool ok = grow < NN;
            const float* hr = hin + (size_t)grow * HD;
            __half* da = Ah + lrow * ASTH;
#pragma unroll
            for (int q = 0; q < 8; q++) {
                int col = cbase + q * 32;
                float4 v = ok ? *(const float4*)(hr + col)
                              : make_float4(0.f, 0.f, 0.f, 0.f);
                *(__half2*)(da + col)     = __floats2half2_rn(v.x, v.y);
                *(__half2*)(da + col + 2) = __floats2half2_rn(v.z, v.w);
            }
            const float* xr = xsrc + ((size_t)grow * T + t) * 64;
            __half* dx = Xh + lrow * XSTH;
#pragma unroll
            for (int q = 0; q < 2; q++) {
                int col = cbase + q * 32;
                float4 v = ok ? *(const float4*)(xr + col)
                              : make_float4(0.f, 0.f, 0.f, 0.f);
                *(__half2*)(dx + col)     = __floats2half2_rn(v.x, v.y);
                *(__half2*)(dx + col + 2) = __floats2half2_rn(v.z, v.w);
            }
        }
        __syncthreads();   // staged tiles visible to all warps

#pragma unroll
        for (int jc = 0; jc < 4; jc++) {
            float acc[8][4];
#pragma unroll
            for (int j = 0; j < 8; j++)
#pragma unroll
                for (int r = 0; r < 4; r++) acc[j][r] = 0.f;

#pragma unroll
            for (int pc = 0; pc < 5; pc++) {
                const int c = jc * 5 + pc;
                const int slot = c % 3;
                const int nuse = (slot == 2) ? 6 : 7;
                unsigned par = (unsigned)((t * nuse + c / 3) & 1);
                MBAR_WAIT(mbaddr + slot * 8, par);

                const unsigned* Bs = Ring + slot * CHUNK_WORDS;
                // A fragment source for this chunk
                const unsigned abase = (pc < 4) ? ah_base : xh_base;
                const int astr = (pc < 4) ? ASTH : XSTH;
                const int kofs = (pc < 4) ? pc * 64 : 0;

#pragma unroll
                for (int ks = 0; ks < 4; ks++) {
                    unsigned af[4];
                    int arow = wm * 16 + (i4 & 1) * 8 + r8;
                    int acol = kofs + ks * 16 + (i4 >> 1) * 8;
                    ldsm_x4(af, abase + (arow * astr + acol) * 2);
#pragma unroll
                    for (int gc = 0; gc < 3; gc++) {
                        const int ci = (pc == 4 && gc == 2) ? 3 : gc;
#pragma unroll
                        for (int u = 0; u < 2; u++) {
                            int fb = ((((wn * 3 + gc) * 2 + u) * 4 + ks) * 32
                                      + lane) * 2;
                            uint2 bf = *(const uint2*)(Bs + fb);
                            mma_f16(acc[ci * 2 + u], af, &bf.x);
                        }
                    }
                }
                __syncthreads();           // all consumers done with slot
                if (tid == 0 && c + 3 < 20) ISSUE_CHUNK(c + 3);
            }

            // ---- epilogue: GRU update for these 64 j ----
            const int j0 = jc * 64;
#pragma unroll
            for (int u = 0; u < 2; u++)
#pragma unroll
                for (int h2 = 0; h2 < 2; h2++)
#pragma unroll
                    for (int pp = 0; pp < 2; pp++) {
                        int row = m0 + wm * 16 + gid + h2 * 8;
                        if (row >= NN) continue;
                        int jg = j0 + wn * 16 + u * 8 + 2 * tig + pp;
                        int reg = h2 * 2 + pp;
                        float ar  = acc[0 + u][reg];
                        float az  = acc[2 + u][reg];
                        float anh = acc[4 + u][reg];
                        float anx = acc[6 + u][reg];
                        float r = sigf(ar + bias[jg]);
                        float z = sigf(az + bias[256 + jg]);
                        float n = tanhf(anx + bias[512 + jg] +
                                        r * (anh + bhh[512 + jg]));
                        float hp = hin[(size_t)row * HD + jg];
                        hout[(size_t)row * HD + jg] = (1.f - z) * n + z * hp;
                    }
        }
        __threadfence_block();
        __syncthreads();   // hout visible; Ah/Xh free for next t
    }
#undef ISSUE_CHUNK
}

// ---------------- fp32 f32x2 GEMM (GNN section) ----------------
__device__ __forceinline__ unsigned long long pack2(float x, float y) {
    unsigned long long r;
    asm("mov.b64 %0, {%1, %2};" : "=l"(r) : "f"(x), "f"(y));
    return r;
}
__device__ __forceinline__ void unpack2(unsigned long long v, float& x, float& y) {
    asm("mov.b64 {%0, %1}, %2;" : "=f"(x), "=f"(y) : "l"(v));
}
__device__ __forceinline__ void ffma2(unsigned long long& d, unsigned long long a,
                                      unsigned long long b) {
    asm("fma.rn.f32x2 %0, %1, %2, %0;" : "+l"(d) : "l"(a), "l"(b));
}

__global__ void __launch_bounds__(256) gemm_tn(
    const float* __restrict__ A, int lda,
    const float* __restrict__ B, int ldb,
    const float* __restrict__ bias,
    float* __restrict__ C, int ldc,
    int M, int K, int relu)
{
    __shared__ float As[16][128];
    __shared__ float Bs[16][64];
    const int tid = threadIdx.x;
    const int m0 = blockIdx.x * 128;
    const int n0 = blockIdx.y * 64;
    const int tx = tid & 15;
    const int ty = tid >> 4;

    unsigned long long acc[8][2];
#pragma unroll
    for (int i = 0; i < 8; i++) { acc[i][0] = 0ull; acc[i][1] = 0ull; }

    const int ar0 = tid >> 2;
    const int ar1 = (tid + 256) >> 2;
    const int aq = tid & 3;
    const int br = tid >> 2;
    const int bq = tid & 3;

    for (int k0 = 0; k0 < K; k0 += 16) {
        float4 va0 = make_float4(0.f, 0.f, 0.f, 0.f);
        float4 va1 = va0;
        if (m0 + ar0 < M) va0 = *(const float4*)(A + (size_t)(m0 + ar0) * lda + k0 + aq * 4);
        if (m0 + ar1 < M) va1 = *(const float4*)(A + (size_t)(m0 + ar1) * lda + k0 + aq * 4);
        float4 vb = *(const float4*)(B + (size_t)(n0 + br) * ldb + k0 + bq * 4);

        As[aq * 4 + 0][ar0] = va0.x; As[aq * 4 + 1][ar0] = va0.y;
        As[aq * 4 + 2][ar0] = va0.z; As[aq * 4 + 3][ar0] = va0.w;
        As[aq * 4 + 0][ar1] = va1.x; As[aq * 4 + 1][ar1] = va1.y;
        As[aq * 4 + 2][ar1] = va1.z; As[aq * 4 + 3][ar1] = va1.w;
        Bs[bq * 4 + 0][br] = vb.x; Bs[bq * 4 + 1][br] = vb.y;
        Bs[bq * 4 + 2][br] = vb.z; Bs[bq * 4 + 3][br] = vb.w;
        __syncthreads();

#pragma unroll
        for (int kk = 0; kk < 16; kk++) {
            float4 a0 = *(const float4*)&As[kk][ty * 8];
            float4 a1 = *(const float4*)&As[kk][ty * 8 + 4];
            unsigned long long b0 = *(const unsigned long long*)&Bs[kk][tx * 4];
            unsigned long long b1 = *(const unsigned long long*)&Bs[kk][tx * 4 + 2];
            float av[8] = {a0.x, a0.y, a0.z, a0.w, a1.x, a1.y, a1.z, a1.w};
#pragma unroll
            for (int i = 0; i < 8; i++) {
                unsigned long long a2 = pack2(av[i], av[i]);
                ffma2(acc[i][0], a2, b0);
                ffma2(acc[i][1], a2, b1);
            }
        }
        __syncthreads();
    }

    float b4[4] = {0.f, 0.f, 0.f, 0.f};
    if (bias) {
        float4 bv = *(const float4*)(bias + n0 + tx * 4);
        b4[0] = bv.x; b4[1] = bv.y; b4[2] = bv.z; b4[3] = bv.w;
    }
#pragma unroll
    for (int i = 0; i < 8; i++) {
        int m = m0 + ty * 8 + i;
        if (m < M) {
            float c0, c1, c2, c3;
            unpack2(acc[i][0], c0, c1);
            unpack2(acc[i][1], c2, c3);
            c0 += b4[0]; c1 += b4[1]; c2 += b4[2]; c3 += b4[3];
            if (relu) {
                c0 = fmaxf(c0, 0.f); c1 = fmaxf(c1, 0.f);
                c2 = fmaxf(c2, 0.f); c3 = fmaxf(c3, 0.f);
            }
            *(float4*)(C + (size_t)m * ldc + n0 + tx * 4) = make_float4(c0, c1, c2, c3);
        }
    }
}

__global__ void k_concat(const float* __restrict__ hs, const float* __restrict__ hm,
                         const float* __restrict__ hl) {
    int i = blockIdx.x * 256 + threadIdx.x;
    if (i >= NN * H3) return;
    int n = i / H3, j = i % H3;
    float v;
    if (j < 256)      v = hs[n * HD + j];
    else if (j < 512) v = hm[n * HD + j - 256];
    else              v = hl[n * HD + j - 512];
    d_COMB[i] = v;
}

// ---------------- SAGE attention (decomposed scores) ----------------
__device__ __forceinline__ unsigned fenc(float f) {
    unsigned u = __float_as_uint(f);
    return (u & 0x80000000u) ? ~u : (u | 0x80000000u);
}
__device__ __forceinline__ float fdec(unsigned u) {
    u = (u & 0x80000000u) ? (u & 0x7fffffffu) : ~u;
    return __uint_as_float(u);
}

__global__ void k_pq(const float* __restrict__ aw) {
    int n = blockIdx.x * 8 + (threadIdx.x >> 5);
    int lane = threadIdx.x & 31;
    if (n >= NN) return;
    float p = 0.f, q = 0.f;
#pragma unroll
    for (int j = lane; j < 256; j += 32) {
        float v = d_XL[n * GD + j];
        p += v * aw[j];
        q += v * aw[256 + j];
    }
#pragma unroll
    for (int o = 16; o; o >>= 1) {
        p += __shfl_xor_sync(0xffffffffu, p, o);
        q += __shfl_xor_sync(0xffffffffu, q, o);
    }
    if (lane == 0) { d_P[n] = p; d_Q[n] = q; }
}

__global__ void k_init() {
    int n = blockIdx.x * 256 + threadIdx.x;
    if (n < NN) { d_MENC[n] = 0x007fffffu; d_SSUM[n] = 0.f; }
}

__global__ void k_edge1(const int* __restrict__ ei, const float* __restrict__ ea,
                        const float* __restrict__ aw, const float* __restrict__ ab) {
    int e = blockIdx.x * 256 + threadIdx.x;
    if (e >= NE) return;
    int row = ei[e], col = ei[NE + e];
    float sc = d_P[row] + d_Q[col] + aw[512] * ea[e] + ab[0];
    d_SC[e] = sc;
    atomicMax(&d_MENC[row], fenc(sc));
}

__global__ void k_edge2(const int* __restrict__ ei) {
    int e = blockIdx.x * 256 + threadIdx.x;
    if (e >= NE) return;
    int row = ei[e];
    float m = fdec(d_MENC[row]);
    float ex = expf(d_SC[e] - m);
    d_SC[e] = ex;
    atomicAdd(&d_SSUM[row], ex);
}

__global__ void k_edge3(const int* __restrict__ ei) {
    int e = blockIdx.x * 4 + (threadIdx.x >> 6);
    int l = threadIdx.x & 63;
    if (e >= NE) return;
    int row = ei[e], col = ei[NE + e];
    float alpha = d_SC[e] / (d_SSUM[row] + 1e-16f);
    float4 v = *(const float4*)&d_XL[row * GD + l * 4];
    float* dst = &d_AGG[col * GD + l * 4];
    atomicAdd(dst + 0, alpha * v.x);
    atomicAdd(dst + 1, alpha * v.y);
    atomicAdd(dst + 2, alpha * v.z);
    atomicAdd(dst + 3, alpha * v.w);
}

__global__ void k_finish(const float* __restrict__ addsrc, float* __restrict__ dst) {
    int i = blockIdx.x * 256 + threadIdx.x;
    if (i >= NN * GD) return;
    float v = d_AGG[i];
    v = v > 0.f ? v : 0.f;
    if (addsrc) v += addsrc[i];
    dst[i] = v;
}

__global__ void k_heads(const float* __restrict__ impW, const float* __restrict__ impb,
                        const float* __restrict__ uncW, const float* __restrict__ uncb,
                        float* __restrict__ out) {
    int n = blockIdx.x * 8 + (threadIdx.x >> 5);
    int lane = threadIdx.x & 31;
    if (n >= NN) return;
    float a = 0.f, b = 0.f;
#pragma unroll
    for (int j = lane; j < GD; j += 32) {
        float v = d_G2[n * GD + j];
        a += v * impW[j];
        b += v * uncW[j];
    }
#pragma unroll
    for (int o = 16; o; o >>= 1) {
        a += __shfl_xor_sync(0xffffffffu, a, o);
        b += __shfl_xor_sync(0xffffffffu, b, o);
    }
    if (lane == 0) {
        out[n] = tanhf(a + impb[0]);
        out[NN + n] = 1.f / (1.f + expf(-(b + uncb[0])));
    }
}

// ---------------- host orchestration ----------------
extern "C" void kernel_launch(void* const* d_in, const int* in_sizes, int n_in,
                              void* d_out, int out_size)
{
    const float* x_s = (const float*)d_in[0];
    const float* x_m = (const float*)d_in[1];
    const float* x_l = (const float*)d_in[2];
    const int*   ei  = (const int*)d_in[3];
    const float* ea  = (const float*)d_in[4];
    // scale order here: 0=long, 1=medium, 2=short
    const float* Wih[3] = {(const float*)d_in[13], (const float*)d_in[9], (const float*)d_in[5]};
    const float* Whh[3] = {(const float*)d_in[14], (const float*)d_in[10], (const float*)d_in[6]};
    const float* bih[3] = {(const float*)d_in[15], (const float*)d_in[11], (const float*)d_in[7]};
    const float* bhh[3] = {(const float*)d_in[16], (const float*)d_in[12], (const float*)d_in[8]};
    const float* fW   = (const float*)d_in[17];
    const float* fb   = (const float*)d_in[18];
    const float* g1W  = (const float*)d_in[19];
    const float* g1aw = (const float*)d_in[20];
    const float* g1ab = (const float*)d_in[21];
    const float* g2W  = (const float*)d_in[22];
    const float* g2aw = (const float*)d_in[23];
    const float* g2ab = (const float*)d_in[24];
    const float* impW = (const float*)d_in[25];
    const float* impb = (const float*)d_in[26];
    const float* uncW = (const float*)d_in[27];
    const float* uncb = (const float*)d_in[28];

    void *pWPK, *pBIAS, *pHA, *pHB;
    void *pCOMB, *pTEMB, *pXL, *pAGG, *pG1, *pG2;
    cudaGetSymbolAddress(&pWPK, d_WPK);
    cudaGetSymbolAddress(&pBIAS, d_BIAS);
    cudaGetSymbolAddress(&pHA, d_HA);
    cudaGetSymbolAddress(&pHB, d_HB);
    cudaGetSymbolAddress(&pCOMB, d_COMB);
    cudaGetSymbolAddress(&pTEMB, d_TEMB);
    cudaGetSymbolAddress(&pXL, d_XL);
    cudaGetSymbolAddress(&pAGG, d_AGG);
    cudaGetSymbolAddress(&pG1, d_G1);
    cudaGetSymbolAddress(&pG2, d_G2);
    unsigned* WPKp = (unsigned*)pWPK;
    float* BIASp = (float*)pBIAS;
    float* HA = (float*)pHA; float* HB = (float*)pHB;
    float* COMB = (float*)pCOMB; float* TEMB = (float*)pTEMB;
    float* XL = (float*)pXL; float* AGG = (float*)pAGG;
    float* G1 = (float*)pG1; float* G2 = (float*)pG2;

    cudaFuncSetAttribute(gru_persist,
                         cudaFuncAttributeMaxDynamicSharedMemorySize, PERSIST_SMEM);

    // ---- fold biases + repack weights ----
    for (int s = 0; s < 3; s++)
        k_prep_bias<<<1, 768>>>(bih[s], bhh[s], s);
    k_pack<<<(3 * 20 * CHUNK_WORDS + 255) / 256, 256>>>(
        Whh[0], Wih[0], Whh[1], Wih[1], Whh[2], Wih[2]);

    // ---- persistent recurrence: ONE launch for all 3 GRUs, all timesteps --
    cudaMemsetAsync(HA, 0, (size_t)3 * NN * HD * sizeof(float));
    gru_persist<<<3 * MB, 1024, PERSIST_SMEM>>>(
        HA, HB, WPKp, x_l, x_m, x_s, BIASp, bhh[0], bhh[1], bhh[2]);

    // finals all land in HA (T even for every scale): 0=l, 1=m, 2=s
    float* HL = HA;
    float* HM = HA + (size_t)NN * HD;
    float* HS = HA + (size_t)2 * NN * HD;

    // ---- fusion ----
    dim3 gS((NN + 127) / 128, GD / 64);
    k_concat<<<(NN * H3 + 255) / 256, 256>>>(HS, HM, HL);
    gemm_tn<<<gS, 256>>>(COMB, H3, fW, H3, fb, TEMB, GD, NN, H3, 1);

    // ---- SAGE layer 1 ----
    gemm_tn<<<gS, 256>>>(TEMB, GD, g1W, GD, nullptr, XL, GD, NN, GD, 0);
    k_pq<<<(NN + 7) / 8, 256>>>(g1aw);
    k_init<<<(NN + 255) / 256, 256>>>();
    cudaMemsetAsync(AGG, 0, (size_t)NN * GD * sizeof(float));
    k_edge1<<<(NE + 255) / 256, 256>>>(ei, ea, g1aw, g1ab);
    k_edge2<<<(NE + 255) / 256, 256>>>(ei);
    k_edge3<<<NE / 4, 256>>>(ei);
    k_finish<<<(NN * GD + 255) / 256, 256>>>(nullptr, G1);

    // ---- SAGE layer 2 ----
    gemm_tn<<<gS, 256>>>(G1, GD, g2W, GD, nullptr, XL, GD, NN, GD, 0);
    k_pq<<<(NN + 7) / 8, 256>>>(g2aw);
    k_init<<<(NN + 255) / 256, 256>>>();
    cudaMemsetAsync(AGG, 0, (size_t)NN * GD * sizeof(float));
    k_edge1<<<(NE + 255) / 256, 256>>>(ei, ea, g2aw, g2ab);
    k_edge2<<<(NE + 255) / 256, 256>>>(ei);
    k_edge3<<<NE / 4, 256>>>(ei);
    k_finish<<<(NN * GD + 255) / 256, 256>>>(TEMB, G2);

    // ---- heads ----
    k_heads<<<(NN + 7) / 8, 256>>>(impW, impb, uncW, uncb, (float*)d_out);
}

// round 10
// speedup vs baseline: 3.2467x; 1.1893x over previous
#include <cuda_runtime.h>
#include <cuda_fp16.h>

#define NN 10000
#define NE 320000
#define FD 64
#define HD 256
#define GD 256
#define H3 768
#define MB 79                 // blocks per scale (ceil 10000/128)

#define ASTH 264              // h tile smem stride (halves)
#define XSTH 72               // x tile smem stride (halves)
#define ASM_H (128 * ASTH)
#define XSM_H (128 * XSTH)
#define CHUNK_WORDS 6144      // 192 rows x 64 halves = 24576 B
#define CHUNK_BYTES 24576
#define RING_BYTES (3 * CHUNK_BYTES)
// smem: [ring 73728][Ah 67584][Xh 18432][mbar 24]
#define SM_AH_OFF RING_BYTES
#define SM_XH_OFF (SM_AH_OFF + ASM_H * 2)
#define SM_MB_OFF (SM_XH_OFF + XSM_H * 2)
#define PERSIST_SMEM (SM_MB_OFF + 32)

// ---------------- static scratch ----------------
__device__ unsigned d_WPK[3 * 20 * CHUNK_WORDS];  // repacked fp16 weights
__device__ float d_BIAS[3 * 768];          // bih + (col<512 ? bhh : 0)
__device__ float d_HA[3 * NN * HD];
__device__ float d_HB[3 * NN * HD];
__device__ float d_COMB[NN * H3];
__device__ float d_TEMB[NN * GD];
__device__ float d_XL[NN * GD];
__device__ float d_AGG[NN * GD];
__device__ float d_G1[NN * GD];
__device__ float d_G2[NN * GD];
__device__ float d_P[NN];
__device__ float d_Q[NN];
__device__ float d_SSUM[NN];
__device__ unsigned d_MENC[NN];
__device__ float d_SC[NE];

// ---------------- helpers ----------------
__device__ __forceinline__ float sigf(float x) { return 1.f / (1.f + expf(-x)); }
// fast gate math (EX2/RCP-based, ~1e-6 rel err)
__device__ __forceinline__ float fsig(float x) {
    return __fdividef(1.f, 1.f + __expf(-x));
}
__device__ __forceinline__ float ftanh(float x) {
    x = fminf(fmaxf(x, -15.f), 15.f);
    float e = __expf(-2.f * x);
    return __fdividef(1.f - e, 1.f + e);
}

__device__ __forceinline__ unsigned smem_u32(const void* p) {
    return (unsigned)__cvta_generic_to_shared(p);
}

__device__ __forceinline__ void mma_f16(float* c, const unsigned* a, const unsigned* b) {
    asm volatile(
        "mma.sync.aligned.m16n8k16.row.col.f32.f16.f16.f32 "
        "{%0,%1,%2,%3},{%4,%5,%6,%7},{%8,%9},{%0,%1,%2,%3};"
        : "+f"(c[0]), "+f"(c[1]), "+f"(c[2]), "+f"(c[3])
        : "r"(a[0]), "r"(a[1]), "r"(a[2]), "r"(a[3]), "r"(b[0]), "r"(b[1]));
}

__device__ __forceinline__ void ldsm_x4(unsigned* r, unsigned addr) {
    asm volatile("ldmatrix.sync.aligned.m8n8.x4.shared.b16 {%0,%1,%2,%3}, [%4];"
                 : "=r"(r[0]), "=r"(r[1]), "=r"(r[2]), "=r"(r[3]) : "r"(addr));
}

#define MBAR_WAIT(addr, par) do {                                               \
    asm volatile(                                                               \
        "{\n\t.reg .pred P1;\n\t"                                               \
        "WAIT_%=:\n\t"                                                          \
        "mbarrier.try_wait.parity.acquire.cta.shared::cta.b64 P1, [%0], %1, 0x989680;\n\t" \
        "@P1 bra.uni DONE_%=;\n\t"                                              \
        "bra.uni WAIT_%=;\n\t"                                                  \
        "DONE_%=:\n\t}"                                                         \
        :: "r"(addr), "r"(par) : "memory");                                     \
} while (0)

// ---------------- bias fold ----------------
__global__ void k_prep_bias(const float* __restrict__ bih,
                            const float* __restrict__ bhh, int s) {
    int i = threadIdx.x;   // 768 threads
    d_BIAS[s * 768 + i] = bih[i] + (i < 512 ? bhh[i] : 0.f);
}

// ---------------- weight repack into fragment-ordered chunks ----------------
// chunk c = jc*5 + pc; pc<4 -> Whh k-slice pc*64, pc==4 -> Wih (K=64).
// word q = ((((wn*3+gc)*2+u)*4+ks)*32 + lane)*2 + w
// source row = gc*256 + jc*64 + wn*16 + u*8 + (lane>>2)
// source k   = ks*16 + 2*(lane&3) + w*8   (halves k, k+1)
__global__ void k_pack(const float* __restrict__ whL, const float* __restrict__ wiL,
                       const float* __restrict__ whM, const float* __restrict__ wiM,
                       const float* __restrict__ whS, const float* __restrict__ wiS) {
    int W = blockIdx.x * 256 + threadIdx.x;
    if (W >= 3 * 20 * CHUNK_WORDS) return;
    int s = W / (20 * CHUNK_WORDS);
    int r = W % (20 * CHUNK_WORDS);
    int c = r / CHUNK_WORDS;
    int q = r % CHUNK_WORDS;
    int w = q & 1, lane = (q >> 1) & 31, ks = (q >> 6) & 3, u = (q >> 8) & 1;
    int gc = (q >> 9) % 3, wn = (q >> 9) / 3;
    int jc = c / 5, pc = c % 5;
    int gid = lane >> 2, tig = lane & 3;
    int grow = gc * 256 + jc * 64 + wn * 16 + u * 8 + gid;
    int k0 = ks * 16 + 2 * tig + w * 8;
    const float* wh = (s == 0) ? whL : ((s == 1) ? whM : whS);
    const float* wi = (s == 0) ? wiL : ((s == 1) ? wiM : wiS);
    const float* src = (pc < 4) ? (wh + (size_t)grow * 256 + pc * 64 + k0)
                                : (wi + (size_t)grow * 64 + k0);
    __half2 h2 = __floats2half2_rn(src[0], src[1]);
    d_WPK[W] = *(unsigned*)&h2;
}

// ================== persistent GRU: fp16 mma + bulk-DMA, 1024 threads ======
__global__ void __launch_bounds__(1024) gru_persist(
    float* __restrict__ hA, float* __restrict__ hB,
    const unsigned* __restrict__ wpk,
    const float* __restrict__ xL, const float* __restrict__ xM,
    const float* __restrict__ xS,
    const float* __restrict__ biasAll,
    const float* __restrict__ bhhL, const float* __restrict__ bhhM,
    const float* __restrict__ bhhS)
{
    extern __shared__ char smraw[];
    unsigned* Ring = (unsigned*)smraw;
    __half* Ah = (__half*)(smraw + SM_AH_OFF);
    __half* Xh = (__half*)(smraw + SM_XH_OFF);
    const unsigned ringaddr = smem_u32(smraw);
    const unsigned mbaddr = smem_u32(smraw + SM_MB_OFF);
    const unsigned ah_base = smem_u32(Ah);
    const unsigned xh_base = smem_u32(Xh);

    const int tid = threadIdx.x;
    const int s = blockIdx.x / MB;             // 0=long,1=medium,2=short
    const int m0 = (blockIdx.x % MB) * 128;
    const int T = (s == 0) ? 60 : ((s == 1) ? 30 : 8);
    const float* xsrc = (s == 0) ? xL : ((s == 1) ? xM : xS);
    const float* bhh = (s == 0) ? bhhL : ((s == 1) ? bhhM : bhhS);
    const float* bias = biasAll + s * 768;
    float* ha = hA + (size_t)s * NN * HD;
    float* hb = hB + (size_t)s * NN * HD;

    const int lane = tid & 31, gid = lane >> 2, tig = lane & 3;
    const int warp = tid >> 5;
    const int wm = warp & 7, wn = warp >> 3;   // 8 m-groups x 4 n-groups
    const int lrow = tid >> 3;                 // 0..127 staging row
    const int cbase = (tid & 7) * 4;           // col base for staging
    const int i4 = lane >> 3, r8 = lane & 7;   // ldmatrix address split

    // init mbarriers (arrive count 1: the expect_tx arrive)
    if (tid < 3) {
        asm volatile("mbarrier.init.shared.b64 [%0], %1;"
                     :: "r"(mbaddr + tid * 8), "r"(1u) : "memory");
    }
    __syncthreads();

#define ISSUE_CHUNK(cc) do {                                                    \
        int sl_ = (cc) % 3;                                                     \
        unsigned mb_ = mbaddr + sl_ * 8;                                        \
        asm volatile("mbarrier.arrive.expect_tx.shared.b64 _, [%0], %1;"        \
                     :: "r"(mb_), "r"((unsigned)CHUNK_BYTES) : "memory");       \
        unsigned dst_ = ringaddr + sl_ * CHUNK_BYTES;                           \
        const void* src_ = (const char*)wpk +                                   \
                           ((size_t)(s * 20 + (cc))) * CHUNK_BYTES;             \
        asm volatile(                                                           \
            "cp.async.bulk.shared::cluster.global.mbarrier::complete_tx::bytes " \
            "[%0], [%1], %2, [%3];"                                             \
            :: "r"(dst_), "l"(src_), "r"((unsigned)CHUNK_BYTES), "r"(mb_)       \
            : "memory");                                                        \
    } while (0)

    for (int t = 0; t < T; t++) {
        const float* hin = (t & 1) ? hb : ha;
        float* hout = (t & 1) ? ha : hb;

        // prologue copies (slots free: end-of-step sync passed)
        if (tid == 0) { ISSUE_CHUNK(0); ISSUE_CHUNK(1); ISSUE_CHUNK(2); }

        // ---- stage h (128x256) and x_t (128x64) into SMEM as fp16 ----
        {
            int grow = m0 + lrow;
            bool ok = grow < NN;
            const float* hr = hin + (size_t)grow * HD;
            __half* da = Ah + lrow * ASTH;
#pragma unroll
            for (int q = 0; q < 8; q++) {
                int col = cbase + q * 32;
                float4 v = ok ? *(const float4*)(hr + col)
                              : make_float4(0.f, 0.f, 0.f, 0.f);
                *(__half2*)(da + col)     = __floats2half2_rn(v.x, v.y);
                *(__half2*)(da + col + 2) = __floats2half2_rn(v.z, v.w);
            }
            const float* xr = xsrc + ((size_t)grow * T + t) * 64;
            __half* dx = Xh + lrow * XSTH;
#pragma unroll
            for (int q = 0; q < 2; q++) {
                int col = cbase + q * 32;
                float4 v = ok ? *(const float4*)(xr + col)
                              : make_float4(0.f, 0.f, 0.f, 0.f);
                *(__half2*)(dx + col)     = __floats2half2_rn(v.x, v.y);
                *(__half2*)(dx + col + 2) = __floats2half2_rn(v.z, v.w);
            }
        }
        __syncthreads();   // staged tiles visible to all warps

#pragma unroll
        for (int jc = 0; jc < 4; jc++) {
            float acc[8][4];
#pragma unroll
            for (int j = 0; j < 8; j++)
#pragma unroll
                for (int r = 0; r < 4; r++) acc[j][r] = 0.f;

#pragma unroll
            for (int pc = 0; pc < 5; pc++) {
                const int c = jc * 5 + pc;
                const int slot = c % 3;
                const int nuse = (slot == 2) ? 6 : 7;
                unsigned par = (unsigned)((t * nuse + c / 3) & 1);
                MBAR_WAIT(mbaddr + slot * 8, par);

                const unsigned* Bs = Ring + slot * CHUNK_WORDS;
                // A fragment source for this chunk
                const unsigned abase = (pc < 4) ? ah_base : xh_base;
                const int astr = (pc < 4) ? ASTH : XSTH;
                const int kofs = (pc < 4) ? pc * 64 : 0;

#pragma unroll
                for (int ks = 0; ks < 4; ks++) {
                    unsigned af[4];
                    int arow = wm * 16 + (i4 & 1) * 8 + r8;
                    int acol = kofs + ks * 16 + (i4 >> 1) * 8;
                    ldsm_x4(af, abase + (arow * astr + acol) * 2);
#pragma unroll
                    for (int gc = 0; gc < 3; gc++) {
                        const int ci = (pc == 4 && gc == 2) ? 3 : gc;
#pragma unroll
                        for (int u = 0; u < 2; u++) {
                            int fb = ((((wn * 3 + gc) * 2 + u) * 4 + ks) * 32
                                      + lane) * 2;
                            uint2 bf = *(const uint2*)(Bs + fb);
                            mma_f16(acc[ci * 2 + u], af, &bf.x);
                        }
                    }
                }
                __syncthreads();           // all consumers done with slot
                if (tid == 0 && c + 3 < 20) ISSUE_CHUNK(c + 3);
            }

            // ---- epilogue: GRU update for these 64 j (fast gates, float2) --
            const int j0 = jc * 64;
#pragma unroll
            for (int u = 0; u < 2; u++)
#pragma unroll
                for (int h2 = 0; h2 < 2; h2++) {
                    int row = m0 + wm * 16 + gid + h2 * 8;
                    if (row >= NN) continue;
                    int jg = j0 + wn * 16 + u * 8 + 2 * tig;
                    float2 hp = *(const float2*)(hin + (size_t)row * HD + jg);
                    float2 ho;
                    {
                        float r0 = fsig(acc[0 + u][h2 * 2 + 0] + bias[jg]);
                        float z0 = fsig(acc[2 + u][h2 * 2 + 0] + bias[256 + jg]);
                        float n0 = ftanh(acc[6 + u][h2 * 2 + 0] + bias[512 + jg] +
                                         r0 * (acc[4 + u][h2 * 2 + 0] + bhh[512 + jg]));
                        ho.x = (1.f - z0) * n0 + z0 * hp.x;
                    }
                    {
                        float r1 = fsig(acc[0 + u][h2 * 2 + 1] + bias[jg + 1]);
                        float z1 = fsig(acc[2 + u][h2 * 2 + 1] + bias[256 + jg + 1]);
                        float n1 = ftanh(acc[6 + u][h2 * 2 + 1] + bias[512 + jg + 1] +
                                         r1 * (acc[4 + u][h2 * 2 + 1] + bhh[512 + jg + 1]));
                        ho.y = (1.f - z1) * n1 + z1 * hp.y;
                    }
                    *(float2*)(hout + (size_t)row * HD + jg) = ho;
                }
        }
        __threadfence_block();
        __syncthreads();   // hout visible; Ah/Xh free for next t
    }
#undef ISSUE_CHUNK
}

// ---------------- fp32 f32x2 GEMM (GNN section) ----------------
__device__ __forceinline__ unsigned long long pack2(float x, float y) {
    unsigned long long r;
    asm("mov.b64 %0, {%1, %2};" : "=l"(r) : "f"(x), "f"(y));
    return r;
}
__device__ __forceinline__ void unpack2(unsigned long long v, float& x, float& y) {
    asm("mov.b64 {%0, %1}, %2;" : "=f"(x), "=f"(y) : "l"(v));
}
__device__ __forceinline__ void ffma2(unsigned long long& d, unsigned long long a,
                                      unsigned long long b) {
    asm("fma.rn.f32x2 %0, %1, %2, %0;" : "+l"(d) : "l"(a), "l"(b));
}

__global__ void __launch_bounds__(256) gemm_tn(
    const float* __restrict__ A, int lda,
    const float* __restrict__ B, int ldb,
    const float* __restrict__ bias,
    float* __restrict__ C, int ldc,
    int M, int K, int relu)
{
    __shared__ float As[16][128];
    __shared__ float Bs[16][64];
    const int tid = threadIdx.x;
    const int m0 = blockIdx.x * 128;
    const int n0 = blockIdx.y * 64;
    const int tx = tid & 15;
    const int ty = tid >> 4;

    unsigned long long acc[8][2];
#pragma unroll
    for (int i = 0; i < 8; i++) { acc[i][0] = 0ull; acc[i][1] = 0ull; }

    const int ar0 = tid >> 2;
    const int ar1 = (tid + 256) >> 2;
    const int aq = tid & 3;
    const int br = tid >> 2;
    const int bq = tid & 3;

    for (int k0 = 0; k0 < K; k0 += 16) {
        float4 va0 = make_float4(0.f, 0.f, 0.f, 0.f);
        float4 va1 = va0;
        if (m0 + ar0 < M) va0 = *(const float4*)(A + (size_t)(m0 + ar0) * lda + k0 + aq * 4);
        if (m0 + ar1 < M) va1 = *(const float4*)(A + (size_t)(m0 + ar1) * lda + k0 + aq * 4);
        float4 vb = *(const float4*)(B + (size_t)(n0 + br) * ldb + k0 + bq * 4);

        As[aq * 4 + 0][ar0] = va0.x; As[aq * 4 + 1][ar0] = va0.y;
        As[aq * 4 + 2][ar0] = va0.z; As[aq * 4 + 3][ar0] = va0.w;
        As[aq * 4 + 0][ar1] = va1.x; As[aq * 4 + 1][ar1] = va1.y;
        As[aq * 4 + 2][ar1] = va1.z; As[aq * 4 + 3][ar1] = va1.w;
        Bs[bq * 4 + 0][br] = vb.x; Bs[bq * 4 + 1][br] = vb.y;
        Bs[bq * 4 + 2][br] = vb.z; Bs[bq * 4 + 3][br] = vb.w;
        __syncthreads();

#pragma unroll
        for (int kk = 0; kk < 16; kk++) {
            float4 a0 = *(const float4*)&As[kk][ty * 8];
            float4 a1 = *(const float4*)&As[kk][ty * 8 + 4];
            unsigned long long b0 = *(const unsigned long long*)&Bs[kk][tx * 4];
            unsigned long long b1 = *(const unsigned long long*)&Bs[kk][tx * 4 + 2];
            float av[8] = {a0.x, a0.y, a0.z, a0.w, a1.x, a1.y, a1.z, a1.w};
#pragma unroll
            for (int i = 0; i < 8; i++) {
                unsigned long long a2 = pack2(av[i], av[i]);
                ffma2(acc[i][0], a2, b0);
                ffma2(acc[i][1], a2, b1);
            }
        }
        __syncthreads();
    }

    float b4[4] = {0.f, 0.f, 0.f, 0.f};
    if (bias) {
        float4 bv = *(const float4*)(bias + n0 + tx * 4);
        b4[0] = bv.x; b4[1] = bv.y; b4[2] = bv.z; b4[3] = bv.w;
    }
#pragma unroll
    for (int i = 0; i < 8; i++) {
        int m = m0 + ty * 8 + i;
        if (m < M) {
            float c0, c1, c2, c3;
            unpack2(acc[i][0], c0, c1);
            unpack2(acc[i][1], c2, c3);
            c0 += b4[0]; c1 += b4[1]; c2 += b4[2]; c3 += b4[3];
            if (relu) {
                c0 = fmaxf(c0, 0.f); c1 = fmaxf(c1, 0.f);
                c2 = fmaxf(c2, 0.f); c3 = fmaxf(c3, 0.f);
            }
            *(float4*)(C + (size_t)m * ldc + n0 + tx * 4) = make_float4(c0, c1, c2, c3);
        }
    }
}

__global__ void k_concat(const float* __restrict__ hs, const float* __restrict__ hm,
                         const float* __restrict__ hl) {
    int i = blockIdx.x * 256 + threadIdx.x;
    if (i >= NN * H3) return;
    int n = i / H3, j = i % H3;
    float v;
    if (j < 256)      v = hs[n * HD + j];
    else if (j < 512) v = hm[n * HD + j - 256];
    else              v = hl[n * HD + j - 512];
    d_COMB[i] = v;
}

// ---------------- SAGE attention (decomposed scores) ----------------
__device__ __forceinline__ unsigned fenc(float f) {
    unsigned u = __float_as_uint(f);
    return (u & 0x80000000u) ? ~u : (u | 0x80000000u);
}
__device__ __forceinline__ float fdec(unsigned u) {
    u = (u & 0x80000000u) ? (u & 0x7fffffffu) : ~u;
    return __uint_as_float(u);
}

__global__ void k_pq(const float* __restrict__ aw) {
    int n = blockIdx.x * 8 + (threadIdx.x >> 5);
    int lane = threadIdx.x & 31;
    if (n >= NN) return;
    float p = 0.f, q = 0.f;
#pragma unroll
    for (int j = lane; j < 256; j += 32) {
        float v = d_XL[n * GD + j];
        p += v * aw[j];
        q += v * aw[256 + j];
    }
#pragma unroll
    for (int o = 16; o; o >>= 1) {
        p += __shfl_xor_sync(0xffffffffu, p, o);
        q += __shfl_xor_sync(0xffffffffu, q, o);
    }
    if (lane == 0) { d_P[n] = p; d_Q[n] = q; }
}

__global__ void k_init() {
    int n = blockIdx.x * 256 + threadIdx.x;
    if (n < NN) { d_MENC[n] = 0x007fffffu; d_SSUM[n] = 0.f; }
}

__global__ void k_edge1(const int* __restrict__ ei, const float* __restrict__ ea,
                        const float* __restrict__ aw, const float* __restrict__ ab) {
    int e = blockIdx.x * 256 + threadIdx.x;
    if (e >= NE) return;
    int row = ei[e], col = ei[NE + e];
    float sc = d_P[row] + d_Q[col] + aw[512] * ea[e] + ab[0];
    d_SC[e] = sc;
    atomicMax(&d_MENC[row], fenc(sc));
}

__global__ void k_edge2(const int* __restrict__ ei) {
    int e = blockIdx.x * 256 + threadIdx.x;
    if (e >= NE) return;
    int row = ei[e];
    float m = fdec(d_MENC[row]);
    float ex = __expf(d_SC[e] - m);
    d_SC[e] = ex;
    atomicAdd(&d_SSUM[row], ex);
}

__global__ void k_edge3(const int* __restrict__ ei) {
    int e = blockIdx.x * 4 + (threadIdx.x >> 6);
    int l = threadIdx.x & 63;
    if (e >= NE) return;
    int row = ei[e], col = ei[NE + e];
    float alpha = d_SC[e] / (d_SSUM[row] + 1e-16f);
    float4 v = *(const float4*)&d_XL[row * GD + l * 4];
    float* dst = &d_AGG[col * GD + l * 4];
    atomicAdd(dst + 0, alpha * v.x);
    atomicAdd(dst + 1, alpha * v.y);
    atomicAdd(dst + 2, alpha * v.z);
    atomicAdd(dst + 3, alpha * v.w);
}

__global__ void k_finish(const float* __restrict__ addsrc, float* __restrict__ dst) {
    int i = blockIdx.x * 256 + threadIdx.x;
    if (i >= NN * GD) return;
    float v = d_AGG[i];
    v = v > 0.f ? v : 0.f;
    if (addsrc) v += addsrc[i];
    dst[i] = v;
}

__global__ void k_heads(const float* __restrict__ impW, const float* __restrict__ impb,
                        const float* __restrict__ uncW, const float* __restrict__ uncb,
                        float* __restrict__ out) {
    int n = blockIdx.x * 8 + (threadIdx.x >> 5);
    int lane = threadIdx.x & 31;
    if (n >= NN) return;
    float a = 0.f, b = 0.f;
#pragma unroll
    for (int j = lane; j < GD; j += 32) {
        float v = d_G2[n * GD + j];
        a += v * impW[j];
        b += v * uncW[j];
    }
#pragma unroll
    for (int o = 16; o; o >>= 1) {
        a += __shfl_xor_sync(0xffffffffu, a, o);
        b += __shfl_xor_sync(0xffffffffu, b, o);
    }
    if (lane == 0) {
        out[n] = tanhf(a + impb[0]);
        out[NN + n] = 1.f / (1.f + expf(-(b + uncb[0])));
    }
}

// ---------------- host orchestration ----------------
extern "C" void kernel_launch(void* const* d_in, const int* in_sizes, int n_in,
                              void* d_out, int out_size)
{
    const float* x_s = (const float*)d_in[0];
    const float* x_m = (const float*)d_in[1];
    const float* x_l = (const float*)d_in[2];
    const int*   ei  = (const int*)d_in[3];
    const float* ea  = (const float*)d_in[4];
    // scale order here: 0=long, 1=medium, 2=short
    const float* Wih[3] = {(const float*)d_in[13], (const float*)d_in[9], (const float*)d_in[5]};
    const float* Whh[3] = {(const float*)d_in[14], (const float*)d_in[10], (const float*)d_in[6]};
    const float* bih[3] = {(const float*)d_in[15], (const float*)d_in[11], (const float*)d_in[7]};
    const float* bhh[3] = {(const float*)d_in[16], (const float*)d_in[12], (const float*)d_in[8]};
    const float* fW   = (const float*)d_in[17];
    const float* fb   = (const float*)d_in[18];
    const float* g1W  = (const float*)d_in[19];
    const float* g1aw = (const float*)d_in[20];
    const float* g1ab = (const float*)d_in[21];
    const float* g2W  = (const float*)d_in[22];
    const float* g2aw = (const float*)d_in[23];
    const float* g2ab = (const float*)d_in[24];
    const float* impW = (const float*)d_in[25];
    const float* impb = (const float*)d_in[26];
    const float* uncW = (const float*)d_in[27];
    const float* uncb = (const float*)d_in[28];

    void *pWPK, *pBIAS, *pHA, *pHB;
    void *pCOMB, *pTEMB, *pXL, *pAGG, *pG1, *pG2;
    cudaGetSymbolAddress(&pWPK, d_WPK);
    cudaGetSymbolAddress(&pBIAS, d_BIAS);
    cudaGetSymbolAddress(&pHA, d_HA);
    cudaGetSymbolAddress(&pHB, d_HB);
    cudaGetSymbolAddress(&pCOMB, d_COMB);
    cudaGetSymbolAddress(&pTEMB, d_TEMB);
    cudaGetSymbolAddress(&pXL, d_XL);
    cudaGetSymbolAddress(&pAGG, d_AGG);
    cudaGetSymbolAddress(&pG1, d_G1);
    cudaGetSymbolAddress(&pG2, d_G2);
    unsigned* WPKp = (unsigned*)pWPK;
    float* BIASp = (float*)pBIAS;
    float* HA = (float*)pHA; float* HB = (float*)pHB;
    float* COMB = (float*)pCOMB; float* TEMB = (float*)pTEMB;
    float* XL = (float*)pXL; float* AGG = (float*)pAGG;
    float* G1 = (float*)pG1; float* G2 = (float*)pG2;

    cudaFuncSetAttribute(gru_persist,
                         cudaFuncAttributeMaxDynamicSharedMemorySize, PERSIST_SMEM);

    // ---- fold biases + repack weights ----
    for (int s = 0; s < 3; s++)
        k_prep_bias<<<1, 768>>>(bih[s], bhh[s], s);
    k_pack<<<(3 * 20 * CHUNK_WORDS + 255) / 256, 256>>>(
        Whh[0], Wih[0], Whh[1], Wih[1], Whh[2], Wih[2]);

    // ---- persistent recurrence: ONE launch for all 3 GRUs, all timesteps --
    cudaMemsetAsync(HA, 0, (size_t)3 * NN * HD * sizeof(float));
    gru_persist<<<3 * MB, 1024, PERSIST_SMEM>>>(
        HA, HB, WPKp, x_l, x_m, x_s, BIASp, bhh[0], bhh[1], bhh[2]);

    // finals all land in HA (T even for every scale): 0=l, 1=m, 2=s
    float* HL = HA;
    float* HM = HA + (size_t)NN * HD;
    float* HS = HA + (size_t)2 * NN * HD;

    // ---- fusion ----
    dim3 gS((NN + 127) / 128, GD / 64);
    k_concat<<<(NN * H3 + 255) / 256, 256>>>(HS, HM, HL);
    gemm_tn<<<gS, 256>>>(COMB, H3, fW, H3, fb, TEMB, GD, NN, H3, 1);

    // ---- SAGE layer 1 ----
    gemm_tn<<<gS, 256>>>(TEMB, GD, g1W, GD, nullptr, XL, GD, NN, GD, 0);
    k_pq<<<(NN + 7) / 8, 256>>>(g1aw);
    k_init<<<(NN + 255) / 256, 256>>>();
    cudaMemsetAsync(AGG, 0, (size_t)NN * GD * sizeof(float));
    k_edge1<<<(NE + 255) / 256, 256>>>(ei, ea, g1aw, g1ab);
    k_edge2<<<(NE + 255) / 256, 256>>>(ei);
    k_edge3<<<NE / 4, 256>>>(ei);
    k_finish<<<(NN * GD + 255) / 256, 256>>>(nullptr, G1);

    // ---- SAGE layer 2 ----
    gemm_tn<<<gS, 256>>>(G1, GD, g2W, GD, nullptr, XL, GD, NN, GD, 0);
    k_pq<<<(NN + 7) / 8, 256>>>(g2aw);
    k_init<<<(NN + 255) / 256, 256>>>();
    cudaMemsetAsync(AGG, 0, (size_t)NN * GD * sizeof(float));
    k_edge1<<<(NE + 255) / 256, 256>>>(ei, ea, g2aw, g2ab);
    k_edge2<<<(NE + 255) / 256, 256>>>(ei);
    k_edge3<<<NE / 4, 256>>>(ei);
    k_finish<<<(NN * GD + 255) / 256, 256>>>(TEMB, G2);

    // ---- heads ----
    k_heads<<<(NN + 7) / 8, 256>>>(impW, impb, uncW, uncb, (float*)d_out);
}

// round 11
// speedup vs baseline: 3.8688x; 1.1916x over previous
#include <cuda_runtime.h>
#include <cuda_fp16.h>

#define NN 10000
#define NE 320000
#define FD 64
#define HD 256
#define GD 256
#define H3 768
#define MB 79                 // blocks per scale (ceil 10000/128)

#define ASTH 264              // h tile smem stride (halves)
#define XSTH 72               // x tile smem stride (halves)
#define ASM_H (128 * ASTH)
#define XSM_H (128 * XSTH)
#define CHUNK_WORDS 6144      // 192 rows x 64 halves = 24576 B
#define CHUNK_BYTES 24576
#define RING_BYTES (3 * CHUNK_BYTES)
#define SM_AH_OFF RING_BYTES
#define SM_XH_OFF (SM_AH_OFF + ASM_H * 2)
#define SM_MB_OFF (SM_XH_OFF + XSM_H * 2)
#define PERSIST_SMEM (SM_MB_OFF + 32)

// ---------------- static scratch ----------------
__device__ unsigned d_WPK[3 * 20 * CHUNK_WORDS];  // repacked fp16 GRU weights
__device__ unsigned d_FWPK[256 / 64 * 768 / 64 * 2048];  // fusion W packed
__device__ unsigned d_G1PK[256 / 64 * 256 / 64 * 2048];
__device__ unsigned d_G2PK[256 / 64 * 256 / 64 * 2048];
__device__ float d_BIAS[3 * 768];
__device__ float d_HA[3 * NN * HD];
__device__ float d_HB[3 * NN * HD];
__device__ float d_COMB[NN * H3];
__device__ float d_TEMB[NN * GD];
__device__ float d_XL[NN * GD];
__device__ float d_G1[NN * GD];
__device__ float d_G2[NN * GD];
__device__ float d_P[NN];
__device__ float d_Q[NN];
__device__ float d_SSUM[NN];
__device__ unsigned d_MENC[NN];
__device__ float d_SC[NE];
__device__ int d_CNT[NN];
__device__ int d_PTR[NN + 1];
__device__ int d_CUR[NN];
__device__ int d_EID[NE];

// ---------------- helpers ----------------
__device__ __forceinline__ float fsig(float x) {
    return __fdividef(1.f, 1.f + __expf(-x));
}
__device__ __forceinline__ float ftanh(float x) {
    x = fminf(fmaxf(x, -15.f), 15.f);
    float e = __expf(-2.f * x);
    return __fdividef(1.f - e, 1.f + e);
}

__device__ __forceinline__ unsigned smem_u32(const void* p) {
    return (unsigned)__cvta_generic_to_shared(p);
}

__device__ __forceinline__ void mma_f16(float* c, const unsigned* a, const unsigned* b) {
    asm volatile(
        "mma.sync.aligned.m16n8k16.row.col.f32.f16.f16.f32 "
        "{%0,%1,%2,%3},{%4,%5,%6,%7},{%8,%9},{%0,%1,%2,%3};"
        : "+f"(c[0]), "+f"(c[1]), "+f"(c[2]), "+f"(c[3])
        : "r"(a[0]), "r"(a[1]), "r"(a[2]), "r"(a[3]), "r"(b[0]), "r"(b[1]));
}

__device__ __forceinline__ void ldsm_x4(unsigned* r, unsigned addr) {
    asm volatile("ldmatrix.sync.aligned.m8n8.x4.shared.b16 {%0,%1,%2,%3}, [%4];"
                 : "=r"(r[0]), "=r"(r[1]), "=r"(r[2]), "=r"(r[3]) : "r"(addr));
}

#define MBAR_WAIT(addr, par) do {                                               \
    asm volatile(                                                               \
        "{\n\t.reg .pred P1;\n\t"                                               \
        "WAIT_%=:\n\t"                                                          \
        "mbarrier.try_wait.parity.acquire.cta.shared::cta.b64 P1, [%0], %1, 0x989680;\n\t" \
        "@P1 bra.uni DONE_%=;\n\t"                                              \
        "bra.uni WAIT_%=;\n\t"                                                  \
        "DONE_%=:\n\t}"                                                         \
        :: "r"(addr), "r"(par) : "memory");                                     \
} while (0)

// ---------------- bias fold ----------------
__global__ void k_prep_bias(const float* __restrict__ bih,
                            const float* __restrict__ bhh, int s) {
    int i = threadIdx.x;
    d_BIAS[s * 768 + i] = bih[i] + (i < 512 ? bhh[i] : 0.f);
}

// ---------------- GRU weight repack (fragment-ordered chunks) --------------
__global__ void k_pack(const float* __restrict__ whL, const float* __restrict__ wiL,
                       const float* __restrict__ whM, const float* __restrict__ wiM,
                       const float* __restrict__ whS, const float* __restrict__ wiS) {
    int W = blockIdx.x * 256 + threadIdx.x;
    if (W >= 3 * 20 * CHUNK_WORDS) return;
    int s = W / (20 * CHUNK_WORDS);
    int r = W % (20 * CHUNK_WORDS);
    int c = r / CHUNK_WORDS;
    int q = r % CHUNK_WORDS;
    int w = q & 1, lane = (q >> 1) & 31, ks = (q >> 6) & 3, u = (q >> 8) & 1;
    int gc = (q >> 9) % 3, wn = (q >> 9) / 3;
    int jc = c / 5, pc = c % 5;
    int grow = gc * 256 + jc * 64 + wn * 16 + u * 8 + (lane >> 2);
    int k0 = ks * 16 + 2 * (lane & 3) + w * 8;
    const float* wh = (s == 0) ? whL : ((s == 1) ? whM : whS);
    const float* wi = (s == 0) ? wiL : ((s == 1) ? wiM : wiS);
    const float* src = (pc < 4) ? (wh + (size_t)grow * 256 + pc * 64 + k0)
                                : (wi + (size_t)grow * 64 + k0);
    __half2 h2 = __floats2half2_rn(src[0], src[1]);
    d_WPK[W] = *(unsigned*)&h2;
}

// ---------------- generic GEMM weight repack: W[N][K] -> fragment order ----
// layout [nb][kc][q], q = ((((wn*4+nt)*4+ks)*32+lane)*2+w
__global__ void k_packW(const float* __restrict__ W, unsigned* __restrict__ dst,
                        int N, int K) {
    int idx = blockIdx.x * 256 + threadIdx.x;
    int KC = K >> 6;
    int total = (N >> 6) * KC * 2048;
    if (idx >= total) return;
    int nb = idx / (KC * 2048);
    int r = idx % (KC * 2048);
    int kc = r / 2048;
    int q = r % 2048;
    int w = q & 1, lane = (q >> 1) & 31, ks = (q >> 6) & 3;
    int nt = (q >> 8) & 3, wn = (q >> 10) & 1;
    int n = nb * 64 + wn * 32 + nt * 8 + (lane >> 2);
    int k = kc * 64 + ks * 16 + 2 * (lane & 3) + w * 8;
    __half2 h2 = __floats2half2_rn(W[(size_t)n * K + k], W[(size_t)n * K + k + 1]);
    dst[idx] = *(unsigned*)&h2;
}

// ================== persistent GRU (unchanged from R10) ====================
__global__ void __launch_bounds__(1024) gru_persist(
    float* __restrict__ hA, float* __restrict__ hB,
    const unsigned* __restrict__ wpk,
    const float* __restrict__ xL, const float* __restrict__ xM,
    const float* __restrict__ xS,
    const float* __restrict__ biasAll,
    const float* __restrict__ bhhL, const float* __restrict__ bhhM,
    const float* __restrict__ bhhS)
{
    extern __shared__ char smraw[];
    unsigned* Ring = (unsigned*)smraw;
    __half* Ah = (__half*)(smraw + SM_AH_OFF);
    __half* Xh = (__half*)(smraw + SM_XH_OFF);
    const unsigned ringaddr = smem_u32(smraw);
    const unsigned mbaddr = smem_u32(smraw + SM_MB_OFF);
    const unsigned ah_base = smem_u32(Ah);
    const unsigned xh_base = smem_u32(Xh);

    const int tid = threadIdx.x;
    const int s = blockIdx.x / MB;
    const int m0 = (blockIdx.x % MB) * 128;
    const int T = (s == 0) ? 60 : ((s == 1) ? 30 : 8);
    const float* xsrc = (s == 0) ? xL : ((s == 1) ? xM : xS);
    const float* bhh = (s == 0) ? bhhL : ((s == 1) ? bhhM : bhhS);
    const float* bias = biasAll + s * 768;
    float* ha = hA + (size_t)s * NN * HD;
    float* hb = hB + (size_t)s * NN * HD;

    const int lane = tid & 31, gid = lane >> 2, tig = lane & 3;
    const int warp = tid >> 5;
    const int wm = warp & 7, wn = warp >> 3;
    const int lrow = tid >> 3;
    const int cbase = (tid & 7) * 4;
    const int i4 = lane >> 3, r8 = lane & 7;

    if (tid < 3) {
        asm volatile("mbarrier.init.shared.b64 [%0], %1;"
                     :: "r"(mbaddr + tid * 8), "r"(1u) : "memory");
    }
    __syncthreads();

#define ISSUE_CHUNK(cc) do {                                                    \
        int sl_ = (cc) % 3;                                                     \
        unsigned mb_ = mbaddr + sl_ * 8;                                        \
        asm volatile("mbarrier.arrive.expect_tx.shared.b64 _, [%0], %1;"        \
                     :: "r"(mb_), "r"((unsigned)CHUNK_BYTES) : "memory");       \
        unsigned dst_ = ringaddr + sl_ * CHUNK_BYTES;                           \
        const void* src_ = (const char*)wpk +                                   \
                           ((size_t)(s * 20 + (cc))) * CHUNK_BYTES;             \
        asm volatile(                                                           \
            "cp.async.bulk.shared::cluster.global.mbarrier::complete_tx::bytes " \
            "[%0], [%1], %2, [%3];"                                             \
            :: "r"(dst_), "l"(src_), "r"((unsigned)CHUNK_BYTES), "r"(mb_)       \
            : "memory");                                                        \
    } while (0)

    for (int t = 0; t < T; t++) {
        const float* hin = (t & 1) ? hb : ha;
        float* hout = (t & 1) ? ha : hb;

        if (tid == 0) { ISSUE_CHUNK(0); ISSUE_CHUNK(1); ISSUE_CHUNK(2); }

        {
            int grow = m0 + lrow;
            bool ok = grow < NN;
            const float* hr = hin + (size_t)grow * HD;
            __half* da = Ah + lrow * ASTH;
#pragma unroll
            for (int q = 0; q < 8; q++) {
                int col = cbase + q * 32;
                float4 v = ok ? *(const float4*)(hr + col)
                              : make_float4(0.f, 0.f, 0.f, 0.f);
                *(__half2*)(da + col)     = __floats2half2_rn(v.x, v.y);
                *(__half2*)(da + col + 2) = __floats2half2_rn(v.z, v.w);
            }
            const float* xr = xsrc + ((size_t)grow * T + t) * 64;
            __half* dx = Xh + lrow * XSTH;
#pragma unroll
            for (int q = 0; q < 2; q++) {
                int col = cbase + q * 32;
                float4 v = ok ? *(const float4*)(xr + col)
                              : make_float4(0.f, 0.f, 0.f, 0.f);
                *(__half2*)(dx + col)     = __floats2half2_rn(v.x, v.y);
                *(__half2*)(dx + col + 2) = __floats2half2_rn(v.z, v.w);
            }
        }
        __syncthreads();

#pragma unroll
        for (int jc = 0; jc < 4; jc++) {
            float acc[8][4];
#pragma unroll
            for (int j = 0; j < 8; j++)
#pragma unroll
                for (int r = 0; r < 4; r++) acc[j][r] = 0.f;

#pragma unroll
            for (int pc = 0; pc < 5; pc++) {
                const int c = jc * 5 + pc;
                const int slot = c % 3;
                const int nuse = (slot == 2) ? 6 : 7;
                unsigned par = (unsigned)((t * nuse + c / 3) & 1);
                MBAR_WAIT(mbaddr + slot * 8, par);

                const unsigned* Bs = Ring + slot * CHUNK_WORDS;
                const unsigned abase = (pc < 4) ? ah_base : xh_base;
                const int astr = (pc < 4) ? ASTH : XSTH;
                const int kofs = (pc < 4) ? pc * 64 : 0;

#pragma unroll
                for (int ks = 0; ks < 4; ks++) {
                    unsigned af[4];
                    int arow = wm * 16 + (i4 & 1) * 8 + r8;
                    int acol = kofs + ks * 16 + (i4 >> 1) * 8;
                    ldsm_x4(af, abase + (arow * astr + acol) * 2);
#pragma unroll
                    for (int gc = 0; gc < 3; gc++) {
                        const int ci = (pc == 4 && gc == 2) ? 3 : gc;
#pragma unroll
                        for (int u = 0; u < 2; u++) {
                            int fb = ((((wn * 3 + gc) * 2 + u) * 4 + ks) * 32
                                      + lane) * 2;
                            uint2 bf = *(const uint2*)(Bs + fb);
                            mma_f16(acc[ci * 2 + u], af, &bf.x);
                        }
                    }
                }
                __syncthreads();
                if (tid == 0 && c + 3 < 20) ISSUE_CHUNK(c + 3);
            }

            const int j0 = jc * 64;
#pragma unroll
            for (int u = 0; u < 2; u++)
#pragma unroll
                for (int h2 = 0; h2 < 2; h2++) {
                    int row = m0 + wm * 16 + gid + h2 * 8;
                    if (row >= NN) continue;
                    int jg = j0 + wn * 16 + u * 8 + 2 * tig;
                    float2 hp = *(const float2*)(hin + (size_t)row * HD + jg);
                    float2 ho;
                    {
                        float r0 = fsig(acc[0 + u][h2 * 2 + 0] + bias[jg]);
                        float z0 = fsig(acc[2 + u][h2 * 2 + 0] + bias[256 + jg]);
                        float n0 = ftanh(acc[6 + u][h2 * 2 + 0] + bias[512 + jg] +
                                         r0 * (acc[4 + u][h2 * 2 + 0] + bhh[512 + jg]));
                        ho.x = (1.f - z0) * n0 + z0 * hp.x;
                    }
                    {
                        float r1 = fsig(acc[0 + u][h2 * 2 + 1] + bias[jg + 1]);
                        float z1 = fsig(acc[2 + u][h2 * 2 + 1] + bias[256 + jg + 1]);
                        float n1 = ftanh(acc[6 + u][h2 * 2 + 1] + bias[512 + jg + 1] +
                                         r1 * (acc[4 + u][h2 * 2 + 1] + bhh[512 + jg + 1]));
                        ho.y = (1.f - z1) * n1 + z1 * hp.y;
                    }
                    *(float2*)(hout + (size_t)row * HD + jg) = ho;
                }
        }
        __threadfence_block();
        __syncthreads();
    }
#undef ISSUE_CHUNK
}

// ================== fp16 MMA GEMM: C[M,256] = A[M,K]fp32 x Wpk^T ===========
// block 256 thr, 8 warps (4m x 2n), tile 128m x 64n, K chunks of 64.
__global__ void __launch_bounds__(256) gemm_h(
    const float* __restrict__ A, int K,
    const unsigned* __restrict__ Bpk,
    const float* __restrict__ bias,
    float* __restrict__ C, int M, int relu)
{
    __shared__ __half Ash[128 * 72];
    const int tid = threadIdx.x, lane = tid & 31, warp = tid >> 5;
    const int wm = warp & 3, wn = warp >> 2;
    const int gid = lane >> 2, tig = lane & 3;
    const int i4 = lane >> 3, r8 = lane & 7;
    const int m0 = blockIdx.x * 128;
    const unsigned ab = smem_u32(Ash);
    const int KC = K >> 6;
    const unsigned* Bbase = Bpk + (size_t)blockIdx.y * KC * 2048;

    float acc[2][4][4];
#pragma unroll
    for (int i = 0; i < 2; i++)
#pragma unroll
        for (int nt = 0; nt < 4; nt++)
#pragma unroll
            for (int r = 0; r < 4; r++) acc[i][nt][r] = 0.f;

    const int srow = tid >> 1, scs = (tid & 1) * 32;

    for (int kc = 0; kc < KC; kc++) {
        __syncthreads();
        {
            bool ok = (m0 + srow) < M;
            const float* ar = A + (size_t)(m0 + srow) * K + kc * 64 + scs;
            __half* da = Ash + srow * 72 + scs;
#pragma unroll
            for (int qq = 0; qq < 8; qq++) {
                float4 v = ok ? *(const float4*)(ar + qq * 4)
                              : make_float4(0.f, 0.f, 0.f, 0.f);
                *(__half2*)(da + qq * 4)     = __floats2half2_rn(v.x, v.y);
                *(__half2*)(da + qq * 4 + 2) = __floats2half2_rn(v.z, v.w);
            }
        }
        __syncthreads();
        const unsigned* Bc = Bbase + kc * 2048;
#pragma unroll
        for (int ks = 0; ks < 4; ks++) {
            unsigned af[2][4];
#pragma unroll
            for (int i = 0; i < 2; i++) {
                int arow = wm * 32 + i * 16 + (i4 & 1) * 8 + r8;
                int acol = ks * 16 + (i4 >> 1) * 8;
                ldsm_x4(af[i], ab + (arow * 72 + acol) * 2);
            }
#pragma unroll
            for (int nt = 0; nt < 4; nt++) {
                int fb = (((wn * 4 + nt) * 4 + ks) * 32 + lane) * 2;
                uint2 bf = *(const uint2*)(Bc + fb);
#pragma unroll
                for (int i = 0; i < 2; i++)
                    mma_f16(acc[i][nt], af[i], &bf.x);
            }
        }
    }

#pragma unroll
    for (int i = 0; i < 2; i++)
#pragma unroll
        for (int nt = 0; nt < 4; nt++)
#pragma unroll
            for (int h2 = 0; h2 < 2; h2++) {
                int row = m0 + wm * 32 + i * 16 + h2 * 8 + gid;
                if (row >= M) continue;
                int col = blockIdx.y * 64 + wn * 32 + nt * 8 + 2 * tig;
                float2 o;
                o.x = acc[i][nt][h2 * 2 + 0] + (bias ? bias[col] : 0.f);
                o.y = acc[i][nt][h2 * 2 + 1] + (bias ? bias[col + 1] : 0.f);
                if (relu) { o.x = fmaxf(o.x, 0.f); o.y = fmaxf(o.y, 0.f); }
                *(float2*)(C + (size_t)row * GD + col) = o;
            }
}

__global__ void k_concat(const float* __restrict__ hs, const float* __restrict__ hm,
                         const float* __restrict__ hl) {
    int i = blockIdx.x * 256 + threadIdx.x;
    if (i >= NN * H3) return;
    int n = i / H3, j = i % H3;
    float v;
    if (j < 256)      v = hs[n * HD + j];
    else if (j < 512) v = hm[n * HD + j - 256];
    else              v = hl[n * HD + j - 512];
    d_COMB[i] = v;
}

// ---------------- CSR build (by destination col) ----------------
__global__ void k_hist(const int* __restrict__ ei) {
    int e = blockIdx.x * 256 + threadIdx.x;
    if (e < NE) atomicAdd(&d_CNT[ei[NE + e]], 1);
}

__global__ void k_scan() {   // 1 block, 1024 threads
    __shared__ int part[1024];
    int t = threadIdx.x;
    int base = t * 10;
    int sum = 0;
#pragma unroll
    for (int i = 0; i < 10; i++) {
        int idx = base + i;
        if (idx < NN) sum += d_CNT[idx];
    }
    part[t] = sum;
    __syncthreads();
    for (int off = 1; off < 1024; off <<= 1) {
        int v = (t >= off) ? part[t - off] : 0;
        __syncthreads();
        part[t] += v;
        __syncthreads();
    }
    int run = (t > 0) ? part[t - 1] : 0;
#pragma unroll
    for (int i = 0; i < 10; i++) {
        int idx = base + i;
        if (idx < NN) {
            d_PTR[idx] = run;
            run += d_CNT[idx];
        }
    }
    if (t == 0) d_PTR[NN] = part[1023];
}

__global__ void k_scatter(const int* __restrict__ ei) {
    int e = blockIdx.x * 256 + threadIdx.x;
    if (e >= NE) return;
    int col = ei[NE + e];
    int pos = atomicAdd(&d_CUR[col], 1);
    d_EID[d_PTR[col] + pos] = e;
}

// ---------------- SAGE attention (decomposed scores) ----------------
__device__ __forceinline__ unsigned fenc(float f) {
    unsigned u = __float_as_uint(f);
    return (u & 0x80000000u) ? ~u : (u | 0x80000000u);
}
__device__ __forceinline__ float fdec(unsigned u) {
    u = (u & 0x80000000u) ? (u & 0x7fffffffu) : ~u;
    return __uint_as_float(u);
}

__global__ void k_pq(const float* __restrict__ aw) {
    int n = blockIdx.x * 8 + (threadIdx.x >> 5);
    int lane = threadIdx.x & 31;
    if (n >= NN) return;
    float p = 0.f, q = 0.f;
#pragma unroll
    for (int j = lane; j < 256; j += 32) {
        float v = d_XL[n * GD + j];
        p += v * aw[j];
        q += v * aw[256 + j];
    }
#pragma unroll
    for (int o = 16; o; o >>= 1) {
        p += __shfl_xor_sync(0xffffffffu, p, o);
        q += __shfl_xor_sync(0xffffffffu, q, o);
    }
    if (lane == 0) { d_P[n] = p; d_Q[n] = q; }
}

__global__ void k_init() {
    int n = blockIdx.x * 256 + threadIdx.x;
    if (n < NN) { d_MENC[n] = 0x007fffffu; d_SSUM[n] = 0.f; }
}

__global__ void k_edge1(const int* __restrict__ ei, const float* __restrict__ ea,
                        const float* __restrict__ aw, const float* __restrict__ ab) {
    int e = blockIdx.x * 256 + threadIdx.x;
    if (e >= NE) return;
    int row = ei[e], col = ei[NE + e];
    float sc = d_P[row] + d_Q[col] + aw[512] * ea[e] + ab[0];
    d_SC[e] = sc;
    atomicMax(&d_MENC[row], fenc(sc));
}

__global__ void k_edge2(const int* __restrict__ ei) {
    int e = blockIdx.x * 256 + threadIdx.x;
    if (e >= NE) return;
    int row = ei[e];
    float m = fdec(d_MENC[row]);
    float ex = __expf(d_SC[e] - m);
    d_SC[e] = ex;
    atomicAdd(&d_SSUM[row], ex);
}

__global__ void k_alpha(const int* __restrict__ ei) {
    int e = blockIdx.x * 256 + threadIdx.x;
    if (e >= NE) return;
    d_SC[e] = d_SC[e] / (d_SSUM[ei[e]] + 1e-16f);
}

// CSR aggregation: 4 nodes per block, 64 threads per node, no atomics.
__global__ void __launch_bounds__(256) k_agg(const int* __restrict__ ei,
                                             const float* __restrict__ addsrc,
                                             float* __restrict__ dst) {
    int node = blockIdx.x * 4 + (threadIdx.x >> 6);
    int l = threadIdx.x & 63;
    if (node >= NN) return;
    int beg = d_PTR[node], end = d_PTR[node + 1];
    float4 acc = make_float4(0.f, 0.f, 0.f, 0.f);
    for (int idx = beg; idx < end; idx++) {
        int e = d_EID[idx];
        int row = ei[e];
        float alpha = d_SC[e];
        float4 v = *(const float4*)&d_XL[(size_t)row * GD + l * 4];
        acc.x += alpha * v.x; acc.y += alpha * v.y;
        acc.z += alpha * v.z; acc.w += alpha * v.w;
    }
    float4 o;
    o.x = fmaxf(acc.x, 0.f); o.y = fmaxf(acc.y, 0.f);
    o.z = fmaxf(acc.z, 0.f); o.w = fmaxf(acc.w, 0.f);
    if (addsrc) {
        float4 a = *(const float4*)&addsrc[(size_t)node * GD + l * 4];
        o.x += a.x; o.y += a.y; o.z += a.z; o.w += a.w;
    }
    *(float4*)&dst[(size_t)node * GD + l * 4] = o;
}

__global__ void k_heads(const float* __restrict__ impW, const float* __restrict__ impb,
                        const float* __restrict__ uncW, const float* __restrict__ uncb,
                        float* __restrict__ out) {
    int n = blockIdx.x * 8 + (threadIdx.x >> 5);
    int lane = threadIdx.x & 31;
    if (n >= NN) return;
    float a = 0.f, b = 0.f;
#pragma unroll
    for (int j = lane; j < GD; j += 32) {
        float v = d_G2[n * GD + j];
        a += v * impW[j];
        b += v * uncW[j];
    }
#pragma unroll
    for (int o = 16; o; o >>= 1) {
        a += __shfl_xor_sync(0xffffffffu, a, o);
        b += __shfl_xor_sync(0xffffffffu, b, o);
    }
    if (lane == 0) {
        out[n] = tanhf(a + impb[0]);
        out[NN + n] = 1.f / (1.f + expf(-(b + uncb[0])));
    }
}

// ---------------- host orchestration ----------------
extern "C" void kernel_launch(void* const* d_in, const int* in_sizes, int n_in,
                              void* d_out, int out_size)
{
    const float* x_s = (const float*)d_in[0];
    const float* x_m = (const float*)d_in[1];
    const float* x_l = (const float*)d_in[2];
    const int*   ei  = (const int*)d_in[3];
    const float* ea  = (const float*)d_in[4];
    // scale order here: 0=long, 1=medium, 2=short
    const float* Wih[3] = {(const float*)d_in[13], (const float*)d_in[9], (const float*)d_in[5]};
    const float* Whh[3] = {(const float*)d_in[14], (const float*)d_in[10], (const float*)d_in[6]};
    const float* bih[3] = {(const float*)d_in[15], (const float*)d_in[11], (const float*)d_in[7]};
    const float* bhh[3] = {(const float*)d_in[16], (const float*)d_in[12], (const float*)d_in[8]};
    const float* fW   = (const float*)d_in[17];
    const float* fb   = (const float*)d_in[18];
    const float* g1W  = (const float*)d_in[19];
    const float* g1aw = (const float*)d_in[20];
    const float* g1ab = (const float*)d_in[21];
    const float* g2W  = (const float*)d_in[22];
    const float* g2aw = (const float*)d_in[23];
    const float* g2ab = (const float*)d_in[24];
    const float* impW = (const float*)d_in[25];
    const float* impb = (const float*)d_in[26];
    const float* uncW = (const float*)d_in[27];
    const float* uncb = (const float*)d_in[28];

    void *pWPK, *pFW, *pG1W, *pG2W, *pBIAS, *pHA, *pHB;
    void *pCOMB, *pTEMB, *pXL, *pG1, *pG2, *pCNT, *pCUR;
    cudaGetSymbolAddress(&pWPK, d_WPK);
    cudaGetSymbolAddress(&pFW, d_FWPK);
    cudaGetSymbolAddress(&pG1W, d_G1PK);
    cudaGetSymbolAddress(&pG2W, d_G2PK);
    cudaGetSymbolAddress(&pBIAS, d_BIAS);
    cudaGetSymbolAddress(&pHA, d_HA);
    cudaGetSymbolAddress(&pHB, d_HB);
    cudaGetSymbolAddress(&pCOMB, d_COMB);
    cudaGetSymbolAddress(&pTEMB, d_TEMB);
    cudaGetSymbolAddress(&pXL, d_XL);
    cudaGetSymbolAddress(&pG1, d_G1);
    cudaGetSymbolAddress(&pG2, d_G2);
    cudaGetSymbolAddress(&pCNT, d_CNT);
    cudaGetSymbolAddress(&pCUR, d_CUR);
    unsigned* WPKp = (unsigned*)pWPK;
    float* BIASp = (float*)pBIAS;
    float* HA = (float*)pHA; float* HB = (float*)pHB;
    float* COMB = (float*)pCOMB; float* TEMB = (float*)pTEMB;
    float* XL = (float*)pXL;
    float* G1 = (float*)pG1; float* G2 = (float*)pG2;

    cudaFuncSetAttribute(gru_persist,
                         cudaFuncAttributeMaxDynamicSharedMemorySize, PERSIST_SMEM);

    // ---- fold biases + repack weights ----
    for (int s = 0; s < 3; s++)
        k_prep_bias<<<1, 768>>>(bih[s], bhh[s], s);
    k_pack<<<(3 * 20 * CHUNK_WORDS + 255) / 256, 256>>>(
        Whh[0], Wih[0], Whh[1], Wih[1], Whh[2], Wih[2]);
    k_packW<<<(4 * 12 * 2048 + 255) / 256, 256>>>(fW, (unsigned*)pFW, 256, 768);
    k_packW<<<(4 * 4 * 2048 + 255) / 256, 256>>>(g1W, (unsigned*)pG1W, 256, 256);
    k_packW<<<(4 * 4 * 2048 + 255) / 256, 256>>>(g2W, (unsigned*)pG2W, 256, 256);

    // ---- CSR build (edge_index reused by both SAGE layers) ----
    cudaMemsetAsync(pCNT, 0, NN * sizeof(int));
    cudaMemsetAsync(pCUR, 0, NN * sizeof(int));
    k_hist<<<(NE + 255) / 256, 256>>>(ei);
    k_scan<<<1, 1024>>>();
    k_scatter<<<(NE + 255) / 256, 256>>>(ei);

    // ---- persistent recurrence ----
    cudaMemsetAsync(HA, 0, (size_t)3 * NN * HD * sizeof(float));
    gru_persist<<<3 * MB, 1024, PERSIST_SMEM>>>(
        HA, HB, WPKp, x_l, x_m, x_s, BIASp, bhh[0], bhh[1], bhh[2]);

    float* HL = HA;
    float* HM = HA + (size_t)NN * HD;
    float* HS = HA + (size_t)2 * NN * HD;

    // ---- fusion ----
    dim3 gH((NN + 127) / 128, 4);
    k_concat<<<(NN * H3 + 255) / 256, 256>>>(HS, HM, HL);
    gemm_h<<<gH, 256>>>(COMB, 768, (unsigned*)pFW, fb, TEMB, NN, 1);

    // ---- SAGE layer 1 ----
    gemm_h<<<gH, 256>>>(TEMB, 256, (unsigned*)pG1W, nullptr, XL, NN, 0);
    k_pq<<<(NN + 7) / 8, 256>>>(g1aw);
    k_init<<<(NN + 255) / 256, 256>>>();
    k_edge1<<<(NE + 255) / 256, 256>>>(ei, ea, g1aw, g1ab);
    k_edge2<<<(NE + 255) / 256, 256>>>(ei);
    k_alpha<<<(NE + 255) / 256, 256>>>(ei);
    k_agg<<<(NN + 3) / 4, 256>>>(ei, nullptr, G1);

    // ---- SAGE layer 2 ----
    gemm_h<<<gH, 256>>>(G1, 256, (unsigned*)pG2W, nullptr, XL, NN, 0);
    k_pq<<<(NN + 7) / 8, 256>>>(g2aw);
    k_init<<<(NN + 255) / 256, 256>>>();
    k_edge1<<<(NE + 255) / 256, 256>>>(ei, ea, g2aw, g2ab);
    k_edge2<<<(NE + 255) / 256, 256>>>(ei);
    k_alpha<<<(NE + 255) / 256, 256>>>(ei);
    k_agg<<<(NN + 3) / 4, 256>>>(ei, TEMB, G2);

    // ---- heads ----
    k_heads<<<(NN + 7) / 8, 256>>>(impW, impb, uncW, uncb, (float*)d_out);
}

// round 12
// speedup vs baseline: 4.0026x; 1.0346x over previous
#include <cuda_runtime.h>
#include <cuda_fp16.h>

#define NN 10000
#define NE 320000
#define FD 64
#define HD 256
#define GD 256
#define H3 768
#define MB 79                 // blocks per scale (ceil 10000/128)

#define ASTH 264              // h tile smem stride (halves)
#define XSTH 72               // x tile smem stride (halves)
#define ASM_H (128 * ASTH)    // halves per A tile (33792)
#define XSM_H (128 * XSTH)
#define CHUNK_WORDS 6144      // 192 rows x 64 halves = 24576 B
#define CHUNK_BYTES 24576
// smem: [ring 2x24576][Ah0][Ah1][Xh][mbar]
#define AH0_OFF (2 * CHUNK_BYTES)
#define AH1_OFF (AH0_OFF + ASM_H * 2)
#define XH_OFF (AH1_OFF + ASM_H * 2)
#define MB_OFF (XH_OFF + XSM_H * 2)
#define PERSIST_SMEM (MB_OFF + 32)

// ---------------- static scratch ----------------
__device__ unsigned d_WPK[3 * 20 * CHUNK_WORDS];  // repacked fp16 GRU weights
__device__ unsigned d_FWPK[256 / 64 * 768 / 64 * 2048];  // fusion W packed
__device__ unsigned d_G1PK[256 / 64 * 256 / 64 * 2048];
__device__ unsigned d_G2PK[256 / 64 * 256 / 64 * 2048];
__device__ float d_BIAS[3 * 768];
__device__ float d_HA[3 * NN * HD];
__device__ float d_COMB[NN * H3];
__device__ float d_TEMB[NN * GD];
__device__ float d_XL[NN * GD];
__device__ float d_G1[NN * GD];
__device__ float d_G2[NN * GD];
__device__ float d_P[NN];
__device__ float d_Q[NN];
__device__ float d_SSUM[NN];
__device__ unsigned d_MENC[NN];
__device__ float d_SC[NE];
__device__ int d_CNT[NN];
__device__ int d_PTR[NN + 1];
__device__ int d_CUR[NN];
__device__ int d_EID[NE];

// ---------------- helpers ----------------
__device__ __forceinline__ float fsig(float x) {
    return __fdividef(1.f, 1.f + __expf(-x));
}
__device__ __forceinline__ float ftanh(float x) {
    x = fminf(fmaxf(x, -15.f), 15.f);
    float e = __expf(-2.f * x);
    return __fdividef(1.f - e, 1.f + e);
}

__device__ __forceinline__ unsigned smem_u32(const void* p) {
    return (unsigned)__cvta_generic_to_shared(p);
}

__device__ __forceinline__ void mma_f16(float* c, const unsigned* a, const unsigned* b) {
    asm volatile(
        "mma.sync.aligned.m16n8k16.row.col.f32.f16.f16.f32 "
        "{%0,%1,%2,%3},{%4,%5,%6,%7},{%8,%9},{%0,%1,%2,%3};"
        : "+f"(c[0]), "+f"(c[1]), "+f"(c[2]), "+f"(c[3])
        : "r"(a[0]), "r"(a[1]), "r"(a[2]), "r"(a[3]), "r"(b[0]), "r"(b[1]));
}

__device__ __forceinline__ void ldsm_x4(unsigned* r, unsigned addr) {
    asm volatile("ldmatrix.sync.aligned.m8n8.x4.shared.b16 {%0,%1,%2,%3}, [%4];"
                 : "=r"(r[0]), "=r"(r[1]), "=r"(r[2]), "=r"(r[3]) : "r"(addr));
}

#define MBAR_WAIT(addr, par) do {                                               \
    asm volatile(                                                               \
        "{\n\t.reg .pred P1;\n\t"                                               \
        "WAIT_%=:\n\t"                                                          \
        "mbarrier.try_wait.parity.acquire.cta.shared::cta.b64 P1, [%0], %1, 0x989680;\n\t" \
        "@P1 bra.uni DONE_%=;\n\t"                                              \
        "bra.uni WAIT_%=;\n\t"                                                  \
        "DONE_%=:\n\t}"                                                         \
        :: "r"(addr), "r"(par) : "memory");                                     \
} while (0)

// ---------------- bias fold ----------------
__global__ void k_prep_bias(const float* __restrict__ bih,
                            const float* __restrict__ bhh, int s) {
    int i = threadIdx.x;
    d_BIAS[s * 768 + i] = bih[i] + (i < 512 ? bhh[i] : 0.f);
}

// ---------------- GRU weight repack (fragment-ordered chunks) --------------
__global__ void k_pack(const float* __restrict__ whL, const float* __restrict__ wiL,
                       const float* __restrict__ whM, const float* __restrict__ wiM,
                       const float* __restrict__ whS, const float* __restrict__ wiS) {
    int W = blockIdx.x * 256 + threadIdx.x;
    if (W >= 3 * 20 * CHUNK_WORDS) return;
    int s = W / (20 * CHUNK_WORDS);
    int r = W % (20 * CHUNK_WORDS);
    int c = r / CHUNK_WORDS;
    int q = r % CHUNK_WORDS;
    int w = q & 1, lane = (q >> 1) & 31, ks = (q >> 6) & 3, u = (q >> 8) & 1;
    int gc = (q >> 9) % 3, wn = (q >> 9) / 3;
    int jc = c / 5, pc = c % 5;
    int grow = gc * 256 + jc * 64 + wn * 16 + u * 8 + (lane >> 2);
    int k0 = ks * 16 + 2 * (lane & 3) + w * 8;
    const float* wh = (s == 0) ? whL : ((s == 1) ? whM : whS);
    const float* wi = (s == 0) ? wiL : ((s == 1) ? wiM : wiS);
    const float* src = (pc < 4) ? (wh + (size_t)grow * 256 + pc * 64 + k0)
                                : (wi + (size_t)grow * 64 + k0);
    __half2 h2 = __floats2half2_rn(src[0], src[1]);
    d_WPK[W] = *(unsigned*)&h2;
}

// ---------------- generic GEMM weight repack ----------------
__global__ void k_packW(const float* __restrict__ W, unsigned* __restrict__ dst,
                        int N, int K) {
    int idx = blockIdx.x * 256 + threadIdx.x;
    int KC = K >> 6;
    int total = (N >> 6) * KC * 2048;
    if (idx >= total) return;
    int nb = idx / (KC * 2048);
    int r = idx % (KC * 2048);
    int kc = r / 2048;
    int q = r % 2048;
    int w = q & 1, lane = (q >> 1) & 31, ks = (q >> 6) & 3;
    int nt = (q >> 8) & 3, wn = (q >> 10) & 1;
    int n = nb * 64 + wn * 32 + nt * 8 + (lane >> 2);
    int k = kc * 64 + ks * 16 + 2 * (lane & 3) + w * 8;
    __half2 h2 = __floats2half2_rn(W[(size_t)n * K + k], W[(size_t)n * K + k + 1]);
    dst[idx] = *(unsigned*)&h2;
}

// ============ persistent GRU: h lives in SMEM fp16 (ping-pong A tiles) =====
__global__ void __launch_bounds__(1024) gru_persist(
    float* __restrict__ hA,
    const unsigned* __restrict__ wpk,
    const float* __restrict__ xL, const float* __restrict__ xM,
    const float* __restrict__ xS,
    const float* __restrict__ biasAll,
    const float* __restrict__ bhhL, const float* __restrict__ bhhM,
    const float* __restrict__ bhhS)
{
    extern __shared__ char smraw[];
    unsigned* Ring = (unsigned*)smraw;
    __half* Ah0 = (__half*)(smraw + AH0_OFF);
    __half* Ah1 = (__half*)(smraw + AH1_OFF);
    __half* Xh = (__half*)(smraw + XH_OFF);
    const unsigned ringaddr = smem_u32(smraw);
    const unsigned mbaddr = smem_u32(smraw + MB_OFF);
    const unsigned xh_base = smem_u32(Xh);

    const int tid = threadIdx.x;
    const int s = blockIdx.x / MB;
    const int m0 = (blockIdx.x % MB) * 128;
    const int T = (s == 0) ? 60 : ((s == 1) ? 30 : 8);
    const float* xsrc = (s == 0) ? xL : ((s == 1) ? xM : xS);
    const float* bhh = (s == 0) ? bhhL : ((s == 1) ? bhhM : bhhS);
    const float* bias = biasAll + s * 768;
    float* ha = hA + (size_t)s * NN * HD;

    const int lane = tid & 31, gid = lane >> 2, tig = lane & 3;
    const int warp = tid >> 5;
    const int wm = warp & 7, wn = warp >> 3;
    const int lrow = tid >> 3;
    const int cbase = (tid & 7) * 4;
    const int i4 = lane >> 3, r8 = lane & 7;

    if (tid < 2) {
        asm volatile("mbarrier.init.shared.b64 [%0], %1;"
                     :: "r"(mbaddr + tid * 8), "r"(1u) : "memory");
    }
    // zero both A tiles (h0 = 0; rows >= NN stay zero forever)
    {
        unsigned* za = (unsigned*)Ah0;   // 2 tiles contiguous = ASM_H uints
        for (int i = tid; i < ASM_H; i += 1024) za[i] = 0;
    }
    __syncthreads();

#define ISSUE_CHUNK(cc) do {                                                    \
        int sl_ = (cc) & 1;                                                     \
        unsigned mb_ = mbaddr + sl_ * 8;                                        \
        asm volatile("mbarrier.arrive.expect_tx.shared.b64 _, [%0], %1;"        \
                     :: "r"(mb_), "r"((unsigned)CHUNK_BYTES) : "memory");       \
        unsigned dst_ = ringaddr + sl_ * CHUNK_BYTES;                           \
        const void* src_ = (const char*)wpk +                                   \
                           ((size_t)(s * 20 + (cc))) * CHUNK_BYTES;             \
        asm volatile(                                                           \
            "cp.async.bulk.shared::cluster.global.mbarrier::complete_tx::bytes " \
            "[%0], [%1], %2, [%3];"                                             \
            :: "r"(dst_), "l"(src_), "r"((unsigned)CHUNK_BYTES), "r"(mb_)       \
            : "memory");                                                        \
    } while (0)

    for (int t = 0; t < T; t++) {
        const __half* Acur = (t & 1) ? Ah1 : Ah0;
        __half* Anxt = (t & 1) ? Ah0 : Ah1;
        const unsigned acur_base = smem_u32(Acur);

        if (tid == 0) { ISSUE_CHUNK(0); ISSUE_CHUNK(1); }

        // ---- stage x_t (128x64) into SMEM as fp16 ----
        {
            int grow = m0 + lrow;
            bool ok = grow < NN;
            const float* xr = xsrc + ((size_t)grow * T + t) * 64;
            __half* dx = Xh + lrow * XSTH;
#pragma unroll
            for (int q = 0; q < 2; q++) {
                int col = cbase + q * 32;
                float4 v = ok ? *(const float4*)(xr + col)
                              : make_float4(0.f, 0.f, 0.f, 0.f);
                *(__half2*)(dx + col)     = __floats2half2_rn(v.x, v.y);
                *(__half2*)(dx + col + 2) = __floats2half2_rn(v.z, v.w);
            }
        }
        __syncthreads();   // x staged; prev-step epilogue writes to Acur visible

#pragma unroll
        for (int jc = 0; jc < 4; jc++) {
            float acc[8][4];
#pragma unroll
            for (int j = 0; j < 8; j++)
#pragma unroll
                for (int r = 0; r < 4; r++) acc[j][r] = 0.f;

#pragma unroll
            for (int pc = 0; pc < 5; pc++) {
                const int c = jc * 5 + pc;
                const int slot = c & 1;
                MBAR_WAIT(mbaddr + slot * 8, (unsigned)((c >> 1) & 1));

                const unsigned* Bs = Ring + slot * CHUNK_WORDS;
                const unsigned abase = (pc < 4) ? acur_base : xh_base;
                const int astr = (pc < 4) ? ASTH : XSTH;
                const int kofs = (pc < 4) ? pc * 64 : 0;

#pragma unroll
                for (int ks = 0; ks < 4; ks++) {
                    unsigned af[4];
                    int arow = wm * 16 + (i4 & 1) * 8 + r8;
                    int acol = kofs + ks * 16 + (i4 >> 1) * 8;
                    ldsm_x4(af, abase + (arow * astr + acol) * 2);
#pragma unroll
                    for (int gc = 0; gc < 3; gc++) {
                        const int ci = (pc == 4 && gc == 2) ? 3 : gc;
#pragma unroll
                        for (int u = 0; u < 2; u++) {
                            int fb = ((((wn * 3 + gc) * 2 + u) * 4 + ks) * 32
                                      + lane) * 2;
                            uint2 bf = *(const uint2*)(Bs + fb);
                            mma_f16(acc[ci * 2 + u], af, &bf.x);
                        }
                    }
                }
                __syncthreads();           // slot consumed by all warps
                if (tid == 0 && c + 2 < 20) ISSUE_CHUNK(c + 2);
            }

            // ---- epilogue: GRU update; h read/write in SMEM fp16 ----
            const int j0 = jc * 64;
#pragma unroll
            for (int u = 0; u < 2; u++)
#pragma unroll
                for (int h2 = 0; h2 < 2; h2++) {
                    int row = wm * 16 + gid + h2 * 8;
                    if (m0 + row >= NN) continue;
                    int jg = j0 + wn * 16 + u * 8 + 2 * tig;
                    float2 hp = __half22float2(
                        *(const __half2*)(Acur + row * ASTH + jg));
                    float2 ho;
                    {
                        float r0 = fsig(acc[0 + u][h2 * 2 + 0] + bias[jg]);
                        float z0 = fsig(acc[2 + u][h2 * 2 + 0] + bias[256 + jg]);
                        float n0 = ftanh(acc[6 + u][h2 * 2 + 0] + bias[512 + jg] +
                                         r0 * (acc[4 + u][h2 * 2 + 0] + bhh[512 + jg]));
                        ho.x = (1.f - z0) * n0 + z0 * hp.x;
                    }
                    {
                        float r1 = fsig(acc[0 + u][h2 * 2 + 1] + bias[jg + 1]);
                        float z1 = fsig(acc[2 + u][h2 * 2 + 1] + bias[256 + jg + 1]);
                        float n1 = ftanh(acc[6 + u][h2 * 2 + 1] + bias[512 + jg + 1] +
                                         r1 * (acc[4 + u][h2 * 2 + 1] + bhh[512 + jg + 1]));
                        ho.y = (1.f - z1) * n1 + z1 * hp.y;
                    }
                    *(__half2*)(Anxt + row * ASTH + jg) =
                        __floats2half2_rn(ho.x, ho.y);
                    if (t == T - 1)
                        *(float2*)(ha + (size_t)(m0 + row) * HD + jg) = ho;
                }
        }
        __syncthreads();   // epilogue STS visible; Xh free for next t
    }
#undef ISSUE_CHUNK
}

// ================== fp16 MMA GEMM: C[M,256] = A[M,K]fp32 x Wpk^T ===========
__global__ void __launch_bounds__(256) gemm_h(
    const float* __restrict__ A, int K,
    const unsigned* __restrict__ Bpk,
    const float* __restrict__ bias,
    float* __restrict__ C, int M, int relu)
{
    __shared__ __half Ash[128 * 72];
    const int tid = threadIdx.x, lane = tid & 31, warp = tid >> 5;
    const int wm = warp & 3, wn = warp >> 2;
    const int gid = lane >> 2, tig = lane & 3;
    const int i4 = lane >> 3, r8 = lane & 7;
    const int m0 = blockIdx.x * 128;
    const unsigned ab = smem_u32(Ash);
    const int KC = K >> 6;
    const unsigned* Bbase = Bpk + (size_t)blockIdx.y * KC * 2048;

    float acc[2][4][4];
#pragma unroll
    for (int i = 0; i < 2; i++)
#pragma unroll
        for (int nt = 0; nt < 4; nt++)
#pragma unroll
            for (int r = 0; r < 4; r++) acc[i][nt][r] = 0.f;

    const int srow = tid >> 1, scs = (tid & 1) * 32;

    for (int kc = 0; kc < KC; kc++) {
        __syncthreads();
        {
            bool ok = (m0 + srow) < M;
            const float* ar = A + (size_t)(m0 + srow) * K + kc * 64 + scs;
            __half* da = Ash + srow * 72 + scs;
#pragma unroll
            for (int qq = 0; qq < 8; qq++) {
                float4 v = ok ? *(const float4*)(ar + qq * 4)
                              : make_float4(0.f, 0.f, 0.f, 0.f);
                *(__half2*)(da + qq * 4)     = __floats2half2_rn(v.x, v.y);
                *(__half2*)(da + qq * 4 + 2) = __floats2half2_rn(v.z, v.w);
            }
        }
        __syncthreads();
        const unsigned* Bc = Bbase + kc * 2048;
#pragma unroll
        for (int ks = 0; ks < 4; ks++) {
            unsigned af[2][4];
#pragma unroll
            for (int i = 0; i < 2; i++) {
                int arow = wm * 32 + i * 16 + (i4 & 1) * 8 + r8;
                int acol = ks * 16 + (i4 >> 1) * 8;
                ldsm_x4(af[i], ab + (arow * 72 + acol) * 2);
            }
#pragma unroll
            for (int nt = 0; nt < 4; nt++) {
                int fb = (((wn * 4 + nt) * 4 + ks) * 32 + lane) * 2;
                uint2 bf = *(const uint2*)(Bc + fb);
#pragma unroll
                for (int i = 0; i < 2; i++)
                    mma_f16(acc[i][nt], af[i], &bf.x);
            }
        }
    }

#pragma unroll
    for (int i = 0; i < 2; i++)
#pragma unroll
        for (int nt = 0; nt < 4; nt++)
#pragma unroll
            for (int h2 = 0; h2 < 2; h2++) {
                int row = m0 + wm * 32 + i * 16 + h2 * 8 + gid;
                if (row >= M) continue;
                int col = blockIdx.y * 64 + wn * 32 + nt * 8 + 2 * tig;
                float2 o;
                o.x = acc[i][nt][h2 * 2 + 0] + (bias ? bias[col] : 0.f);
                o.y = acc[i][nt][h2 * 2 + 1] + (bias ? bias[col + 1] : 0.f);
                if (relu) { o.x = fmaxf(o.x, 0.f); o.y = fmaxf(o.y, 0.f); }
                *(float2*)(C + (size_t)row * GD + col) = o;
            }
}

__global__ void k_concat(const float* __restrict__ hs, const float* __restrict__ hm,
                         const float* __restrict__ hl) {
    int i = blockIdx.x * 256 + threadIdx.x;
    if (i >= NN * H3) return;
    int n = i / H3, j = i % H3;
    float v;
    if (j < 256)      v = hs[n * HD + j];
    else if (j < 512) v = hm[n * HD + j - 256];
    else              v = hl[n * HD + j - 512];
    d_COMB[i] = v;
}

// ---------------- CSR build (by destination col) ----------------
__global__ void k_hist(const int* __restrict__ ei) {
    int e = blockIdx.x * 256 + threadIdx.x;
    if (e < NE) atomicAdd(&d_CNT[ei[NE + e]], 1);
}

__global__ void k_scan() {   // 1 block, 1024 threads
    __shared__ int part[1024];
    int t = threadIdx.x;
    int base = t * 10;
    int sum = 0;
#pragma unroll
    for (int i = 0; i < 10; i++) {
        int idx = base + i;
        if (idx < NN) sum += d_CNT[idx];
    }
    part[t] = sum;
    __syncthreads();
    for (int off = 1; off < 1024; off <<= 1) {
        int v = (t >= off) ? part[t - off] : 0;
        __syncthreads();
        part[t] += v;
        __syncthreads();
    }
    int run = (t > 0) ? part[t - 1] : 0;
#pragma unroll
    for (int i = 0; i < 10; i++) {
        int idx = base + i;
        if (idx < NN) {
            d_PTR[idx] = run;
            run += d_CNT[idx];
        }
    }
    if (t == 0) d_PTR[NN] = part[1023];
}

__global__ void k_scatter(const int* __restrict__ ei) {
    int e = blockIdx.x * 256 + threadIdx.x;
    if (e >= NE) return;
    int col = ei[NE + e];
    int pos = atomicAdd(&d_CUR[col], 1);
    d_EID[d_PTR[col] + pos] = e;
}

// ---------------- SAGE attention (decomposed scores) ----------------
__device__ __forceinline__ unsigned fenc(float f) {
    unsigned u = __float_as_uint(f);
    return (u & 0x80000000u) ? ~u : (u | 0x80000000u);
}
__device__ __forceinline__ float fdec(unsigned u) {
    u = (u & 0x80000000u) ? (u & 0x7fffffffu) : ~u;
    return __uint_as_float(u);
}

__global__ void k_pq(const float* __restrict__ aw) {
    int n = blockIdx.x * 8 + (threadIdx.x >> 5);
    int lane = threadIdx.x & 31;
    if (n >= NN) return;
    float p = 0.f, q = 0.f;
#pragma unroll
    for (int j = lane; j < 256; j += 32) {
        float v = d_XL[n * GD + j];
        p += v * aw[j];
        q += v * aw[256 + j];
    }
#pragma unroll
    for (int o = 16; o; o >>= 1) {
        p += __shfl_xor_sync(0xffffffffu, p, o);
        q += __shfl_xor_sync(0xffffffffu, q, o);
    }
    if (lane == 0) { d_P[n] = p; d_Q[n] = q; }
}

__global__ void k_init() {
    int n = blockIdx.x * 256 + threadIdx.x;
    if (n < NN) { d_MENC[n] = 0x007fffffu; d_SSUM[n] = 0.f; }
}

__global__ void k_edge1(const int* __restrict__ ei, const float* __restrict__ ea,
                        const float* __restrict__ aw, const float* __restrict__ ab) {
    int e = blockIdx.x * 256 + threadIdx.x;
    if (e >= NE) return;
    int row = ei[e], col = ei[NE + e];
    float sc = d_P[row] + d_Q[col] + aw[512] * ea[e] + ab[0];
    d_SC[e] = sc;
    atomicMax(&d_MENC[row], fenc(sc));
}

__global__ void k_edge2(const int* __restrict__ ei) {
    int e = blockIdx.x * 256 + threadIdx.x;
    if (e >= NE) return;
    int row = ei[e];
    float m = fdec(d_MENC[row]);
    float ex = __expf(d_SC[e] - m);
    d_SC[e] = ex;
    atomicAdd(&d_SSUM[row], ex);
}

__global__ void k_alpha(const int* __restrict__ ei) {
    int e = blockIdx.x * 256 + threadIdx.x;
    if (e >= NE) return;
    d_SC[e] = d_SC[e] / (d_SSUM[ei[e]] + 1e-16f);
}

// CSR aggregation: 4 nodes per block, 64 threads per node, no atomics.
__global__ void __launch_bounds__(256) k_agg(const int* __restrict__ ei,
                                             const float* __restrict__ addsrc,
                                             float* __restrict__ dst) {
    int node = blockIdx.x * 4 + (threadIdx.x >> 6);
    int l = threadIdx.x & 63;
    if (node >= NN) return;
    int beg = d_PTR[node], end = d_PTR[node + 1];
    float4 acc = make_float4(0.f, 0.f, 0.f, 0.f);
    for (int idx = beg; idx < end; idx++) {
        int e = d_EID[idx];
        int row = ei[e];
        float alpha = d_SC[e];
        float4 v = *(const float4*)&d_XL[(size_t)row * GD + l * 4];
        acc.x += alpha * v.x; acc.y += alpha * v.y;
        acc.z += alpha * v.z; acc.w += alpha * v.w;
    }
    float4 o;
    o.x = fmaxf(acc.x, 0.f); o.y = fmaxf(acc.y, 0.f);
    o.z = fmaxf(acc.z, 0.f); o.w = fmaxf(acc.w, 0.f);
    if (addsrc) {
        float4 a = *(const float4*)&addsrc[(size_t)node * GD + l * 4];
        o.x += a.x; o.y += a.y; o.z += a.z; o.w += a.w;
    }
    *(float4*)&dst[(size_t)node * GD + l * 4] = o;
}

__global__ void k_heads(const float* __restrict__ impW, const float* __restrict__ impb,
                        const float* __restrict__ uncW, const float* __restrict__ uncb,
                        float* __restrict__ out) {
    int n = blockIdx.x * 8 + (threadIdx.x >> 5);
    int lane = threadIdx.x & 31;
    if (n >= NN) return;
    float a = 0.f, b = 0.f;
#pragma unroll
    for (int j = lane; j < GD; j += 32) {
        float v = d_G2[n * GD + j];
        a += v * impW[j];
        b += v * uncW[j];
    }
#pragma unroll
    for (int o = 16; o; o >>= 1) {
        a += __shfl_xor_sync(0xffffffffu, a, o);
        b += __shfl_xor_sync(0xffffffffu, b, o);
    }
    if (lane == 0) {
        out[n] = tanhf(a + impb[0]);
        out[NN + n] = 1.f / (1.f + expf(-(b + uncb[0])));
    }
}

// ---------------- host orchestration ----------------
extern "C" void kernel_launch(void* const* d_in, const int* in_sizes, int n_in,
                              void* d_out, int out_size)
{
    const float* x_s = (const float*)d_in[0];
    const float* x_m = (const float*)d_in[1];
    const float* x_l = (const float*)d_in[2];
    const int*   ei  = (const int*)d_in[3];
    const float* ea  = (const float*)d_in[4];
    // scale order here: 0=long, 1=medium, 2=short
    const float* Wih[3] = {(const float*)d_in[13], (const float*)d_in[9], (const float*)d_in[5]};
    const float* Whh[3] = {(const float*)d_in[14], (const float*)d_in[10], (const float*)d_in[6]};
    const float* bih[3] = {(const float*)d_in[15], (const float*)d_in[11], (const float*)d_in[7]};
    const float* bhh[3] = {(const float*)d_in[16], (const float*)d_in[12], (const float*)d_in[8]};
    const float* fW   = (const float*)d_in[17];
    const float* fb   = (const float*)d_in[18];
    const float* g1W  = (const float*)d_in[19];
    const float* g1aw = (const float*)d_in[20];
    const float* g1ab = (const float*)d_in[21];
    const float* g2W  = (const float*)d_in[22];
    const float* g2aw = (const float*)d_in[23];
    const float* g2ab = (const float*)d_in[24];
    const float* impW = (const float*)d_in[25];
    const float* impb = (const float*)d_in[26];
    const float* uncW = (const float*)d_in[27];
    const float* uncb = (const float*)d_in[28];

    void *pWPK, *pFW, *pG1W, *pG2W, *pBIAS, *pHA;
    void *pCOMB, *pTEMB, *pXL, *pG1, *pG2, *pCNT, *pCUR;
    cudaGetSymbolAddress(&pWPK, d_WPK);
    cudaGetSymbolAddress(&pFW, d_FWPK);
    cudaGetSymbolAddress(&pG1W, d_G1PK);
    cudaGetSymbolAddress(&pG2W, d_G2PK);
    cudaGetSymbolAddress(&pBIAS, d_BIAS);
    cudaGetSymbolAddress(&pHA, d_HA);
    cudaGetSymbolAddress(&pCOMB, d_COMB);
    cudaGetSymbolAddress(&pTEMB, d_TEMB);
    cudaGetSymbolAddress(&pXL, d_XL);
    cudaGetSymbolAddress(&pG1, d_G1);
    cudaGetSymbolAddress(&pG2, d_G2);
    cudaGetSymbolAddress(&pCNT, d_CNT);
    cudaGetSymbolAddress(&pCUR, d_CUR);
    unsigned* WPKp = (unsigned*)pWPK;
    float* BIASp = (float*)pBIAS;
    float* HA = (float*)pHA;
    float* COMB = (float*)pCOMB; float* TEMB = (float*)pTEMB;
    float* XL = (float*)pXL;
    float* G1 = (float*)pG1; float* G2 = (float*)pG2;

    cudaFuncSetAttribute(gru_persist,
                         cudaFuncAttributeMaxDynamicSharedMemorySize, PERSIST_SMEM);

    // ---- fold biases + repack weights ----
    for (int s = 0; s < 3; s++)
        k_prep_bias<<<1, 768>>>(bih[s], bhh[s], s);
    k_pack<<<(3 * 20 * CHUNK_WORDS + 255) / 256, 256>>>(
        Whh[0], Wih[0], Whh[1], Wih[1], Whh[2], Wih[2]);
    k_packW<<<(4 * 12 * 2048 + 255) / 256, 256>>>(fW, (unsigned*)pFW, 256, 768);
    k_packW<<<(4 * 4 * 2048 + 255) / 256, 256>>>(g1W, (unsigned*)pG1W, 256, 256);
    k_packW<<<(4 * 4 * 2048 + 255) / 256, 256>>>(g2W, (unsigned*)pG2W, 256, 256);

    // ---- CSR build (edge_index reused by both SAGE layers) ----
    cudaMemsetAsync(pCNT, 0, NN * sizeof(int));
    cudaMemsetAsync(pCUR, 0, NN * sizeof(int));
    k_hist<<<(NE + 255) / 256, 256>>>(ei);
    k_scan<<<1, 1024>>>();
    k_scatter<<<(NE + 255) / 256, 256>>>(ei);

    // ---- persistent recurrence (h stays in SMEM; finals land in HA) ----
    cudaMemsetAsync(HA, 0, (size_t)3 * NN * HD * sizeof(float));
    gru_persist<<<3 * MB, 1024, PERSIST_SMEM>>>(
        HA, WPKp, x_l, x_m, x_s, BIASp, bhh[0], bhh[1], bhh[2]);

    float* HL = HA;
    float* HM = HA + (size_t)NN * HD;
    float* HS = HA + (size_t)2 * NN * HD;

    // ---- fusion ----
    dim3 gH((NN + 127) / 128, 4);
    k_concat<<<(NN * H3 + 255) / 256, 256>>>(HS, HM, HL);
    gemm_h<<<gH, 256>>>(COMB, 768, (unsigned*)pFW, fb, TEMB, NN, 1);

    // ---- SAGE layer 1 ----
    gemm_h<<<gH, 256>>>(TEMB, 256, (unsigned*)pG1W, nullptr, XL, NN, 0);
    k_pq<<<(NN + 7) / 8, 256>>>(g1aw);
    k_init<<<(NN + 255) / 256, 256>>>();
    k_edge1<<<(NE + 255) / 256, 256>>>(ei, ea, g1aw, g1ab);
    k_edge2<<<(NE + 255) / 256, 256>>>(ei);
    k_alpha<<<(NE + 255) / 256, 256>>>(ei);
    k_agg<<<(NN + 3) / 4, 256>>>(ei, nullptr, G1);

    // ---- SAGE layer 2 ----
    gemm_h<<<gH, 256>>>(G1, 256, (unsigned*)pG2W, nullptr, XL, NN, 0);
    k_pq<<<(NN + 7) / 8, 256>>>(g2aw);
    k_init<<<(NN + 255) / 256, 256>>>();
    k_edge1<<<(NE + 255) / 256, 256>>>(ei, ea, g2aw, g2ab);
    k_edge2<<<(NE + 255) / 256, 256>>>(ei);
    k_alpha<<<(NE + 255) / 256, 256>>>(ei);
    k_agg<<<(NN + 3) / 4, 256>>>(ei, TEMB, G2);

    // ---- heads ----
    k_heads<<<(NN + 7) / 8, 256>>>(impW, impb, uncW, uncb, (float*)d_out);
}

// round 13
// speedup vs baseline: 4.1962x; 1.0484x over previous
#include <cuda_runtime.h>
#include <cuda_fp16.h>

#define NN 10000
#define NE 320000
#define FD 64
#define HD 256
#define GD 256
#define H3 768
#define MB 79                 // blocks per scale (ceil 10000/128)

#define ASTH 264              // h tile smem stride (halves)
#define XSTH 72               // x tile smem stride (halves)
#define ASM_H (128 * ASTH)    // halves per A tile (33792)
#define XSM_H (128 * XSTH)
#define CHUNK_WORDS 6144      // 192 rows x 64 halves = 24576 B
#define CHUNK_BYTES 24576
// smem: [ring 2x24576][Ah0][Ah1][Xh][mbar]
#define AH0_OFF (2 * CHUNK_BYTES)
#define AH1_OFF (AH0_OFF + ASM_H * 2)
#define XH_OFF (AH1_OFF + ASM_H * 2)
#define MB_OFF (XH_OFF + XSM_H * 2)
#define PERSIST_SMEM (MB_OFF + 32)

// ---------------- static scratch ----------------
__device__ unsigned d_WPK[3 * 20 * CHUNK_WORDS];  // repacked fp16 GRU weights
__device__ unsigned d_FWPK[256 / 64 * 768 / 64 * 2048];  // fusion W packed
__device__ unsigned d_G1PK[256 / 64 * 256 / 64 * 2048];
__device__ unsigned d_G2PK[256 / 64 * 256 / 64 * 2048];
__device__ float d_BIAS[3 * 768];
__device__ float d_COMB[NN * H3];
__device__ float d_TEMB[NN * GD];
__device__ float d_XL[NN * GD];
__device__ float d_G1[NN * GD];
__device__ float d_P[NN];
__device__ float d_Q[NN];
__device__ float d_SSUM[NN];
__device__ unsigned d_MENC[NN];
__device__ float d_SC[NE];
__device__ int d_CNT[NN];
__device__ int d_PTR[NN + 1];
__device__ int d_CUR[NN];
__device__ int d_EID[NE];

// ---------------- helpers ----------------
__device__ __forceinline__ float fsig(float x) {
    return __fdividef(1.f, 1.f + __expf(-x));
}
__device__ __forceinline__ float ftanh(float x) {
    x = fminf(fmaxf(x, -15.f), 15.f);
    float e = __expf(-2.f * x);
    return __fdividef(1.f - e, 1.f + e);
}

__device__ __forceinline__ unsigned smem_u32(const void* p) {
    return (unsigned)__cvta_generic_to_shared(p);
}

__device__ __forceinline__ void mma_f16(float* c, const unsigned* a, const unsigned* b) {
    asm volatile(
        "mma.sync.aligned.m16n8k16.row.col.f32.f16.f16.f32 "
        "{%0,%1,%2,%3},{%4,%5,%6,%7},{%8,%9},{%0,%1,%2,%3};"
        : "+f"(c[0]), "+f"(c[1]), "+f"(c[2]), "+f"(c[3])
        : "r"(a[0]), "r"(a[1]), "r"(a[2]), "r"(a[3]), "r"(b[0]), "r"(b[1]));
}

__device__ __forceinline__ void ldsm_x4(unsigned* r, unsigned addr) {
    asm volatile("ldmatrix.sync.aligned.m8n8.x4.shared.b16 {%0,%1,%2,%3}, [%4];"
                 : "=r"(r[0]), "=r"(r[1]), "=r"(r[2]), "=r"(r[3]) : "r"(addr));
}

#define MBAR_WAIT(addr, par) do {                                               \
    asm volatile(                                                               \
        "{\n\t.reg .pred P1;\n\t"                                               \
        "WAIT_%=:\n\t"                                                          \
        "mbarrier.try_wait.parity.acquire.cta.shared::cta.b64 P1, [%0], %1, 0x989680;\n\t" \
        "@P1 bra.uni DONE_%=;\n\t"                                              \
        "bra.uni WAIT_%=;\n\t"                                                  \
        "DONE_%=:\n\t}"                                                         \
        :: "r"(addr), "r"(par) : "memory");                                     \
} while (0)

// ---------------- bias fold ----------------
__global__ void k_prep_bias(const float* __restrict__ bih,
                            const float* __restrict__ bhh, int s) {
    int i = threadIdx.x;
    d_BIAS[s * 768 + i] = bih[i] + (i < 512 ? bhh[i] : 0.f);
}

// ---------------- GRU weight repack (fragment-ordered chunks) --------------
__global__ void k_pack(const float* __restrict__ whL, const float* __restrict__ wiL,
                       const float* __restrict__ whM, const float* __restrict__ wiM,
                       const float* __restrict__ whS, const float* __restrict__ wiS) {
    int W = blockIdx.x * 256 + threadIdx.x;
    if (W >= 3 * 20 * CHUNK_WORDS) return;
    int s = W / (20 * CHUNK_WORDS);
    int r = W % (20 * CHUNK_WORDS);
    int c = r / CHUNK_WORDS;
    int q = r % CHUNK_WORDS;
    int w = q & 1, lane = (q >> 1) & 31, ks = (q >> 6) & 3, u = (q >> 8) & 1;
    int gc = (q >> 9) % 3, wn = (q >> 9) / 3;
    int jc = c / 5, pc = c % 5;
    int grow = gc * 256 + jc * 64 + wn * 16 + u * 8 + (lane >> 2);
    int k0 = ks * 16 + 2 * (lane & 3) + w * 8;
    const float* wh = (s == 0) ? whL : ((s == 1) ? whM : whS);
    const float* wi = (s == 0) ? wiL : ((s == 1) ? wiM : wiS);
    const float* src = (pc < 4) ? (wh + (size_t)grow * 256 + pc * 64 + k0)
                                : (wi + (size_t)grow * 64 + k0);
    __half2 h2 = __floats2half2_rn(src[0], src[1]);
    d_WPK[W] = *(unsigned*)&h2;
}

// ---------------- generic GEMM weight repack ----------------
__global__ void k_packW(const float* __restrict__ W, unsigned* __restrict__ dst,
                        int N, int K) {
    int idx = blockIdx.x * 256 + threadIdx.x;
    int KC = K >> 6;
    int total = (N >> 6) * KC * 2048;
    if (idx >= total) return;
    int nb = idx / (KC * 2048);
    int r = idx % (KC * 2048);
    int kc = r / 2048;
    int q = r % 2048;
    int w = q & 1, lane = (q >> 1) & 31, ks = (q >> 6) & 3;
    int nt = (q >> 8) & 3, wn = (q >> 10) & 1;
    int n = nb * 64 + wn * 32 + nt * 8 + (lane >> 2);
    int k = kc * 64 + ks * 16 + 2 * (lane & 3) + w * 8;
    __half2 h2 = __floats2half2_rn(W[(size_t)n * K + k], W[(size_t)n * K + k + 1]);
    dst[idx] = *(unsigned*)&h2;
}

// ============ persistent GRU: h in SMEM fp16; finals -> COMB layout ========
__global__ void __launch_bounds__(1024) gru_persist(
    float* __restrict__ comb,
    const unsigned* __restrict__ wpk,
    const float* __restrict__ xL, const float* __restrict__ xM,
    const float* __restrict__ xS,
    const float* __restrict__ biasAll,
    const float* __restrict__ bhhL, const float* __restrict__ bhhM,
    const float* __restrict__ bhhS)
{
    extern __shared__ char smraw[];
    unsigned* Ring = (unsigned*)smraw;
    __half* Ah0 = (__half*)(smraw + AH0_OFF);
    __half* Ah1 = (__half*)(smraw + AH1_OFF);
    __half* Xh = (__half*)(smraw + XH_OFF);
    const unsigned ringaddr = smem_u32(smraw);
    const unsigned mbaddr = smem_u32(smraw + MB_OFF);
    const unsigned xh_base = smem_u32(Xh);

    const int tid = threadIdx.x;
    const int s = blockIdx.x / MB;
    const int m0 = (blockIdx.x % MB) * 128;
    const int T = (s == 0) ? 60 : ((s == 1) ? 30 : 8);
    const int co = (2 - s) * 256;   // column offset in COMB (hs|hm|hl)
    const float* xsrc = (s == 0) ? xL : ((s == 1) ? xM : xS);
    const float* bhh = (s == 0) ? bhhL : ((s == 1) ? bhhM : bhhS);
    const float* bias = biasAll + s * 768;

    const int lane = tid & 31, gid = lane >> 2, tig = lane & 3;
    const int warp = tid >> 5;
    const int wm = warp & 7, wn = warp >> 3;
    const int lrow = tid >> 3;
    const int cbase = (tid & 7) * 4;
    const int i4 = lane >> 3, r8 = lane & 7;

    if (tid < 2) {
        asm volatile("mbarrier.init.shared.b64 [%0], %1;"
                     :: "r"(mbaddr + tid * 8), "r"(1u) : "memory");
    }
    // zero both A tiles (h0 = 0; rows >= NN stay zero forever)
    {
        unsigned* za = (unsigned*)Ah0;
        for (int i = tid; i < ASM_H; i += 1024) za[i] = 0;
    }
    __syncthreads();

#define ISSUE_CHUNK(cc) do {                                                    \
        int sl_ = (cc) & 1;                                                     \
        unsigned mb_ = mbaddr + sl_ * 8;                                        \
        asm volatile("mbarrier.arrive.expect_tx.shared.b64 _, [%0], %1;"        \
                     :: "r"(mb_), "r"((unsigned)CHUNK_BYTES) : "memory");       \
        unsigned dst_ = ringaddr + sl_ * CHUNK_BYTES;                           \
        const void* src_ = (const char*)wpk +                                   \
                           ((size_t)(s * 20 + (cc))) * CHUNK_BYTES;             \
        asm volatile(                                                           \
            "cp.async.bulk.shared::cluster.global.mbarrier::complete_tx::bytes " \
            "[%0], [%1], %2, [%3];"                                             \
            :: "r"(dst_), "l"(src_), "r"((unsigned)CHUNK_BYTES), "r"(mb_)       \
            : "memory");                                                        \
    } while (0)

    for (int t = 0; t < T; t++) {
        const __half* Acur = (t & 1) ? Ah1 : Ah0;
        __half* Anxt = (t & 1) ? Ah0 : Ah1;
        const unsigned acur_base = smem_u32(Acur);

        if (tid == 0) { ISSUE_CHUNK(0); ISSUE_CHUNK(1); }

        // ---- stage x_t (128x64) into SMEM as fp16 ----
        {
            int grow = m0 + lrow;
            bool ok = grow < NN;
            const float* xr = xsrc + ((size_t)grow * T + t) * 64;
            __half* dx = Xh + lrow * XSTH;
#pragma unroll
            for (int q = 0; q < 2; q++) {
                int col = cbase + q * 32;
                float4 v = ok ? *(const float4*)(xr + col)
                              : make_float4(0.f, 0.f, 0.f, 0.f);
                *(__half2*)(dx + col)     = __floats2half2_rn(v.x, v.y);
                *(__half2*)(dx + col + 2) = __floats2half2_rn(v.z, v.w);
            }
        }
        __syncthreads();   // x staged; prev-step epilogue writes visible

#pragma unroll
        for (int jc = 0; jc < 4; jc++) {
            float acc[8][4];
#pragma unroll
            for (int j = 0; j < 8; j++)
#pragma unroll
                for (int r = 0; r < 4; r++) acc[j][r] = 0.f;

#pragma unroll
            for (int pc = 0; pc < 5; pc++) {
                const int c = jc * 5 + pc;
                const int slot = c & 1;
                MBAR_WAIT(mbaddr + slot * 8, (unsigned)((c >> 1) & 1));

                const unsigned* Bs = Ring + slot * CHUNK_WORDS;
                const unsigned abase = (pc < 4) ? acur_base : xh_base;
                const int astr = (pc < 4) ? ASTH : XSTH;
                const int kofs = (pc < 4) ? pc * 64 : 0;
                const unsigned arowoff =
                    abase + ((wm * 16 + (i4 & 1) * 8 + r8) * astr + kofs
                             + (i4 >> 1) * 8) * 2;

                // software-pipelined A fragments across ks
                unsigned afA[4], afB[4];
                ldsm_x4(afA, arowoff);
#pragma unroll
                for (int ks = 0; ks < 4; ks++) {
                    unsigned* afc = (ks & 1) ? afB : afA;
                    unsigned* afn = (ks & 1) ? afA : afB;
                    if (ks < 3) ldsm_x4(afn, arowoff + (ks + 1) * 32);
#pragma unroll
                    for (int gc = 0; gc < 3; gc++) {
                        const int ci = (pc == 4 && gc == 2) ? 3 : gc;
#pragma unroll
                        for (int u = 0; u < 2; u++) {
                            int fb = ((((wn * 3 + gc) * 2 + u) * 4 + ks) * 32
                                      + lane) * 2;
                            uint2 bf = *(const uint2*)(Bs + fb);
                            mma_f16(acc[ci * 2 + u], afc, &bf.x);
                        }
                    }
                }
                __syncthreads();           // slot consumed by all warps
                if (tid == 0 && c + 2 < 20) ISSUE_CHUNK(c + 2);
            }

            // ---- epilogue: GRU update; h read/write in SMEM fp16 ----
            const int j0 = jc * 64;
#pragma unroll
            for (int u = 0; u < 2; u++)
#pragma unroll
                for (int h2 = 0; h2 < 2; h2++) {
                    int row = wm * 16 + gid + h2 * 8;
                    if (m0 + row >= NN) continue;
                    int jg = j0 + wn * 16 + u * 8 + 2 * tig;
                    float2 hp = __half22float2(
                        *(const __half2*)(Acur + row * ASTH + jg));
                    float2 ho;
                    {
                        float r0 = fsig(acc[0 + u][h2 * 2 + 0] + bias[jg]);
                        float z0 = fsig(acc[2 + u][h2 * 2 + 0] + bias[256 + jg]);
                        float n0 = ftanh(acc[6 + u][h2 * 2 + 0] + bias[512 + jg] +
                                         r0 * (acc[4 + u][h2 * 2 + 0] + bhh[512 + jg]));
                        ho.x = (1.f - z0) * n0 + z0 * hp.x;
                    }
                    {
                        float r1 = fsig(acc[0 + u][h2 * 2 + 1] + bias[jg + 1]);
                        float z1 = fsig(acc[2 + u][h2 * 2 + 1] + bias[256 + jg + 1]);
                        float n1 = ftanh(acc[6 + u][h2 * 2 + 1] + bias[512 + jg + 1] +
                                         r1 * (acc[4 + u][h2 * 2 + 1] + bhh[512 + jg + 1]));
                        ho.y = (1.f - z1) * n1 + z1 * hp.y;
                    }
                    *(__half2*)(Anxt + row * ASTH + jg) =
                        __floats2half2_rn(ho.x, ho.y);
                    if (t == T - 1)
                        *(float2*)(comb + (size_t)(m0 + row) * H3 + co + jg) = ho;
                }
        }
        __syncthreads();   // epilogue STS visible; Xh free for next t
    }
#undef ISSUE_CHUNK
}

// ================== fp16 MMA GEMM: C[M,256] = A[M,K]fp32 x Wpk^T ===========
__global__ void __launch_bounds__(256) gemm_h(
    const float* __restrict__ A, int K,
    const unsigned* __restrict__ Bpk,
    const float* __restrict__ bias,
    float* __restrict__ C, int M, int relu)
{
    __shared__ __half Ash[128 * 72];
    const int tid = threadIdx.x, lane = tid & 31, warp = tid >> 5;
    const int wm = warp & 3, wn = warp >> 2;
    const int gid = lane >> 2, tig = lane & 3;
    const int i4 = lane >> 3, r8 = lane & 7;
    const int m0 = blockIdx.x * 128;
    const unsigned ab = smem_u32(Ash);
    const int KC = K >> 6;
    const unsigned* Bbase = Bpk + (size_t)blockIdx.y * KC * 2048;

    float acc[2][4][4];
#pragma unroll
    for (int i = 0; i < 2; i++)
#pragma unroll
        for (int nt = 0; nt < 4; nt++)
#pragma unroll
            for (int r = 0; r < 4; r++) acc[i][nt][r] = 0.f;

    const int srow = tid >> 1, scs = (tid & 1) * 32;

    for (int kc = 0; kc < KC; kc++) {
        __syncthreads();
        {
            bool ok = (m0 + srow) < M;
            const float* ar = A + (size_t)(m0 + srow) * K + kc * 64 + scs;
            __half* da = Ash + srow * 72 + scs;
#pragma unroll
            for (int qq = 0; qq < 8; qq++) {
                float4 v = ok ? *(const float4*)(ar + qq * 4)
                              : make_float4(0.f, 0.f, 0.f, 0.f);
                *(__half2*)(da + qq * 4)     = __floats2half2_rn(v.x, v.y);
                *(__half2*)(da + qq * 4 + 2) = __floats2half2_rn(v.z, v.w);
            }
        }
        __syncthreads();
        const unsigned* Bc = Bbase + kc * 2048;
#pragma unroll
        for (int ks = 0; ks < 4; ks++) {
            unsigned af[2][4];
#pragma unroll
            for (int i = 0; i < 2; i++) {
                int arow = wm * 32 + i * 16 + (i4 & 1) * 8 + r8;
                int acol = ks * 16 + (i4 >> 1) * 8;
                ldsm_x4(af[i], ab + (arow * 72 + acol) * 2);
            }
#pragma unroll
            for (int nt = 0; nt < 4; nt++) {
                int fb = (((wn * 4 + nt) * 4 + ks) * 32 + lane) * 2;
                uint2 bf = *(const uint2*)(Bc + fb);
#pragma unroll
                for (int i = 0; i < 2; i++)
                    mma_f16(acc[i][nt], af[i], &bf.x);
            }
        }
    }

#pragma unroll
    for (int i = 0; i < 2; i++)
#pragma unroll
        for (int nt = 0; nt < 4; nt++)
#pragma unroll
            for (int h2 = 0; h2 < 2; h2++) {
                int row = m0 + wm * 32 + i * 16 + h2 * 8 + gid;
                if (row >= M) continue;
                int col = blockIdx.y * 64 + wn * 32 + nt * 8 + 2 * tig;
                float2 o;
                o.x = acc[i][nt][h2 * 2 + 0] + (bias ? bias[col] : 0.f);
                o.y = acc[i][nt][h2 * 2 + 1] + (bias ? bias[col + 1] : 0.f);
                if (relu) { o.x = fmaxf(o.x, 0.f); o.y = fmaxf(o.y, 0.f); }
                *(float2*)(C + (size_t)row * GD + col) = o;
            }
}

// ---------------- CSR build (by destination col) ----------------
__global__ void k_hist(const int* __restrict__ ei) {
    int e = blockIdx.x * 256 + threadIdx.x;
    if (e < NE) atomicAdd(&d_CNT[ei[NE + e]], 1);
}

__global__ void k_scan() {   // 1 block, 1024 threads
    __shared__ int part[1024];
    int t = threadIdx.x;
    int base = t * 10;
    int sum = 0;
#pragma unroll
    for (int i = 0; i < 10; i++) {
        int idx = base + i;
        if (idx < NN) sum += d_CNT[idx];
    }
    part[t] = sum;
    __syncthreads();
    for (int off = 1; off < 1024; off <<= 1) {
        int v = (t >= off) ? part[t - off] : 0;
        __syncthreads();
        part[t] += v;
        __syncthreads();
    }
    int run = (t > 0) ? part[t - 1] : 0;
#pragma unroll
    for (int i = 0; i < 10; i++) {
        int idx = base + i;
        if (idx < NN) {
            d_PTR[idx] = run;
            run += d_CNT[idx];
        }
    }
    if (t == 0) d_PTR[NN] = part[1023];
}

__global__ void k_scatter(const int* __restrict__ ei) {
    int e = blockIdx.x * 256 + threadIdx.x;
    if (e >= NE) return;
    int col = ei[NE + e];
    int pos = atomicAdd(&d_CUR[col], 1);
    d_EID[d_PTR[col] + pos] = e;
}

// ---------------- SAGE attention (decomposed scores) ----------------
__device__ __forceinline__ unsigned fenc(float f) {
    unsigned u = __float_as_uint(f);
    return (u & 0x80000000u) ? ~u : (u | 0x80000000u);
}
__device__ __forceinline__ float fdec(unsigned u) {
    u = (u & 0x80000000u) ? (u & 0x7fffffffu) : ~u;
    return __uint_as_float(u);
}

// p,q per node + init of MENC/SSUM (folded)
__global__ void k_pq(const float* __restrict__ aw) {
    int n = blockIdx.x * 8 + (threadIdx.x >> 5);
    int lane = threadIdx.x & 31;
    if (n >= NN) return;
    float p = 0.f, q = 0.f;
#pragma unroll
    for (int j = lane; j < 256; j += 32) {
        float v = d_XL[n * GD + j];
        p += v * aw[j];
        q += v * aw[256 + j];
    }
#pragma unroll
    for (int o = 16; o; o >>= 1) {
        p += __shfl_xor_sync(0xffffffffu, p, o);
        q += __shfl_xor_sync(0xffffffffu, q, o);
    }
    if (lane == 0) {
        d_P[n] = p; d_Q[n] = q;
        d_MENC[n] = 0x007fffffu;   // fenc(-inf)
        d_SSUM[n] = 0.f;
    }
}

__global__ void k_edge1(const int* __restrict__ ei, const float* __restrict__ ea,
                        const float* __restrict__ aw, const float* __restrict__ ab) {
    int e = blockIdx.x * 256 + threadIdx.x;
    if (e >= NE) return;
    int row = ei[e], col = ei[NE + e];
    float sc = d_P[row] + d_Q[col] + aw[512] * ea[e] + ab[0];
    d_SC[e] = sc;
    atomicMax(&d_MENC[row], fenc(sc));
}

__global__ void k_edge2(const int* __restrict__ ei) {
    int e = blockIdx.x * 256 + threadIdx.x;
    if (e >= NE) return;
    int row = ei[e];
    float m = fdec(d_MENC[row]);
    float ex = __expf(d_SC[e] - m);
    d_SC[e] = ex;
    atomicAdd(&d_SSUM[row], ex);
}

// CSR aggregation layer 1: alpha division folded in; relu; -> G1
__global__ void __launch_bounds__(256) k_agg(const int* __restrict__ ei,
                                             float* __restrict__ dst) {
    int node = blockIdx.x * 4 + (threadIdx.x >> 6);
    int l = threadIdx.x & 63;
    int beg = d_PTR[node], end = d_PTR[node + 1];
    float4 acc = make_float4(0.f, 0.f, 0.f, 0.f);
    for (int idx = beg; idx < end; idx++) {
        int e = d_EID[idx];
        int row = ei[e];
        float alpha = __fdividef(d_SC[e], d_SSUM[row] + 1e-16f);
        float4 v = *(const float4*)&d_XL[(size_t)row * GD + l * 4];
        acc.x += alpha * v.x; acc.y += alpha * v.y;
        acc.z += alpha * v.z; acc.w += alpha * v.w;
    }
    float4 o;
    o.x = fmaxf(acc.x, 0.f); o.y = fmaxf(acc.y, 0.f);
    o.z = fmaxf(acc.z, 0.f); o.w = fmaxf(acc.w, 0.f);
    *(float4*)&dst[(size_t)node * GD + l * 4] = o;
}

// CSR aggregation layer 2 + residual + heads (fused; G2 never stored)
__global__ void __launch_bounds__(256) k_agg2(const int* __restrict__ ei,
                                              const float* __restrict__ addsrc,
                                              const float* __restrict__ impW,
                                              const float* __restrict__ impb,
                                              const float* __restrict__ uncW,
                                              const float* __restrict__ uncb,
                                              float* __restrict__ out) {
    __shared__ float red[4][2][2];
    int nib = threadIdx.x >> 6;
    int node = blockIdx.x * 4 + nib;   // NN % 4 == 0: always valid
    int l = threadIdx.x & 63;
    int beg = d_PTR[node], end = d_PTR[node + 1];
    float4 acc = make_float4(0.f, 0.f, 0.f, 0.f);
    for (int idx = beg; idx < end; idx++) {
        int e = d_EID[idx];
        int row = ei[e];
        float alpha = __fdividef(d_SC[e], d_SSUM[row] + 1e-16f);
        float4 v = *(const float4*)&d_XL[(size_t)row * GD + l * 4];
        acc.x += alpha * v.x; acc.y += alpha * v.y;
        acc.z += alpha * v.z; acc.w += alpha * v.w;
    }
    float4 a4 = *(const float4*)&addsrc[(size_t)node * GD + l * 4];
    float4 o;
    o.x = fmaxf(acc.x, 0.f) + a4.x; o.y = fmaxf(acc.y, 0.f) + a4.y;
    o.z = fmaxf(acc.z, 0.f) + a4.z; o.w = fmaxf(acc.w, 0.f) + a4.w;
    float4 iw = *(const float4*)&impW[l * 4];
    float4 uw = *(const float4*)&uncW[l * 4];
    float pa = o.x * iw.x + o.y * iw.y + o.z * iw.z + o.w * iw.w;
    float pb = o.x * uw.x + o.y * uw.y + o.z * uw.z + o.w * uw.w;
#pragma unroll
    for (int off = 16; off; off >>= 1) {
        pa += __shfl_xor_sync(0xffffffffu, pa, off);
        pb += __shfl_xor_sync(0xffffffffu, pb, off);
    }
    int half = (threadIdx.x >> 5) & 1;
    if ((threadIdx.x & 31) == 0) {
        red[nib][half][0] = pa;
        red[nib][half][1] = pb;
    }
    __syncthreads();
    if (l == 0) {
        float a = red[nib][0][0] + red[nib][1][0] + impb[0];
        float b = red[nib][0][1] + red[nib][1][1] + uncb[0];
        out[node] = tanhf(a);
        out[NN + node] = 1.f / (1.f + expf(-b));
    }
}

// ---------------- host orchestration ----------------
extern "C" void kernel_launch(void* const* d_in, const int* in_sizes, int n_in,
                              void* d_out, int out_size)
{
    const float* x_s = (const float*)d_in[0];
    const float* x_m = (const float*)d_in[1];
    const float* x_l = (const float*)d_in[2];
    const int*   ei  = (const int*)d_in[3];
    const float* ea  = (const float*)d_in[4];
    // scale order here: 0=long, 1=medium, 2=short
    const float* Wih[3] = {(const float*)d_in[13], (const float*)d_in[9], (const float*)d_in[5]};
    const float* Whh[3] = {(const float*)d_in[14], (const float*)d_in[10], (const float*)d_in[6]};
    const float* bih[3] = {(const float*)d_in[15], (const float*)d_in[11], (const float*)d_in[7]};
    const float* bhh[3] = {(const float*)d_in[16], (const float*)d_in[12], (const float*)d_in[8]};
    const float* fW   = (const float*)d_in[17];
    const float* fb   = (const float*)d_in[18];
    const float* g1W  = (const float*)d_in[19];
    const float* g1aw = (const float*)d_in[20];
    const float* g1ab = (const float*)d_in[21];
    const float* g2W  = (const float*)d_in[22];
    const float* g2aw = (const float*)d_in[23];
    const float* g2ab = (const float*)d_in[24];
    const float* impW = (const float*)d_in[25];
    const float* impb = (const float*)d_in[26];
    const float* uncW = (const float*)d_in[27];
    const float* uncb = (const float*)d_in[28];

    void *pWPK, *pFW, *pG1W, *pG2W, *pBIAS;
    void *pCOMB, *pTEMB, *pXL, *pG1, *pCNT, *pCUR;
    cudaGetSymbolAddress(&pWPK, d_WPK);
    cudaGetSymbolAddress(&pFW, d_FWPK);
    cudaGetSymbolAddress(&pG1W, d_G1PK);
    cudaGetSymbolAddress(&pG2W, d_G2PK);
    cudaGetSymbolAddress(&pBIAS, d_BIAS);
    cudaGetSymbolAddress(&pCOMB, d_COMB);
    cudaGetSymbolAddress(&pTEMB, d_TEMB);
    cudaGetSymbolAddress(&pXL, d_XL);
    cudaGetSymbolAddress(&pG1, d_G1);
    cudaGetSymbolAddress(&pCNT, d_CNT);
    cudaGetSymbolAddress(&pCUR, d_CUR);
    unsigned* WPKp = (unsigned*)pWPK;
    float* BIASp = (float*)pBIAS;
    float* COMB = (float*)pCOMB; float* TEMB = (float*)pTEMB;
    float* XL = (float*)pXL;
    float* G1 = (float*)pG1;

    cudaFuncSetAttribute(gru_persist,
                         cudaFuncAttributeMaxDynamicSharedMemorySize, PERSIST_SMEM);

    // ---- fold biases + repack weights ----
    for (int s = 0; s < 3; s++)
        k_prep_bias<<<1, 768>>>(bih[s], bhh[s], s);
    k_pack<<<(3 * 20 * CHUNK_WORDS + 255) / 256, 256>>>(
        Whh[0], Wih[0], Whh[1], Wih[1], Whh[2], Wih[2]);
    k_packW<<<(4 * 12 * 2048 + 255) / 256, 256>>>(fW, (unsigned*)pFW, 256, 768);
    k_packW<<<(4 * 4 * 2048 + 255) / 256, 256>>>(g1W, (unsigned*)pG1W, 256, 256);
    k_packW<<<(4 * 4 * 2048 + 255) / 256, 256>>>(g2W, (unsigned*)pG2W, 256, 256);

    // ---- CSR build (edge_index reused by both SAGE layers) ----
    cudaMemsetAsync(pCNT, 0, NN * sizeof(int));
    cudaMemsetAsync(pCUR, 0, NN * sizeof(int));
    k_hist<<<(NE + 255) / 256, 256>>>(ei);
    k_scan<<<1, 1024>>>();
    k_scatter<<<(NE + 255) / 256, 256>>>(ei);

    // ---- persistent recurrence (finals written directly into COMB) ----
    gru_persist<<<3 * MB, 1024, PERSIST_SMEM>>>(
        COMB, WPKp, x_l, x_m, x_s, BIASp, bhh[0], bhh[1], bhh[2]);

    // ---- fusion ----
    dim3 gH((NN + 127) / 128, 4);
    gemm_h<<<gH, 256>>>(COMB, 768, (unsigned*)pFW, fb, TEMB, NN, 1);

    // ---- SAGE layer 1 ----
    gemm_h<<<gH, 256>>>(TEMB, 256, (unsigned*)pG1W, nullptr, XL, NN, 0);
    k_pq<<<(NN + 7) / 8, 256>>>(g1aw);
    k_edge1<<<(NE + 255) / 256, 256>>>(ei, ea, g1aw, g1ab);
    k_edge2<<<(NE + 255) / 256, 256>>>(ei);
    k_agg<<<NN / 4, 256>>>(ei, G1);

    // ---- SAGE layer 2 (aggregation + residual + heads fused) ----
    gemm_h<<<gH, 256>>>(G1, 256, (unsigned*)pG2W, nullptr, XL, NN, 0);
    k_pq<<<(NN + 7) / 8, 256>>>(g2aw);
    k_edge1<<<(NE + 255) / 256, 256>>>(ei, ea, g2aw, g2ab);
    k_edge2<<<(NE + 255) / 256, 256>>>(ei);
    k_agg2<<<NN / 4, 256>>>(ei, TEMB, impW, impb, uncW, uncb, (float*)d_out);
}

// round 14
// speedup vs baseline: 4.4431x; 1.0588x over previous
#include <cuda_runtime.h>
#include <cuda_fp16.h>

#define NN 10000
#define NE 320000
#define FD 64
#define HD 256
#define GD 256
#define H3 768
#define MB 79                 // blocks per scale (ceil 10000/128)

#define ASTH 264              // h tile smem stride (halves)
#define XSTH 72               // x tile smem stride (halves)
#define ASM_H (128 * ASTH)    // halves per A tile (33792)
#define XSM_H (128 * XSTH)
#define CHUNK_WORDS 6144      // 192 rows x 64 halves = 24576 B
#define CHUNK_BYTES 24576
// smem: [ring 2x24576][Ah0][Ah1][Xh][mbar]
#define AH0_OFF (2 * CHUNK_BYTES)
#define AH1_OFF (AH0_OFF + ASM_H * 2)
#define XH_OFF (AH1_OFF + ASM_H * 2)
#define MB_OFF (XH_OFF + XSM_H * 2)
#define PERSIST_SMEM (MB_OFF + 32)

// ---------------- static scratch ----------------
__device__ unsigned d_WPK[3 * 20 * CHUNK_WORDS];  // repacked fp16 GRU weights
__device__ unsigned d_FWPK[256 / 64 * 768 / 64 * 2048];  // fusion W packed
__device__ unsigned d_G1PK[256 / 64 * 256 / 64 * 2048];
__device__ unsigned d_G2PK[256 / 64 * 256 / 64 * 2048];
__device__ float d_BIAS[3 * 768];
__device__ float d_COMB[NN * H3];
__device__ float d_TEMB[NN * GD];
__device__ float d_XL[NN * GD];
__device__ float d_G1[NN * GD];
__device__ float d_P[NN];
__device__ float d_Q[NN];
__device__ float d_SSUM[NN];
__device__ unsigned d_MENC[NN];
__device__ float d_SC[NE];
__device__ int d_CNT[NN];
__device__ int d_PTR[NN + 1];
__device__ int d_CUR[NN];
__device__ int d_EID[NE];

// ---------------- helpers ----------------
__device__ __forceinline__ float fsig(float x) {
    return __fdividef(1.f, 1.f + __expf(-x));
}
__device__ __forceinline__ float ftanh(float x) {
    x = fminf(fmaxf(x, -15.f), 15.f);
    float e = __expf(-2.f * x);
    return __fdividef(1.f - e, 1.f + e);
}

__device__ __forceinline__ unsigned smem_u32(const void* p) {
    return (unsigned)__cvta_generic_to_shared(p);
}

__device__ __forceinline__ void mma_f16(float* c, const unsigned* a, const unsigned* b) {
    asm volatile(
        "mma.sync.aligned.m16n8k16.row.col.f32.f16.f16.f32 "
        "{%0,%1,%2,%3},{%4,%5,%6,%7},{%8,%9},{%0,%1,%2,%3};"
        : "+f"(c[0]), "+f"(c[1]), "+f"(c[2]), "+f"(c[3])
        : "r"(a[0]), "r"(a[1]), "r"(a[2]), "r"(a[3]), "r"(b[0]), "r"(b[1]));
}

__device__ __forceinline__ void ldsm_x4(unsigned* r, unsigned addr) {
    asm volatile("ldmatrix.sync.aligned.m8n8.x4.shared.b16 {%0,%1,%2,%3}, [%4];"
                 : "=r"(r[0]), "=r"(r[1]), "=r"(r[2]), "=r"(r[3]) : "r"(addr));
}

#define MBAR_WAIT(addr, par) do {                                               \
    asm volatile(                                                               \
        "{\n\t.reg .pred P1;\n\t"                                               \
        "WAIT_%=:\n\t"                                                          \
        "mbarrier.try_wait.parity.acquire.cta.shared::cta.b64 P1, [%0], %1, 0x989680;\n\t" \
        "@P1 bra.uni DONE_%=;\n\t"                                              \
        "bra.uni WAIT_%=;\n\t"                                                  \
        "DONE_%=:\n\t}"                                                         \
        :: "r"(addr), "r"(par) : "memory");                                     \
} while (0)

// ---------------- bias fold ----------------
__global__ void k_prep_bias(const float* __restrict__ bih,
                            const float* __restrict__ bhh, int s) {
    int i = threadIdx.x;
    d_BIAS[s * 768 + i] = bih[i] + (i < 512 ? bhh[i] : 0.f);
}

// ---------------- GRU weight repack (fragment-ordered chunks) --------------
__global__ void k_pack(const float* __restrict__ whL, const float* __restrict__ wiL,
                       const float* __restrict__ whM, const float* __restrict__ wiM,
                       const float* __restrict__ whS, const float* __restrict__ wiS) {
    int W = blockIdx.x * 256 + threadIdx.x;
    if (W >= 3 * 20 * CHUNK_WORDS) return;
    int s = W / (20 * CHUNK_WORDS);
    int r = W % (20 * CHUNK_WORDS);
    int c = r / CHUNK_WORDS;
    int q = r % CHUNK_WORDS;
    int w = q & 1, lane = (q >> 1) & 31, ks = (q >> 6) & 3, u = (q >> 8) & 1;
    int gc = (q >> 9) % 3, wn = (q >> 9) / 3;
    int jc = c / 5, pc = c % 5;
    int grow = gc * 256 + jc * 64 + wn * 16 + u * 8 + (lane >> 2);
    int k0 = ks * 16 + 2 * (lane & 3) + w * 8;
    const float* wh = (s == 0) ? whL : ((s == 1) ? whM : whS);
    const float* wi = (s == 0) ? wiL : ((s == 1) ? wiM : wiS);
    const float* src = (pc < 4) ? (wh + (size_t)grow * 256 + pc * 64 + k0)
                                : (wi + (size_t)grow * 64 + k0);
    __half2 h2 = __floats2half2_rn(src[0], src[1]);
    d_WPK[W] = *(unsigned*)&h2;
}

// ---------------- generic GEMM weight repack ----------------
__global__ void k_packW(const float* __restrict__ W, unsigned* __restrict__ dst,
                        int N, int K) {
    int idx = blockIdx.x * 256 + threadIdx.x;
    int KC = K >> 6;
    int total = (N >> 6) * KC * 2048;
    if (idx >= total) return;
    int nb = idx / (KC * 2048);
    int r = idx % (KC * 2048);
    int kc = r / 2048;
    int q = r % 2048;
    int w = q & 1, lane = (q >> 1) & 31, ks = (q >> 6) & 3;
    int nt = (q >> 8) & 3, wn = (q >> 10) & 1;
    int n = nb * 64 + wn * 32 + nt * 8 + (lane >> 2);
    int k = kc * 64 + ks * 16 + 2 * (lane & 3) + w * 8;
    __half2 h2 = __floats2half2_rn(W[(size_t)n * K + k], W[(size_t)n * K + k + 1]);
    dst[idx] = *(unsigned*)&h2;
}

// ============ persistent GRU: 4m x 8n warp grid; h in SMEM fp16 ============
__global__ void __launch_bounds__(1024) gru_persist(
    float* __restrict__ comb,
    const unsigned* __restrict__ wpk,
    const float* __restrict__ xL, const float* __restrict__ xM,
    const float* __restrict__ xS,
    const float* __restrict__ biasAll,
    const float* __restrict__ bhhL, const float* __restrict__ bhhM,
    const float* __restrict__ bhhS)
{
    extern __shared__ char smraw[];
    unsigned* Ring = (unsigned*)smraw;
    __half* Ah0 = (__half*)(smraw + AH0_OFF);
    __half* Ah1 = (__half*)(smraw + AH1_OFF);
    __half* Xh = (__half*)(smraw + XH_OFF);
    const unsigned ringaddr = smem_u32(smraw);
    const unsigned mbaddr = smem_u32(smraw + MB_OFF);
    const unsigned xh_base = smem_u32(Xh);

    const int tid = threadIdx.x;
    const int s = blockIdx.x / MB;
    const int m0 = (blockIdx.x % MB) * 128;
    const int T = (s == 0) ? 60 : ((s == 1) ? 30 : 8);
    const int co = (2 - s) * 256;   // column offset in COMB (hs|hm|hl)
    const float* xsrc = (s == 0) ? xL : ((s == 1) ? xM : xS);
    const float* bhh = (s == 0) ? bhhL : ((s == 1) ? bhhM : bhhS);
    const float* bias = biasAll + s * 768;

    const int lane = tid & 31, gid = lane >> 2, tig = lane & 3;
    const int warp = tid >> 5;
    const int wm = warp & 3, wn = warp >> 2;   // 4 m-groups x 8 n-octets
    const int lrow = tid >> 3;
    const int cbase = (tid & 7) * 4;
    const int i4 = lane >> 3, r8 = lane & 7;
    // B fragment base index component for this wn (old (wn>>1, u=wn&1) layout)
    const int bq = ((wn >> 1) * 3) * 2 + (wn & 1);   // gc term added as gc*2

    if (tid < 2) {
        asm volatile("mbarrier.init.shared.b64 [%0], %1;"
                     :: "r"(mbaddr + tid * 8), "r"(1u) : "memory");
    }
    // zero both A tiles (h0 = 0; rows >= NN stay zero forever)
    {
        unsigned* za = (unsigned*)Ah0;
        for (int i = tid; i < ASM_H; i += 1024) za[i] = 0;
    }
    __syncthreads();

#define ISSUE_CHUNK(cc) do {                                                    \
        int sl_ = (cc) & 1;                                                     \
        unsigned mb_ = mbaddr + sl_ * 8;                                        \
        asm volatile("mbarrier.arrive.expect_tx.shared.b64 _, [%0], %1;"        \
                     :: "r"(mb_), "r"((unsigned)CHUNK_BYTES) : "memory");       \
        unsigned dst_ = ringaddr + sl_ * CHUNK_BYTES;                           \
        const void* src_ = (const char*)wpk +                                   \
                           ((size_t)(s * 20 + (cc))) * CHUNK_BYTES;             \
        asm volatile(                                                           \
            "cp.async.bulk.shared::cluster.global.mbarrier::complete_tx::bytes " \
            "[%0], [%1], %2, [%3];"                                             \
            :: "r"(dst_), "l"(src_), "r"((unsigned)CHUNK_BYTES), "r"(mb_)       \
            : "memory");                                                        \
    } while (0)

    for (int t = 0; t < T; t++) {
        const __half* Acur = (t & 1) ? Ah1 : Ah0;
        __half* Anxt = (t & 1) ? Ah0 : Ah1;
        const unsigned acur_base = smem_u32(Acur);

        if (tid == 0) { ISSUE_CHUNK(0); ISSUE_CHUNK(1); }

        // ---- stage x_t (128x64) into SMEM as fp16 ----
        {
            int grow = m0 + lrow;
            bool ok = grow < NN;
            const float* xr = xsrc + ((size_t)grow * T + t) * 64;
            __half* dx = Xh + lrow * XSTH;
#pragma unroll
            for (int q = 0; q < 2; q++) {
                int col = cbase + q * 32;
                float4 v = ok ? *(const float4*)(xr + col)
                              : make_float4(0.f, 0.f, 0.f, 0.f);
                *(__half2*)(dx + col)     = __floats2half2_rn(v.x, v.y);
                *(__half2*)(dx + col + 2) = __floats2half2_rn(v.z, v.w);
            }
        }
        __syncthreads();   // x staged; prev-step epilogue writes visible

#pragma unroll
        for (int jc = 0; jc < 4; jc++) {
            float acc[2][4][4];   // [m-tile][gate ci][reg]
#pragma unroll
            for (int i = 0; i < 2; i++)
#pragma unroll
                for (int j = 0; j < 4; j++)
#pragma unroll
                    for (int r = 0; r < 4; r++) acc[i][j][r] = 0.f;

#pragma unroll
            for (int pc = 0; pc < 5; pc++) {
                const int c = jc * 5 + pc;
                const int slot = c & 1;
                MBAR_WAIT(mbaddr + slot * 8, (unsigned)((c >> 1) & 1));

                const unsigned* Bs = Ring + slot * CHUNK_WORDS;
                const unsigned abase = (pc < 4) ? acur_base : xh_base;
                const int astr = (pc < 4) ? ASTH : XSTH;
                const int kofs = (pc < 4) ? pc * 64 : 0;
                const unsigned arow0 =
                    abase + ((wm * 32 + (i4 & 1) * 8 + r8) * astr + kofs
                             + (i4 >> 1) * 8) * 2;
                const unsigned arow1 = arow0 + (unsigned)(16 * astr * 2);

#pragma unroll
                for (int ks = 0; ks < 4; ks++) {
                    unsigned af0[4], af1[4];
                    ldsm_x4(af0, arow0 + ks * 32);
                    ldsm_x4(af1, arow1 + ks * 32);
#pragma unroll
                    for (int gc = 0; gc < 3; gc++) {
                        const int ci = (pc == 4 && gc == 2) ? 3 : gc;
                        int fb = (((bq + gc * 2) * 4 + ks) * 32 + lane) * 2;
                        uint2 bf = *(const uint2*)(Bs + fb);
                        mma_f16(acc[0][ci], af0, &bf.x);
                        mma_f16(acc[1][ci], af1, &bf.x);
                    }
                }
                __syncthreads();           // slot consumed by all warps
                if (tid == 0 && c + 2 < 20) ISSUE_CHUNK(c + 2);
            }

            // ---- epilogue: GRU update; h read/write in SMEM fp16 ----
            const int j0 = jc * 64;
#pragma unroll
            for (int i = 0; i < 2; i++)
#pragma unroll
                for (int h2 = 0; h2 < 2; h2++) {
                    int row = wm * 32 + i * 16 + gid + h2 * 8;
                    if (m0 + row >= NN) continue;
                    int jg = j0 + wn * 8 + 2 * tig;
                    float2 hp = __half22float2(
                        *(const __half2*)(Acur + row * ASTH + jg));
                    float2 ho;
                    {
                        float r0 = fsig(acc[i][0][h2 * 2 + 0] + bias[jg]);
                        float z0 = fsig(acc[i][1][h2 * 2 + 0] + bias[256 + jg]);
                        float n0 = ftanh(acc[i][3][h2 * 2 + 0] + bias[512 + jg] +
                                         r0 * (acc[i][2][h2 * 2 + 0] + bhh[512 + jg]));
                        ho.x = (1.f - z0) * n0 + z0 * hp.x;
                    }
                    {
                        float r1 = fsig(acc[i][0][h2 * 2 + 1] + bias[jg + 1]);
                        float z1 = fsig(acc[i][1][h2 * 2 + 1] + bias[256 + jg + 1]);
                        float n1 = ftanh(acc[i][3][h2 * 2 + 1] + bias[512 + jg + 1] +
                                         r1 * (acc[i][2][h2 * 2 + 1] + bhh[512 + jg + 1]));
                        ho.y = (1.f - z1) * n1 + z1 * hp.y;
                    }
                    *(__half2*)(Anxt + row * ASTH + jg) =
                        __floats2half2_rn(ho.x, ho.y);
                    if (t == T - 1)
                        *(float2*)(comb + (size_t)(m0 + row) * H3 + co + jg) = ho;
                }
        }
        __syncthreads();   // epilogue STS visible; Xh free for next t
    }
#undef ISSUE_CHUNK
}

// ===== fp16 MMA GEMM (double-buffered A): C[M,256] = A[M,K]fp32 x Wpk^T ====
__global__ void __launch_bounds__(256) gemm_h(
    const float* __restrict__ A, int K,
    const unsigned* __restrict__ Bpk,
    const float* __restrict__ bias,
    float* __restrict__ C, int M, int relu)
{
    __shared__ __half Ash[2][128 * 72];
    const int tid = threadIdx.x, lane = tid & 31, warp = tid >> 5;
    const int wm = warp & 3, wn = warp >> 2;
    const int gid = lane >> 2, tig = lane & 3;
    const int i4 = lane >> 3, r8 = lane & 7;
    const int m0 = blockIdx.x * 128;
    const int KC = K >> 6;
    const unsigned* Bbase = Bpk + (size_t)blockIdx.y * KC * 2048;

    float acc[2][4][4];
#pragma unroll
    for (int i = 0; i < 2; i++)
#pragma unroll
        for (int nt = 0; nt < 4; nt++)
#pragma unroll
            for (int r = 0; r < 4; r++) acc[i][nt][r] = 0.f;

    const int srow = tid >> 1, scs = (tid & 1) * 32;
    const bool okrow = (m0 + srow) < M;

#define STAGE_A(kc, buf)                                                        \
    {                                                                           \
        const float* ar = A + (size_t)(m0 + srow) * K + (kc) * 64 + scs;        \
        __half* da = Ash[buf] + srow * 72 + scs;                                \
        _Pragma("unroll")                                                       \
        for (int qq = 0; qq < 8; qq++) {                                        \
            float4 v = okrow ? *(const float4*)(ar + qq * 4)                    \
                             : make_float4(0.f, 0.f, 0.f, 0.f);                 \
            *(__half2*)(da + qq * 4)     = __floats2half2_rn(v.x, v.y);         \
            *(__half2*)(da + qq * 4 + 2) = __floats2half2_rn(v.z, v.w);         \
        }                                                                       \
    }

    STAGE_A(0, 0);
    __syncthreads();

    for (int kc = 0; kc < KC; kc++) {
        if (kc + 1 < KC) STAGE_A(kc + 1, (kc + 1) & 1);
        const unsigned ab = smem_u32(Ash[kc & 1]);
        const unsigned* Bc = Bbase + kc * 2048;
#pragma unroll
        for (int ks = 0; ks < 4; ks++) {
            unsigned af[2][4];
#pragma unroll
            for (int i = 0; i < 2; i++) {
                int arow = wm * 32 + i * 16 + (i4 & 1) * 8 + r8;
                int acol = ks * 16 + (i4 >> 1) * 8;
                ldsm_x4(af[i], ab + (arow * 72 + acol) * 2);
            }
#pragma unroll
            for (int nt = 0; nt < 4; nt++) {
                int fb = (((wn * 4 + nt) * 4 + ks) * 32 + lane) * 2;
                uint2 bf = *(const uint2*)(Bc + fb);
#pragma unroll
                for (int i = 0; i < 2; i++)
                    mma_f16(acc[i][nt], af[i], &bf.x);
            }
        }
        __syncthreads();
    }
#undef STAGE_A

#pragma unroll
    for (int i = 0; i < 2; i++)
#pragma unroll
        for (int nt = 0; nt < 4; nt++)
#pragma unroll
            for (int h2 = 0; h2 < 2; h2++) {
                int row = m0 + wm * 32 + i * 16 + h2 * 8 + gid;
                if (row >= M) continue;
                int col = blockIdx.y * 64 + wn * 32 + nt * 8 + 2 * tig;
                float2 o;
                o.x = acc[i][nt][h2 * 2 + 0] + (bias ? bias[col] : 0.f);
                o.y = acc[i][nt][h2 * 2 + 1] + (bias ? bias[col + 1] : 0.f);
                if (relu) { o.x = fmaxf(o.x, 0.f); o.y = fmaxf(o.y, 0.f); }
                *(float2*)(C + (size_t)row * GD + col) = o;
            }
}

// ---------------- CSR build (by destination col) ----------------
__global__ void k_hist(const int* __restrict__ ei) {
    int e = blockIdx.x * 256 + threadIdx.x;
    if (e < NE) atomicAdd(&d_CNT[ei[NE + e]], 1);
}

__global__ void k_scan() {   // 1 block, 1024 threads
    __shared__ int part[1024];
    int t = threadIdx.x;
    int base = t * 10;
    int sum = 0;
#pragma unroll
    for (int i = 0; i < 10; i++) {
        int idx = base + i;
        if (idx < NN) sum += d_CNT[idx];
    }
    part[t] = sum;
    __syncthreads();
    for (int off = 1; off < 1024; off <<= 1) {
        int v = (t >= off) ? part[t - off] : 0;
        __syncthreads();
        part[t] += v;
        __syncthreads();
    }
    int run = (t > 0) ? part[t - 1] : 0;
#pragma unroll
    for (int i = 0; i < 10; i++) {
        int idx = base + i;
        if (idx < NN) {
            d_PTR[idx] = run;
            run += d_CNT[idx];
        }
    }
    if (t == 0) d_PTR[NN] = part[1023];
}

__global__ void k_scatter(const int* __restrict__ ei) {
    int e = blockIdx.x * 256 + threadIdx.x;
    if (e >= NE) return;
    int col = ei[NE + e];
    int pos = atomicAdd(&d_CUR[col], 1);
    d_EID[d_PTR[col] + pos] = e;
}

// ---------------- SAGE attention (decomposed scores) ----------------
__device__ __forceinline__ unsigned fenc(float f) {
    unsigned u = __float_as_uint(f);
    return (u & 0x80000000u) ? ~u : (u | 0x80000000u);
}
__device__ __forceinline__ float fdec(unsigned u) {
    u = (u & 0x80000000u) ? (u & 0x7fffffffu) : ~u;
    return __uint_as_float(u);
}

// p,q per node + init of MENC/SSUM (folded)
__global__ void k_pq(const float* __restrict__ aw) {
    int n = blockIdx.x * 8 + (threadIdx.x >> 5);
    int lane = threadIdx.x & 31;
    if (n >= NN) return;
    float p = 0.f, q = 0.f;
#pragma unroll
    for (int j = lane; j < 256; j += 32) {
        float v = d_XL[n * GD + j];
        p += v * aw[j];
        q += v * aw[256 + j];
    }
#pragma unroll
    for (int o = 16; o; o >>= 1) {
        p += __shfl_xor_sync(0xffffffffu, p, o);
        q += __shfl_xor_sync(0xffffffffu, q, o);
    }
    if (lane == 0) {
        d_P[n] = p; d_Q[n] = q;
        d_MENC[n] = 0x007fffffu;   // fenc(-inf)
        d_SSUM[n] = 0.f;
    }
}

__global__ void k_edge1(const int* __restrict__ ei, const float* __restrict__ ea,
                        const float* __restrict__ aw, const float* __restrict__ ab) {
    int e = blockIdx.x * 256 + threadIdx.x;
    if (e >= NE) return;
    int row = ei[e], col = ei[NE + e];
    float sc = d_P[row] + d_Q[col] + aw[512] * ea[e] + ab[0];
    d_SC[e] = sc;
    atomicMax(&d_MENC[row], fenc(sc));
}

__global__ void k_edge2(const int* __restrict__ ei) {
    int e = blockIdx.x * 256 + threadIdx.x;
    if (e >= NE) return;
    int row = ei[e];
    float m = fdec(d_MENC[row]);
    float ex = __expf(d_SC[e] - m);
    d_SC[e] = ex;
    atomicAdd(&d_SSUM[row], ex);
}

// CSR aggregation layer 1: alpha division folded in; relu; -> G1
__global__ void __launch_bounds__(256) k_agg(const int* __restrict__ ei,
                                             float* __restrict__ dst) {
    int node = blockIdx.x * 4 + (threadIdx.x >> 6);
    int l = threadIdx.x & 63;
    int beg = d_PTR[node], end = d_PTR[node + 1];
    float4 acc = make_float4(0.f, 0.f, 0.f, 0.f);
    for (int idx = beg; idx < end; idx++) {
        int e = d_EID[idx];
        int row = ei[e];
        float alpha = __fdividef(d_SC[e], d_SSUM[row] + 1e-16f);
        float4 v = *(const float4*)&d_XL[(size_t)row * GD + l * 4];
        acc.x += alpha * v.x; acc.y += alpha * v.y;
        acc.z += alpha * v.z; acc.w += alpha * v.w;
    }
    float4 o;
    o.x = fmaxf(acc.x, 0.f); o.y = fmaxf(acc.y, 0.f);
    o.z = fmaxf(acc.z, 0.f); o.w = fmaxf(acc.w, 0.f);
    *(float4*)&dst[(size_t)node * GD + l * 4] = o;
}

// CSR aggregation layer 2 + residual + heads (fused; G2 never stored)
__global__ void __launch_bounds__(256) k_agg2(const int* __restrict__ ei,
                                              const float* __restrict__ addsrc,
                                              const float* __restrict__ impW,
                                              const float* __restrict__ impb,
                                              const float* __restrict__ uncW,
                                              const float* __restrict__ uncb,
                                              float* __restrict__ out) {
    __shared__ float red[4][2][2];
    int nib = threadIdx.x >> 6;
    int node = blockIdx.x * 4 + nib;   // NN % 4 == 0: always valid
    int l = threadIdx.x & 63;
    int beg = d_PTR[node], end = d_PTR[node + 1];
    float4 acc = make_float4(0.f, 0.f, 0.f, 0.f);
    for (int idx = beg; idx < end; idx++) {
        int e = d_EID[idx];
        int row = ei[e];
        float alpha = __fdividef(d_SC[e], d_SSUM[row] + 1e-16f);
        float4 v = *(const float4*)&d_XL[(size_t)row * GD + l * 4];
        acc.x += alpha * v.x; acc.y += alpha * v.y;
        acc.z += alpha * v.z; acc.w += alpha * v.w;
    }
    float4 a4 = *(const float4*)&addsrc[(size_t)node * GD + l * 4];
    float4 o;
    o.x = fmaxf(acc.x, 0.f) + a4.x; o.y = fmaxf(acc.y, 0.f) + a4.y;
    o.z = fmaxf(acc.z, 0.f) + a4.z; o.w = fmaxf(acc.w, 0.f) + a4.w;
    float4 iw = *(const float4*)&impW[l * 4];
    float4 uw = *(const float4*)&uncW[l * 4];
    float pa = o.x * iw.x + o.y * iw.y + o.z * iw.z + o.w * iw.w;
    float pb = o.x * uw.x + o.y * uw.y + o.z * uw.z + o.w * uw.w;
#pragma unroll
    for (int off = 16; off; off >>= 1) {
        pa += __shfl_xor_sync(0xffffffffu, pa, off);
        pb += __shfl_xor_sync(0xffffffffu, pb, off);
    }
    int half = (threadIdx.x >> 5) & 1;
    if ((threadIdx.x & 31) == 0) {
        red[nib][half][0] = pa;
        red[nib][half][1] = pb;
    }
    __syncthreads();
    if (l == 0) {
        float a = red[nib][0][0] + red[nib][1][0] + impb[0];
        float b = red[nib][0][1] + red[nib][1][1] + uncb[0];
        out[node] = tanhf(a);
        out[NN + node] = 1.f / (1.f + expf(-b));
    }
}

// ---------------- host orchestration ----------------
extern "C" void kernel_launch(void* const* d_in, const int* in_sizes, int n_in,
                              void* d_out, int out_size)
{
    const float* x_s = (const float*)d_in[0];
    const float* x_m = (const float*)d_in[1];
    const float* x_l = (const float*)d_in[2];
    const int*   ei  = (const int*)d_in[3];
    const float* ea  = (const float*)d_in[4];
    // scale order here: 0=long, 1=medium, 2=short
    const float* Wih[3] = {(const float*)d_in[13], (const float*)d_in[9], (const float*)d_in[5]};
    const float* Whh[3] = {(const float*)d_in[14], (const float*)d_in[10], (const float*)d_in[6]};
    const float* bih[3] = {(const float*)d_in[15], (const float*)d_in[11], (const float*)d_in[7]};
    const float* bhh[3] = {(const float*)d_in[16], (const float*)d_in[12], (const float*)d_in[8]};
    const float* fW   = (const float*)d_in[17];
    const float* fb   = (const float*)d_in[18];
    const float* g1W  = (const float*)d_in[19];
    const float* g1aw = (const float*)d_in[20];
    const float* g1ab = (const float*)d_in[21];
    const float* g2W  = (const float*)d_in[22];
    const float* g2aw = (const float*)d_in[23];
    const float* g2ab = (const float*)d_in[24];
    const float* impW = (const float*)d_in[25];
    const float* impb = (const float*)d_in[26];
    const float* uncW = (const float*)d_in[27];
    const float* uncb = (const float*)d_in[28];

    void *pWPK, *pFW, *pG1W, *pG2W, *pBIAS;
    void *pCOMB, *pTEMB, *pXL, *pG1, *pCNT, *pCUR;
    cudaGetSymbolAddress(&pWPK, d_WPK);
    cudaGetSymbolAddress(&pFW, d_FWPK);
    cudaGetSymbolAddress(&pG1W, d_G1PK);
    cudaGetSymbolAddress(&pG2W, d_G2PK);
    cudaGetSymbolAddress(&pBIAS, d_BIAS);
    cudaGetSymbolAddress(&pCOMB, d_COMB);
    cudaGetSymbolAddress(&pTEMB, d_TEMB);
    cudaGetSymbolAddress(&pXL, d_XL);
    cudaGetSymbolAddress(&pG1, d_G1);
    cudaGetSymbolAddress(&pCNT, d_CNT);
    cudaGetSymbolAddress(&pCUR, d_CUR);
    unsigned* WPKp = (unsigned*)pWPK;
    float* BIASp = (float*)pBIAS;
    float* COMB = (float*)pCOMB; float* TEMB = (float*)pTEMB;
    float* XL = (float*)pXL;
    float* G1 = (float*)pG1;

    cudaFuncSetAttribute(gru_persist,
                         cudaFuncAttributeMaxDynamicSharedMemorySize, PERSIST_SMEM);

    // ---- fold biases + repack weights ----
    for (int s = 0; s < 3; s++)
        k_prep_bias<<<1, 768>>>(bih[s], bhh[s], s);
    k_pack<<<(3 * 20 * CHUNK_WORDS + 255) / 256, 256>>>(
        Whh[0], Wih[0], Whh[1], Wih[1], Whh[2], Wih[2]);
    k_packW<<<(4 * 12 * 2048 + 255) / 256, 256>>>(fW, (unsigned*)pFW, 256, 768);
    k_packW<<<(4 * 4 * 2048 + 255) / 256, 256>>>(g1W, (unsigned*)pG1W, 256, 256);
    k_packW<<<(4 * 4 * 2048 + 255) / 256, 256>>>(g2W, (unsigned*)pG2W, 256, 256);

    // ---- CSR build (edge_index reused by both SAGE layers) ----
    cudaMemsetAsync(pCNT, 0, NN * sizeof(int));
    cudaMemsetAsync(pCUR, 0, NN * sizeof(int));
    k_hist<<<(NE + 255) / 256, 256>>>(ei);
    k_scan<<<1, 1024>>>();
    k_scatter<<<(NE + 255) / 256, 256>>>(ei);

    // ---- persistent recurrence (finals written directly into COMB) ----
    gru_persist<<<3 * MB, 1024, PERSIST_SMEM>>>(
        COMB, WPKp, x_l, x_m, x_s, BIASp, bhh[0], bhh[1], bhh[2]);

    // ---- fusion ----
    dim3 gH((NN + 127) / 128, 4);
    gemm_h<<<gH, 256>>>(COMB, 768, (unsigned*)pFW, fb, TEMB, NN, 1);

    // ---- SAGE layer 1 ----
    gemm_h<<<gH, 256>>>(TEMB, 256, (unsigned*)pG1W, nullptr, XL, NN, 0);
    k_pq<<<(NN + 7) / 8, 256>>>(g1aw);
    k_edge1<<<(NE + 255) / 256, 256>>>(ei, ea, g1aw, g1ab);
    k_edge2<<<(NE + 255) / 256, 256>>>(ei);
    k_agg<<<NN / 4, 256>>>(ei, G1);

    // ---- SAGE layer 2 (aggregation + residual + heads fused) ----
    gemm_h<<<gH, 256>>>(G1, 256, (unsigned*)pG2W, nullptr, XL, NN, 0);
    k_pq<<<(NN + 7) / 8, 256>>>(g2aw);
    k_edge1<<<(NE + 255) / 256, 256>>>(ei, ea, g2aw, g2ab);
    k_edge2<<<(NE + 255) / 256, 256>>>(ei);
    k_agg2<<<NN / 4, 256>>>(ei, TEMB, impW, impb, uncW, uncb, (float*)d_out);
}